// round 12
// baseline (speedup 1.0000x reference)
#include <cuda_runtime.h>
#include <math.h>
#include <stdint.h>

// ----------------------------------------------------------------------------
// NoiseRobustAttractorLayer — TF32 mma.sync. R12: R10 structure (best: 1408us),
// K2/K4/K5 mainloops use ldmatrix fragment loads (A: 2 LDSM, B: 4 LDSM per
// ks-half vs 24 scalar LDS). B stored N-major in smem; weights pre-transposed
// to [kblock][n][k16] for coalesced cp.async. K1/K3 = R10 verbatim.
// ----------------------------------------------------------------------------

#define T_TOK 65536
#define EPSV  1e-5f

__device__ float g_xn  [(size_t)T_TOK * 512];   // fp32 (residual)
__device__ float g_xnt [(size_t)T_TOK * 512];   // tf32-rounded (GEMM A)
__device__ float g_gate[(size_t)T_TOK * 4];
__device__ float g_h   [(size_t)T_TOK * 1024];  // tf32-rounded
__device__ float g_comb[(size_t)T_TOK * 512];   // tf32-rounded
__device__ float g_oact[(size_t)T_TOK * 512];   // tf32-rounded

// row-major tf32 (K3)
__device__ float g_hW2t[4 * 256 * 128];
__device__ float g_dynt[4 * 128 * 128];
// blocked-transposed tf32: [kb][n][k16]
__device__ float g_hW1tT[4 * 512 * 256];   // per head: [32][256][16]
__device__ float g_oW1tT[512 * 512];       // [32][512][16]
__device__ float g_oW2tT[512 * 512];       // [32][512][16]

__device__ __forceinline__ float warp_sum(float v) {
#pragma unroll
    for (int o = 16; o > 0; o >>= 1) v += __shfl_xor_sync(0xffffffffu, v, o);
    return v;
}
__device__ __forceinline__ float gelu_exact(float x) {
    return 0.5f * x * (1.0f + erff(x * 0.70710678118654752f));
}
__device__ __forceinline__ uint32_t f2tf(float x) {
    uint32_t r; asm("cvt.rna.tf32.f32 %0, %1;" : "=r"(r) : "f"(x)); return r;
}
__device__ __forceinline__ float f2tf_f(float x) {
    return __uint_as_float(f2tf(x));
}
__device__ __forceinline__ void mma_tf32(float c[4], const uint32_t a[4],
                                         uint32_t b0, uint32_t b1) {
    asm volatile(
        "mma.sync.aligned.m16n8k8.row.col.f32.tf32.tf32.f32 "
        "{%0,%1,%2,%3},{%4,%5,%6,%7},{%8,%9},{%0,%1,%2,%3};"
        : "+f"(c[0]), "+f"(c[1]), "+f"(c[2]), "+f"(c[3])
        : "r"(a[0]), "r"(a[1]), "r"(a[2]), "r"(a[3]), "r"(b0), "r"(b1));
}
__device__ __forceinline__ void cp16(void* s, const void* g) {
    uint32_t sa = (uint32_t)__cvta_generic_to_shared(s);
    asm volatile("cp.async.cg.shared.global [%0], [%1], 16;" :: "r"(sa), "l"(g));
}
#define CP_COMMIT()  asm volatile("cp.async.commit_group;")
#define CP_WAIT_1()  asm volatile("cp.async.wait_group 1;" ::: "memory")
#define CP_WAIT_2()  asm volatile("cp.async.wait_group 2;" ::: "memory")
#define LDSM4(r0, r1, r2, r3, addr) \
    asm volatile("ldmatrix.sync.aligned.m8n8.x4.shared.b16 {%0,%1,%2,%3}, [%4];" \
        : "=r"(r0), "=r"(r1), "=r"(r2), "=r"(r3) : "r"(addr))

// ============================================================================
// K0: weight pre-conversion fp32 -> tf32 (+ blocked transpose for ldmatrix B)
// ============================================================================
__global__ void __launch_bounds__(256) k_prep(
    const float* __restrict__ hW1, const float* __restrict__ hW2,
    const float* __restrict__ dynm, const float* __restrict__ oW1,
    const float* __restrict__ oW2)
{
    int i = blockIdx.x * 256 + threadIdx.x;
    if (i < 524288) {
        int h = i >> 17, rem = i & 131071;
        int k = rem >> 8, n = rem & 255;
        g_hW1tT[h * 131072 + (k >> 4) * 4096 + n * 16 + (k & 15)] = f2tf_f(hW1[i]);
    } else if (i < 655360) {
        g_hW2t[i - 524288] = f2tf_f(hW2[i - 524288]);
    } else if (i < 720896) {
        g_dynt[i - 655360] = f2tf_f(dynm[i - 655360]);
    } else if (i < 983040) {
        int j = i - 720896;
        int k = j >> 9, n = j & 511;
        g_oW1tT[(k >> 4) * 8192 + n * 16 + (k & 15)] = f2tf_f(oW1[j]);
    } else if (i < 1245184) {
        int j = i - 983040;
        int k = j >> 9, n = j & 511;
        g_oW2tT[(k >> 4) * 8192 + n * 16 + (k & 15)] = f2tf_f(oW2[j]);
    }
}

// ============================================================================
// K1: warp-per-token LN + gate (R10 verbatim).
// ============================================================================
__global__ void __launch_bounds__(256) k_ln_gate(
    const float* __restrict__ x, const float* __restrict__ ng,
    const float* __restrict__ nb, const float* __restrict__ gW,
    const float* __restrict__ gb)
{
    __shared__ float sgW[2048];
    __shared__ float sng[512], snb[512];
    const int tid = threadIdx.x;
    for (int i = tid; i < 2048; i += 256) sgW[i] = gW[i];
    for (int i = tid; i < 512; i += 256) { sng[i] = ng[i]; snb[i] = nb[i]; }
    __syncthreads();

    const int wid = tid >> 5, l = tid & 31;
    const float gb0 = gb[0], gb1 = gb[1], gb2 = gb[2], gb3 = gb[3];
    const float4* sgW4 = (const float4*)sgW;
    const float4* sng4 = (const float4*)sng;
    const float4* snb4 = (const float4*)snb;

    for (int t = blockIdx.x * 8 + wid; t < T_TOK; t += gridDim.x * 8) {
        const float4* xr = (const float4*)(x + (size_t)t * 512);
        float4 v[4];
#pragma unroll
        for (int j = 0; j < 4; j++) v[j] = xr[l + 32 * j];
        float s = 0.f;
#pragma unroll
        for (int j = 0; j < 4; j++) s += v[j].x + v[j].y + v[j].z + v[j].w;
        s = warp_sum(s);
        float m = s * (1.0f / 512.0f);
        float q = 0.f;
#pragma unroll
        for (int j = 0; j < 4; j++) {
            float dx = v[j].x - m, dy = v[j].y - m, dz = v[j].z - m, dw = v[j].w - m;
            q += dx * dx + dy * dy + dz * dz + dw * dw;
        }
        q = warp_sum(q);
        float rs = rsqrtf(q * (1.0f / 512.0f) + EPSV);

        float4 xnv[4];
        float4* xo  = (float4*)(g_xn  + (size_t)t * 512);
        float4* xot = (float4*)(g_xnt + (size_t)t * 512);
#pragma unroll
        for (int j = 0; j < 4; j++) {
            float4 gv = sng4[l + 32 * j];
            float4 bv = snb4[l + 32 * j];
            xnv[j].x = (v[j].x - m) * rs * gv.x + bv.x;
            xnv[j].y = (v[j].y - m) * rs * gv.y + bv.y;
            xnv[j].z = (v[j].z - m) * rs * gv.z + bv.z;
            xnv[j].w = (v[j].w - m) * rs * gv.w + bv.w;
            xo[l + 32 * j] = xnv[j];
            float4 tv;
            tv.x = f2tf_f(xnv[j].x); tv.y = f2tf_f(xnv[j].y);
            tv.z = f2tf_f(xnv[j].z); tv.w = f2tf_f(xnv[j].w);
            xot[l + 32 * j] = tv;
        }
        float p[4] = {0.f, 0.f, 0.f, 0.f};
#pragma unroll
        for (int h = 0; h < 4; h++) {
#pragma unroll
            for (int j = 0; j < 4; j++) {
                float4 wv = sgW4[h * 128 + l + 32 * j];
                p[h] += xnv[j].x * wv.x + xnv[j].y * wv.y
                      + xnv[j].z * wv.z + xnv[j].w * wv.w;
            }
            p[h] = warp_sum(p[h]);
        }
        if (l == 0) {
            g_gate[(size_t)t * 4 + 0] = 1.0f / (1.0f + expf(-(p[0] + gb0)));
            g_gate[(size_t)t * 4 + 1] = 1.0f / (1.0f + expf(-(p[1] + gb1)));
            g_gate[(size_t)t * 4 + 2] = 1.0f / (1.0f + expf(-(p[2] + gb2)));
            g_gate[(size_t)t * 4 + 3] = 1.0f / (1.0f + expf(-(p[3] + gb3)));
        }
    }
}

// ============================================================================
// K2: h = gelu(LN(xn @ hW1[h] + hb1)).  BM=64,BN=256, 4-stage, ldmatrix frags.
// smem: As 4*5120B | BsN 4*20480B (N-major 256x20w) | sB sG sBt ps pq
//     = 107520 B  (2 CTAs/SM)
// ============================================================================
#define K2_SMEM 107520
__global__ void __launch_bounds__(256) k_head1_mma(
    const float* __restrict__ hb1,
    const float* __restrict__ hlg, const float* __restrict__ hlb)
{
    extern __shared__ __align__(16) char dsm[];
    uint32_t* As = (uint32_t*)dsm;                 // 20480 B (4*64*20 w)
    uint32_t* Bs = (uint32_t*)(dsm + 20480);       // 81920 B (4*256*20 w)
    float* sB  = (float*)(dsm + 102400);
    float* sG  = (float*)(dsm + 103424);
    float* sBt = (float*)(dsm + 104448);
    float* ps  = (float*)(dsm + 105472);           // 64*4
    float* pq  = (float*)(dsm + 106496);           // 64*4

    const int h = blockIdx.y;
    const int t0 = blockIdx.x * 64;
    const int tid = threadIdx.x, w = tid >> 5, l = tid & 31;
    const int wr = w >> 2, wc = w & 3, g = l >> 2, tig = l & 3;

    sB[tid] = hb1[h * 256 + tid]; sG[tid] = hlg[h * 256 + tid]; sBt[tid] = hlb[h * 256 + tid];

    // ldmatrix lane offsets (bytes within a stage)
    const uint32_t sbase = (uint32_t)__cvta_generic_to_shared(dsm);
    const int aRow = (l & 7) + ((l >> 3) & 1) * 8;
    const int aCol = (l >> 4) * 4;
    const uint32_t aLane = (uint32_t)(((wr * 32 + aRow) * 20 + aCol) * 4);
    const int bRow = wc * 64 + ((l >> 3) * 8) + (l & 7);
    const uint32_t bLaneA = (uint32_t)(bRow * 80);
    const uint32_t bLaneB = bLaneA + 2560;   // +32 n rows

    float acc[2][8][4];
#pragma unroll
    for (int mt = 0; mt < 2; mt++)
#pragma unroll
        for (int nt = 0; nt < 8; nt++)
#pragma unroll
            for (int i = 0; i < 4; i++) acc[mt][nt][i] = 0.f;

    const float* WpT = g_hW1tT + (size_t)h * 131072;
    const int ar = tid >> 2, ac4 = (tid & 3) * 4;
    const float* Ap = g_xnt + (size_t)(t0 + ar) * 512 + ac4;

    auto load_stage = [&](int s, int k0) {
        cp16(&As[s * 1280 + ar * 20 + ac4], Ap + k0);
        const float* src = WpT + (size_t)(k0 >> 4) * 4096 + tid * 16;
        uint32_t* dst = &Bs[s * 5120 + tid * 20];
#pragma unroll
        for (int q = 0; q < 4; q++) cp16(dst + q * 4, src + q * 4);
    };

    load_stage(0, 0);  CP_COMMIT();
    load_stage(1, 16); CP_COMMIT();
    load_stage(2, 32); CP_COMMIT();
    int cur = 0;
    for (int it = 0; it < 32; it++) {
        CP_WAIT_2();
        __syncthreads();
        if (it + 3 < 32) load_stage((cur + 3) & 3, (it + 3) * 16);
        CP_COMMIT();
        const uint32_t aB = sbase + cur * 5120;
        const uint32_t bB = sbase + 20480 + cur * 20480;
#pragma unroll
        for (int ks = 0; ks < 16; ks += 8) {
            uint32_t af0[4], af1[4];
            LDSM4(af0[0], af0[1], af0[2], af0[3], aB + aLane + ks * 4);
            LDSM4(af1[0], af1[1], af1[2], af1[3], aB + aLane + 1280 + ks * 4);
            uint32_t b0lo[4], b0hi[4], b1lo[4], b1hi[4];
            LDSM4(b0lo[0], b0lo[1], b0lo[2], b0lo[3], bB + bLaneA + ks * 4);
            LDSM4(b0hi[0], b0hi[1], b0hi[2], b0hi[3], bB + bLaneB + ks * 4);
            LDSM4(b1lo[0], b1lo[1], b1lo[2], b1lo[3], bB + bLaneA + (ks + 4) * 4);
            LDSM4(b1hi[0], b1hi[1], b1hi[2], b1hi[3], bB + bLaneB + (ks + 4) * 4);
#pragma unroll
            for (int nt = 0; nt < 4; nt++) {
                mma_tf32(acc[0][nt], af0, b0lo[nt], b1lo[nt]);
                mma_tf32(acc[1][nt], af1, b0lo[nt], b1lo[nt]);
            }
#pragma unroll
            for (int nt = 0; nt < 4; nt++) {
                mma_tf32(acc[0][nt + 4], af0, b0hi[nt], b1hi[nt]);
                mma_tf32(acc[1][nt + 4], af1, b0hi[nt], b1hi[nt]);
            }
        }
        cur = (cur + 1) & 3;
    }
    __syncthreads();

    // epilogue: bias + LN(256) + gelu ; store tf32-rounded
    float rsm[4] = {0, 0, 0, 0}, rsq[4] = {0, 0, 0, 0};
#pragma unroll
    for (int mt = 0; mt < 2; mt++)
#pragma unroll
        for (int nt = 0; nt < 8; nt++) {
            int c0 = wc * 64 + nt * 8 + 2 * tig;
            float v0 = acc[mt][nt][0] + sB[c0], v1 = acc[mt][nt][1] + sB[c0 + 1];
            float v2 = acc[mt][nt][2] + sB[c0], v3 = acc[mt][nt][3] + sB[c0 + 1];
            acc[mt][nt][0] = v0; acc[mt][nt][1] = v1; acc[mt][nt][2] = v2; acc[mt][nt][3] = v3;
            rsm[mt * 2 + 0] += v0 + v1; rsq[mt * 2 + 0] += v0 * v0 + v1 * v1;
            rsm[mt * 2 + 1] += v2 + v3; rsq[mt * 2 + 1] += v2 * v2 + v3 * v3;
        }
#pragma unroll
    for (int off = 1; off < 4; off <<= 1)
#pragma unroll
        for (int q = 0; q < 4; q++) {
            rsm[q] += __shfl_xor_sync(0xffffffffu, rsm[q], off);
            rsq[q] += __shfl_xor_sync(0xffffffffu, rsq[q], off);
        }
    if (tig == 0) {
#pragma unroll
        for (int q = 0; q < 4; q++) {
            int row = wr * 32 + (q >> 1) * 16 + (q & 1) * 8 + g;
            ps[row * 4 + wc] = rsm[q]; pq[row * 4 + wc] = rsq[q];
        }
    }
    __syncthreads();
    float mv[4], rv[4];
#pragma unroll
    for (int q = 0; q < 4; q++) {
        int row = wr * 32 + (q >> 1) * 16 + (q & 1) * 8 + g;
        float s  = ps[row * 4 + 0] + ps[row * 4 + 1] + ps[row * 4 + 2] + ps[row * 4 + 3];
        float s2 = pq[row * 4 + 0] + pq[row * 4 + 1] + pq[row * 4 + 2] + pq[row * 4 + 3];
        float m = s * (1.f / 256.f);
        float var = s2 * (1.f / 256.f) - m * m;
        mv[q] = m; rv[q] = rsqrtf(var + EPSV);
    }
#pragma unroll
    for (int mt = 0; mt < 2; mt++)
#pragma unroll
        for (int nt = 0; nt < 8; nt++) {
            int c0 = wc * 64 + nt * 8 + 2 * tig;
            int q0 = mt * 2;
            int row0 = t0 + wr * 32 + mt * 16 + g;
            float u0 = gelu_exact((acc[mt][nt][0] - mv[q0]) * rv[q0] * sG[c0] + sBt[c0]);
            float u1 = gelu_exact((acc[mt][nt][1] - mv[q0]) * rv[q0] * sG[c0 + 1] + sBt[c0 + 1]);
            *(float2*)&g_h[(size_t)row0 * 1024 + h * 256 + c0] =
                make_float2(f2tf_f(u0), f2tf_f(u1));
            float u2 = gelu_exact((acc[mt][nt][2] - mv[q0 + 1]) * rv[q0 + 1] * sG[c0] + sBt[c0]);
            float u3 = gelu_exact((acc[mt][nt][3] - mv[q0 + 1]) * rv[q0 + 1] * sG[c0 + 1] + sBt[c0 + 1]);
            *(float2*)&g_h[(size_t)(row0 + 8) * 1024 + h * 256 + c0] =
                make_float2(f2tf_f(u2), f2tf_f(u3));
        }
}

// ============================================================================
// K3: state GEMM (3-stage) ; [dyn|sa] GEMM (3-stage) ; softmax mix.
// (R10 verbatim — 256 threads, 2 CTAs/SM.)
// ============================================================================
#define K3_SMEM 88864
__global__ void __launch_bounds__(256, 2) k_head2_mma(
    const float* __restrict__ hb2, const float* __restrict__ attr)
{
    extern __shared__ __align__(16) char dsm[];
    uint32_t* As  = (uint32_t*)dsm;                // 15360 (3*64*20)
    uint32_t* Bs  = (uint32_t*)(dsm + 15360);      // 26112 (3*16*136)
    float*    Ss  = (float*)(dsm + 41472);         // 33792 (64*132)
    float*    At  = (float*)(dsm + 75264);         //  4096 (8*128)
    uint32_t* AtT = (uint32_t*)(dsm + 79360);      //  4096 (128*8)
    float*    Sa  = (float*)(dsm + 83456);         //  2048
    float*    Sw  = (float*)(dsm + 85504);         //  2048
    float*    s2p = (float*)(dsm + 87552);         //  1024
    float*    a2s = (float*)(dsm + 88576);         //    32
    float*    Sgt = (float*)(dsm + 88608);         //   256

    const int h = blockIdx.y;
    const int t0 = blockIdx.x * 64;
    const int tid = threadIdx.x, w = tid >> 5, l = tid & 31;
    const int wr = w >> 2, wc = w & 3, g = l >> 2, tig = l & 3;

    {
        float4 v = *(const float4*)(attr + (size_t)h * 1024 + tid * 4);
        *(float4*)&At[tid * 4] = v;
        int a0 = tid >> 5, d0 = (tid & 31) * 4;
        AtT[(d0 + 0) * 8 + a0] = f2tf(v.x);
        AtT[(d0 + 1) * 8 + a0] = f2tf(v.y);
        AtT[(d0 + 2) * 8 + a0] = f2tf(v.z);
        AtT[(d0 + 3) * 8 + a0] = f2tf(v.w);
    }

    float acc[2][4][4];
#pragma unroll
    for (int mt = 0; mt < 2; mt++)
#pragma unroll
        for (int nt = 0; nt < 4; nt++)
#pragma unroll
            for (int i = 0; i < 4; i++) acc[mt][nt][i] = 0.f;

    const int ar = tid >> 2, ac4 = (tid & 3) * 4;
    const float* Ap = g_h + (size_t)(t0 + ar) * 1024 + h * 256 + ac4;
    const float* Wp = g_hW2t + (size_t)h * 256 * 128;

    auto load_stage1 = [&](int s, int k0) {
        cp16(&As[s * 1280 + ar * 20 + ac4], Ap + k0);
#pragma unroll
        for (int i = 0; i < 2; i++) {
            int idx = tid + 256 * i;
            int kk = idx >> 5, c4 = (idx & 31) * 4;
            cp16(&Bs[s * 2176 + kk * 136 + c4], Wp + (size_t)(k0 + kk) * 128 + c4);
        }
    };

    load_stage1(0, 0);  CP_COMMIT();
    load_stage1(1, 16); CP_COMMIT();
    __syncthreads();
    if (tid < 8) {
        float q = 0.f;
#pragma unroll
        for (int k = 0; k < 128; k++) q += At[tid * 128 + k] * At[tid * 128 + k];
        a2s[tid] = q;
    }

    int cur = 0;
    for (int it = 0; it < 16; it++) {
        CP_WAIT_1();
        __syncthreads();
        if (it + 2 < 16) load_stage1((cur + 2 >= 3) ? cur - 1 : cur + 2, (it + 2) * 16);
        CP_COMMIT();
        const uint32_t* Ab = &As[cur * 1280];
        const uint32_t* Bb = &Bs[cur * 2176];
#pragma unroll
        for (int ks = 0; ks < 16; ks += 8) {
            uint32_t af[2][4];
#pragma unroll
            for (int mt = 0; mt < 2; mt++) {
                int rb = (wr * 32 + mt * 16 + g) * 20 + ks;
                af[mt][0] = Ab[rb + tig];       af[mt][1] = Ab[rb + 160 + tig];
                af[mt][2] = Ab[rb + tig + 4];   af[mt][3] = Ab[rb + 160 + tig + 4];
            }
#pragma unroll
            for (int nt = 0; nt < 4; nt++) {
                int cb = wc * 32 + nt * 8 + g;
                uint32_t b0 = Bb[(ks + tig) * 136 + cb];
                uint32_t b1 = Bb[(ks + tig + 4) * 136 + cb];
                mma_tf32(acc[0][nt], af[0], b0, b1);
                mma_tf32(acc[1][nt], af[1], b0, b1);
            }
        }
        cur = (cur + 1 == 3) ? 0 : cur + 1;
    }
    __syncthreads();

    const float* Dp = g_dynt + (size_t)h * 128 * 128;
    auto load_stage2 = [&](int s, int k0) {
#pragma unroll
        for (int i = 0; i < 2; i++) {
            int idx = tid + 256 * i;
            int kk = idx >> 5, c4 = (idx & 31) * 4;
            cp16(&Bs[s * 2176 + kk * 136 + c4], Dp + (size_t)(k0 + kk) * 128 + c4);
        }
    };
    load_stage2(0, 0);  CP_COMMIT();
    load_stage2(1, 16); CP_COMMIT();

    {
        float rq[4] = {0, 0, 0, 0};
#pragma unroll
        for (int mt = 0; mt < 2; mt++)
#pragma unroll
            for (int nt = 0; nt < 4; nt++) {
                int c0 = wc * 32 + nt * 8 + 2 * tig;
                int row = wr * 32 + mt * 16 + g;
                float b0v = hb2[h * 128 + c0], b1v = hb2[h * 128 + c0 + 1];
                float v0 = f2tf_f(acc[mt][nt][0] + b0v);
                float v1 = f2tf_f(acc[mt][nt][1] + b1v);
                float v2 = f2tf_f(acc[mt][nt][2] + b0v);
                float v3 = f2tf_f(acc[mt][nt][3] + b1v);
                Ss[row * 132 + c0]           = v0;
                Ss[row * 132 + c0 + 1]       = v1;
                Ss[(row + 8) * 132 + c0]     = v2;
                Ss[(row + 8) * 132 + c0 + 1] = v3;
                rq[mt * 2 + 0] += v0 * v0 + v1 * v1;
                rq[mt * 2 + 1] += v2 * v2 + v3 * v3;
            }
#pragma unroll
        for (int off = 1; off < 4; off <<= 1)
#pragma unroll
            for (int q = 0; q < 4; q++)
                rq[q] += __shfl_xor_sync(0xffffffffu, rq[q], off);
        if (tig == 0) {
#pragma unroll
            for (int q = 0; q < 4; q++) {
                int row = wr * 32 + (q >> 1) * 16 + (q & 1) * 8 + g;
                s2p[row * 4 + wc] = rq[q];
            }
        }
    }
    __syncthreads();

    float dcc[2][4][4];
    float scc[2][4];
#pragma unroll
    for (int mt = 0; mt < 2; mt++) {
#pragma unroll
        for (int nt = 0; nt < 4; nt++)
#pragma unroll
            for (int i = 0; i < 4; i++) dcc[mt][nt][i] = 0.f;
#pragma unroll
        for (int i = 0; i < 4; i++) scc[mt][i] = 0.f;
    }

    cur = 0;
    for (int it = 0; it < 8; it++) {
        CP_WAIT_1();
        __syncthreads();
        if (it + 2 < 8) load_stage2((cur + 2 >= 3) ? cur - 1 : cur + 2, (it + 2) * 16);
        CP_COMMIT();
        const uint32_t* Bb = &Bs[cur * 2176];
        const int kbase = it * 16;
#pragma unroll
        for (int ks = 0; ks < 16; ks += 8) {
            uint32_t af[2][4];
#pragma unroll
            for (int mt = 0; mt < 2; mt++) {
                int rb = (wr * 32 + mt * 16 + g) * 132 + kbase + ks;
                af[mt][0] = __float_as_uint(Ss[rb + tig]);
                af[mt][1] = __float_as_uint(Ss[rb + 8 * 132 + tig]);
                af[mt][2] = __float_as_uint(Ss[rb + tig + 4]);
                af[mt][3] = __float_as_uint(Ss[rb + 8 * 132 + tig + 4]);
            }
#pragma unroll
            for (int nt = 0; nt < 4; nt++) {
                int cb = wc * 32 + nt * 8 + g;
                uint32_t b0 = Bb[(ks + tig) * 136 + cb];
                uint32_t b1 = Bb[(ks + tig + 4) * 136 + cb];
                mma_tf32(dcc[0][nt], af[0], b0, b1);
                mma_tf32(dcc[1][nt], af[1], b0, b1);
            }
            uint32_t b0s = AtT[(kbase + ks + tig) * 8 + g];
            uint32_t b1s = AtT[(kbase + ks + tig + 4) * 8 + g];
            mma_tf32(scc[0], af[0], b0s, b1s);
            mma_tf32(scc[1], af[1], b0s, b1s);
        }
        cur = (cur + 1 == 3) ? 0 : cur + 1;
    }
    __syncthreads();

    if (wc == 0) {
#pragma unroll
        for (int mt = 0; mt < 2; mt++) {
            int row = wr * 32 + mt * 16 + g;
            Sa[row * 8 + 2 * tig]           = scc[mt][0];
            Sa[row * 8 + 2 * tig + 1]       = scc[mt][1];
            Sa[(row + 8) * 8 + 2 * tig]     = scc[mt][2];
            Sa[(row + 8) * 8 + 2 * tig + 1] = scc[mt][3];
        }
    }
    __syncthreads();

    const float invs = 0.08838834764831845f;  // 1/sqrt(128)
    if (tid < 64) {
        int row = tid;
        float s2 = s2p[row * 4 + 0] + s2p[row * 4 + 1] + s2p[row * 4 + 2] + s2p[row * 4 + 3];
        float lgt[8], mx = -1e30f;
#pragma unroll
        for (int a = 0; a < 8; a++) {
            float dd = sqrtf(fmaxf(s2 + a2s[a] - 2.0f * Sa[row * 8 + a], 0.0f));
            lgt[a] = -dd * invs;
            mx = fmaxf(mx, lgt[a]);
        }
        float e[8], se = 0.f;
#pragma unroll
        for (int a = 0; a < 8; a++) { e[a] = expf(lgt[a] - mx); se += e[a]; }
        float ise = 1.0f / se;
#pragma unroll
        for (int a = 0; a < 8; a++) Sw[row * 8 + a] = e[a] * ise;
        Sgt[row] = 0.1f * g_gate[(size_t)(t0 + row) * 4 + h];
    }
    __syncthreads();

#pragma unroll
    for (int mt = 0; mt < 2; mt++)
#pragma unroll
        for (int nt = 0; nt < 4; nt++) {
            int c0 = wc * 32 + nt * 8 + 2 * tig;
#pragma unroll
            for (int half = 0; half < 2; half++) {
                int row = wr * 32 + mt * 16 + g + 8 * half;
                float gt = Sgt[row];
                float sv0 = Ss[row * 132 + c0];
                float sv1 = Ss[row * 132 + c0 + 1];
                float ai0 = 0.f, ai1 = 0.f;
#pragma unroll
                for (int a = 0; a < 8; a++) {
                    float wgt = Sw[row * 8 + a];
                    ai0 += wgt * At[a * 128 + c0];
                    ai1 += wgt * At[a * 128 + c0 + 1];
                }
                float dv0 = dcc[mt][nt][2 * half + 0];
                float dv1 = dcc[mt][nt][2 * half + 1];
                float o0 = f2tf_f(sv0 + gt * (ai0 - sv0 + tanhf(dv0)));
                float o1 = f2tf_f(sv1 + gt * (ai1 - sv1 + tanhf(dv1)));
                *(float2*)&g_comb[(size_t)(t0 + row) * 512 + h * 128 + c0] =
                    make_float2(o0, o1);
            }
        }
}

// ============================================================================
// K4: o1 = gelu(LN(comb @ oW1 + ob1)).  BM=64,BN=512, 4-stage, ldmatrix frags.
// smem: As 20480 | BsN 4*40960 | sB sG sBt 6144 | ps pq 4096 = 194560 B
// ============================================================================
#define K4_SMEM 194560
__global__ void __launch_bounds__(512) k_out1_mma(
    const float* __restrict__ ob1,
    const float* __restrict__ olg, const float* __restrict__ olb)
{
    extern __shared__ __align__(16) char dsm[];
    uint32_t* As = (uint32_t*)dsm;                 // 20480 B
    uint32_t* Bs = (uint32_t*)(dsm + 20480);       // 163840 B (4*512*20 w)
    float* sB  = (float*)(dsm + 184320);
    float* sG  = (float*)(dsm + 186368);
    float* sBt = (float*)(dsm + 188416);
    float* ps  = (float*)(dsm + 190464);           // 64*8
    float* pq  = (float*)(dsm + 192512);

    const int t0 = blockIdx.x * 64;
    const int tid = threadIdx.x, w = tid >> 5, l = tid & 31;
    const int wr = w >> 3, wc = w & 7, g = l >> 2, tig = l & 3;

    sB[tid] = ob1[tid]; sG[tid] = olg[tid]; sBt[tid] = olb[tid];

    const uint32_t sbase = (uint32_t)__cvta_generic_to_shared(dsm);
    const int aRow = (l & 7) + ((l >> 3) & 1) * 8;
    const int aCol = (l >> 4) * 4;
    const uint32_t aLane = (uint32_t)(((wr * 32 + aRow) * 20 + aCol) * 4);
    const int bRow = wc * 64 + ((l >> 3) * 8) + (l & 7);
    const uint32_t bLaneA = (uint32_t)(bRow * 80);
    const uint32_t bLaneB = bLaneA + 2560;

    float acc[2][8][4];
#pragma unroll
    for (int mt = 0; mt < 2; mt++)
#pragma unroll
        for (int nt = 0; nt < 8; nt++)
#pragma unroll
            for (int i = 0; i < 4; i++) acc[mt][nt][i] = 0.f;

    const int ar = tid >> 2, ac4 = (tid & 3) * 4;
    const float* Ap = g_comb + (size_t)(t0 + (ar & 63)) * 512 + ac4;

    auto load_stage = [&](int s, int k0) {
        if (tid < 256) cp16(&As[s * 1280 + ar * 20 + ac4], Ap + k0);
        const float* src = g_oW1tT + (size_t)(k0 >> 4) * 8192 + tid * 16;
        uint32_t* dst = &Bs[s * 10240 + tid * 20];
#pragma unroll
        for (int q = 0; q < 4; q++) cp16(dst + q * 4, src + q * 4);
    };

    load_stage(0, 0);  CP_COMMIT();
    load_stage(1, 16); CP_COMMIT();
    load_stage(2, 32); CP_COMMIT();
    int cur = 0;
    for (int it = 0; it < 32; it++) {
        CP_WAIT_2();
        __syncthreads();
        if (it + 3 < 32) load_stage((cur + 3) & 3, (it + 3) * 16);
        CP_COMMIT();
        const uint32_t aB = sbase + cur * 5120;
        const uint32_t bB = sbase + 20480 + cur * 40960;
#pragma unroll
        for (int ks = 0; ks < 16; ks += 8) {
            uint32_t af0[4], af1[4];
            LDSM4(af0[0], af0[1], af0[2], af0[3], aB + aLane + ks * 4);
            LDSM4(af1[0], af1[1], af1[2], af1[3], aB + aLane + 1280 + ks * 4);
            uint32_t b0lo[4], b0hi[4], b1lo[4], b1hi[4];
            LDSM4(b0lo[0], b0lo[1], b0lo[2], b0lo[3], bB + bLaneA + ks * 4);
            LDSM4(b0hi[0], b0hi[1], b0hi[2], b0hi[3], bB + bLaneB + ks * 4);
            LDSM4(b1lo[0], b1lo[1], b1lo[2], b1lo[3], bB + bLaneA + (ks + 4) * 4);
            LDSM4(b1hi[0], b1hi[1], b1hi[2], b1hi[3], bB + bLaneB + (ks + 4) * 4);
#pragma unroll
            for (int nt = 0; nt < 4; nt++) {
                mma_tf32(acc[0][nt], af0, b0lo[nt], b1lo[nt]);
                mma_tf32(acc[1][nt], af1, b0lo[nt], b1lo[nt]);
            }
#pragma unroll
            for (int nt = 0; nt < 4; nt++) {
                mma_tf32(acc[0][nt + 4], af0, b0hi[nt], b1hi[nt]);
                mma_tf32(acc[1][nt + 4], af1, b0hi[nt], b1hi[nt]);
            }
        }
        cur = (cur + 1) & 3;
    }
    __syncthreads();

    float rsm[4] = {0, 0, 0, 0}, rsq[4] = {0, 0, 0, 0};
#pragma unroll
    for (int mt = 0; mt < 2; mt++)
#pragma unroll
        for (int nt = 0; nt < 8; nt++) {
            int c0 = wc * 64 + nt * 8 + 2 * tig;
            float v0 = acc[mt][nt][0] + sB[c0], v1 = acc[mt][nt][1] + sB[c0 + 1];
            float v2 = acc[mt][nt][2] + sB[c0], v3 = acc[mt][nt][3] + sB[c0 + 1];
            acc[mt][nt][0] = v0; acc[mt][nt][1] = v1; acc[mt][nt][2] = v2; acc[mt][nt][3] = v3;
            rsm[mt * 2 + 0] += v0 + v1; rsq[mt * 2 + 0] += v0 * v0 + v1 * v1;
            rsm[mt * 2 + 1] += v2 + v3; rsq[mt * 2 + 1] += v2 * v2 + v3 * v3;
        }
#pragma unroll
    for (int off = 1; off < 4; off <<= 1)
#pragma unroll
        for (int q = 0; q < 4; q++) {
            rsm[q] += __shfl_xor_sync(0xffffffffu, rsm[q], off);
            rsq[q] += __shfl_xor_sync(0xffffffffu, rsq[q], off);
        }
    if (tig == 0) {
#pragma unroll
        for (int q = 0; q < 4; q++) {
            int row = wr * 32 + (q >> 1) * 16 + (q & 1) * 8 + g;
            ps[row * 8 + wc] = rsm[q]; pq[row * 8 + wc] = rsq[q];
        }
    }
    __syncthreads();
    float mv[4], rv[4];
#pragma unroll
    for (int q = 0; q < 4; q++) {
        int row = wr * 32 + (q >> 1) * 16 + (q & 1) * 8 + g;
        float s = 0.f, s2 = 0.f;
#pragma unroll
        for (int j = 0; j < 8; j++) { s += ps[row * 8 + j]; s2 += pq[row * 8 + j]; }
        float m = s * (1.f / 512.f);
        float var = s2 * (1.f / 512.f) - m * m;
        mv[q] = m; rv[q] = rsqrtf(var + EPSV);
    }
#pragma unroll
    for (int mt = 0; mt < 2; mt++)
#pragma unroll
        for (int nt = 0; nt < 8; nt++) {
            int c0 = wc * 64 + nt * 8 + 2 * tig;
            int q0 = mt * 2;
            int row0 = t0 + wr * 32 + mt * 16 + g;
            float u0 = gelu_exact((acc[mt][nt][0] - mv[q0]) * rv[q0] * sG[c0] + sBt[c0]);
            float u1 = gelu_exact((acc[mt][nt][1] - mv[q0]) * rv[q0] * sG[c0 + 1] + sBt[c0 + 1]);
            *(float2*)&g_oact[(size_t)row0 * 512 + c0] = make_float2(f2tf_f(u0), f2tf_f(u1));
            float u2 = gelu_exact((acc[mt][nt][2] - mv[q0 + 1]) * rv[q0 + 1] * sG[c0] + sBt[c0]);
            float u3 = gelu_exact((acc[mt][nt][3] - mv[q0 + 1]) * rv[q0 + 1] * sG[c0 + 1] + sBt[c0 + 1]);
            *(float2*)&g_oact[(size_t)(row0 + 8) * 512 + c0] = make_float2(f2tf_f(u2), f2tf_f(u3));
        }
}

// ============================================================================
// K5: out = xn + oact @ oW2 + ob2.  BM=64,BN=512, 4-stage, ldmatrix frags.
// smem: As 20480 | BsN 163840 | sB 2048 = 186368 B
// ============================================================================
#define K5_SMEM 186368
__global__ void __launch_bounds__(512) k_out2_mma(
    const float* __restrict__ ob2, float* __restrict__ out)
{
    extern __shared__ __align__(16) char dsm[];
    uint32_t* As = (uint32_t*)dsm;                 // 20480
    uint32_t* Bs = (uint32_t*)(dsm + 20480);       // 163840
    float* sB = (float*)(dsm + 184320);

    const int t0 = blockIdx.x * 64;
    const int tid = threadIdx.x, w = tid >> 5, l = tid & 31;
    const int wr = w >> 3, wc = w & 7, g = l >> 2, tig = l & 3;

    sB[tid] = ob2[tid];

    const uint32_t sbase = (uint32_t)__cvta_generic_to_shared(dsm);
    const int aRow = (l & 7) + ((l >> 3) & 1) * 8;
    const int aCol = (l >> 4) * 4;
    const uint32_t aLane = (uint32_t)(((wr * 32 + aRow) * 20 + aCol) * 4);
    const int bRow = wc * 64 + ((l >> 3) * 8) + (l & 7);
    const uint32_t bLaneA = (uint32_t)(bRow * 80);
    const uint32_t bLaneB = bLaneA + 2560;

    float acc[2][8][4];
#pragma unroll
    for (int mt = 0; mt < 2; mt++)
#pragma unroll
        for (int nt = 0; nt < 8; nt++)
#pragma unroll
            for (int i = 0; i < 4; i++) acc[mt][nt][i] = 0.f;

    const int ar = tid >> 2, ac4 = (tid & 3) * 4;
    const float* Ap = g_oact + (size_t)(t0 + (ar & 63)) * 512 + ac4;

    auto load_stage = [&](int s, int k0) {
        if (tid < 256) cp16(&As[s * 1280 + ar * 20 + ac4], Ap + k0);
        const float* src = g_oW2tT + (size_t)(k0 >> 4) * 8192 + tid * 16;
        uint32_t* dst = &Bs[s * 10240 + tid * 20];
#pragma unroll
        for (int q = 0; q < 4; q++) cp16(dst + q * 4, src + q * 4);
    };

    load_stage(0, 0);  CP_COMMIT();
    load_stage(1, 16); CP_COMMIT();
    load_stage(2, 32); CP_COMMIT();
    int cur = 0;
    for (int it = 0; it < 32; it++) {
        CP_WAIT_2();
        __syncthreads();
        if (it + 3 < 32) load_stage((cur + 3) & 3, (it + 3) * 16);
        CP_COMMIT();
        const uint32_t aB = sbase + cur * 5120;
        const uint32_t bB = sbase + 20480 + cur * 40960;
#pragma unroll
        for (int ks = 0; ks < 16; ks += 8) {
            uint32_t af0[4], af1[4];
            LDSM4(af0[0], af0[1], af0[2], af0[3], aB + aLane + ks * 4);
            LDSM4(af1[0], af1[1], af1[2], af1[3], aB + aLane + 1280 + ks * 4);
            uint32_t b0lo[4], b0hi[4], b1lo[4], b1hi[4];
            LDSM4(b0lo[0], b0lo[1], b0lo[2], b0lo[3], bB + bLaneA + ks * 4);
            LDSM4(b0hi[0], b0hi[1], b0hi[2], b0hi[3], bB + bLaneB + ks * 4);
            LDSM4(b1lo[0], b1lo[1], b1lo[2], b1lo[3], bB + bLaneA + (ks + 4) * 4);
            LDSM4(b1hi[0], b1hi[1], b1hi[2], b1hi[3], bB + bLaneB + (ks + 4) * 4);
#pragma unroll
            for (int nt = 0; nt < 4; nt++) {
                mma_tf32(acc[0][nt], af0, b0lo[nt], b1lo[nt]);
                mma_tf32(acc[1][nt], af1, b0lo[nt], b1lo[nt]);
            }
#pragma unroll
            for (int nt = 0; nt < 4; nt++) {
                mma_tf32(acc[0][nt + 4], af0, b0hi[nt], b1hi[nt]);
                mma_tf32(acc[1][nt + 4], af1, b0hi[nt], b1hi[nt]);
            }
        }
        cur = (cur + 1) & 3;
    }

#pragma unroll
    for (int mt = 0; mt < 2; mt++)
#pragma unroll
        for (int nt = 0; nt < 8; nt++) {
            int c0 = wc * 64 + nt * 8 + 2 * tig;
            int row0 = t0 + wr * 32 + mt * 16 + g;
            size_t o0 = (size_t)row0 * 512 + c0;
            size_t o1 = (size_t)(row0 + 8) * 512 + c0;
            float2 x0 = *(const float2*)&g_xn[o0];
            float2 x1 = *(const float2*)&g_xn[o1];
            *(float2*)&out[o0] = make_float2(acc[mt][nt][0] + sB[c0] + x0.x,
                                             acc[mt][nt][1] + sB[c0 + 1] + x0.y);
            *(float2*)&out[o1] = make_float2(acc[mt][nt][2] + sB[c0] + x1.x,
                                             acc[mt][nt][3] + sB[c0 + 1] + x1.y);
        }
}

// ============================================================================
extern "C" void kernel_launch(void* const* d_in, const int* in_sizes, int n_in,
                              void* d_out, int out_size)
{
    (void)in_sizes; (void)n_in; (void)out_size;
    const float* x    = (const float*)d_in[0];
    const float* ng   = (const float*)d_in[1];
    const float* nb   = (const float*)d_in[2];
    const float* hW1  = (const float*)d_in[3];
    const float* hb1  = (const float*)d_in[4];
    const float* hlg  = (const float*)d_in[5];
    const float* hlb  = (const float*)d_in[6];
    const float* hW2  = (const float*)d_in[7];
    const float* hb2  = (const float*)d_in[8];
    const float* attr = (const float*)d_in[9];
    const float* dynm = (const float*)d_in[10];
    const float* gW   = (const float*)d_in[11];
    const float* gb   = (const float*)d_in[12];
    const float* oW1  = (const float*)d_in[13];
    const float* ob1  = (const float*)d_in[14];
    const float* olg  = (const float*)d_in[15];
    const float* olb  = (const float*)d_in[16];
    const float* oW2  = (const float*)d_in[17];
    const float* ob2  = (const float*)d_in[18];
    float* out = (float*)d_out;

    cudaFuncSetAttribute(k_head1_mma, cudaFuncAttributeMaxDynamicSharedMemorySize, K2_SMEM);
    cudaFuncSetAttribute(k_head2_mma, cudaFuncAttributeMaxDynamicSharedMemorySize, K3_SMEM);
    cudaFuncSetAttribute(k_out1_mma,  cudaFuncAttributeMaxDynamicSharedMemorySize, K4_SMEM);
    cudaFuncSetAttribute(k_out2_mma,  cudaFuncAttributeMaxDynamicSharedMemorySize, K5_SMEM);

    k_prep<<<4864, 256>>>(hW1, hW2, dynm, oW1, oW2);
    k_ln_gate<<<8192, 256>>>(x, ng, nb, gW, gb);

    dim3 gh(T_TOK / 64, 4);
    k_head1_mma<<<gh, 256, K2_SMEM>>>(hb1, hlg, hlb);
    k_head2_mma<<<gh, 256, K3_SMEM>>>(hb2, attr);

    k_out1_mma<<<T_TOK / 64, 512, K4_SMEM>>>(ob1, olg, olb);
    k_out2_mma<<<T_TOK / 64, 512, K5_SMEM>>>(ob2, out);
}

// round 13
// speedup vs baseline: 1.4862x; 1.4862x over previous
#include <cuda_runtime.h>
#include <math.h>
#include <stdint.h>

// ----------------------------------------------------------------------------
// NoiseRobustAttractorLayer — TF32 mma.sync. R13: exact R10 (best verified,
// 1408.5us) with ONE change: K5 reshaped to K2's verified 256-thread geometry
// (BM=64, BN=256, grid (T/64, 2), 4-stage ring) -> 2 CTAs/SM instead of the
// register-capped 1 CTA of the 512-thread version. Bit-identical math.
// ----------------------------------------------------------------------------

#define T_TOK 65536
#define EPSV  1e-5f

__device__ float g_xn  [(size_t)T_TOK * 512];   // fp32 (residual)
__device__ float g_xnt [(size_t)T_TOK * 512];   // tf32-rounded (GEMM A)
__device__ float g_gate[(size_t)T_TOK * 4];
__device__ float g_h   [(size_t)T_TOK * 1024];  // tf32-rounded
__device__ float g_comb[(size_t)T_TOK * 512];   // tf32-rounded
__device__ float g_oact[(size_t)T_TOK * 512];   // tf32-rounded

__device__ float g_hW1t[4 * 512 * 256];
__device__ float g_hW2t[4 * 256 * 128];
__device__ float g_dynt[4 * 128 * 128];
__device__ float g_oW1t[512 * 512];
__device__ float g_oW2t[512 * 512];

__device__ __forceinline__ float warp_sum(float v) {
#pragma unroll
    for (int o = 16; o > 0; o >>= 1) v += __shfl_xor_sync(0xffffffffu, v, o);
    return v;
}
__device__ __forceinline__ float gelu_exact(float x) {
    return 0.5f * x * (1.0f + erff(x * 0.70710678118654752f));
}
__device__ __forceinline__ uint32_t f2tf(float x) {
    uint32_t r; asm("cvt.rna.tf32.f32 %0, %1;" : "=r"(r) : "f"(x)); return r;
}
__device__ __forceinline__ float f2tf_f(float x) {
    return __uint_as_float(f2tf(x));
}
__device__ __forceinline__ void mma_tf32(float c[4], const uint32_t a[4],
                                         uint32_t b0, uint32_t b1) {
    asm volatile(
        "mma.sync.aligned.m16n8k8.row.col.f32.tf32.tf32.f32 "
        "{%0,%1,%2,%3},{%4,%5,%6,%7},{%8,%9},{%0,%1,%2,%3};"
        : "+f"(c[0]), "+f"(c[1]), "+f"(c[2]), "+f"(c[3])
        : "r"(a[0]), "r"(a[1]), "r"(a[2]), "r"(a[3]), "r"(b0), "r"(b1));
}
__device__ __forceinline__ void cp16(void* s, const void* g) {
    uint32_t sa = (uint32_t)__cvta_generic_to_shared(s);
    asm volatile("cp.async.cg.shared.global [%0], [%1], 16;" :: "r"(sa), "l"(g));
}
#define CP_COMMIT()  asm volatile("cp.async.commit_group;")
#define CP_WAIT_1()  asm volatile("cp.async.wait_group 1;" ::: "memory")
#define CP_WAIT_2()  asm volatile("cp.async.wait_group 2;" ::: "memory")

// ============================================================================
// K0: weight pre-conversion fp32 -> tf32
// ============================================================================
__global__ void __launch_bounds__(256) k_prep(
    const float* __restrict__ hW1, const float* __restrict__ hW2,
    const float* __restrict__ dynm, const float* __restrict__ oW1,
    const float* __restrict__ oW2)
{
    int i = blockIdx.x * 256 + threadIdx.x;
    if (i < 524288)       g_hW1t[i]           = f2tf_f(hW1[i]);
    else if (i < 655360)  g_hW2t[i - 524288]  = f2tf_f(hW2[i - 524288]);
    else if (i < 720896)  g_dynt[i - 655360]  = f2tf_f(dynm[i - 655360]);
    else if (i < 983040)  g_oW1t[i - 720896]  = f2tf_f(oW1[i - 720896]);
    else if (i < 1245184) g_oW2t[i - 983040]  = f2tf_f(oW2[i - 983040]);
}

// ============================================================================
// K1: warp-per-token LN + gate (R10 verbatim).
// ============================================================================
__global__ void __launch_bounds__(256) k_ln_gate(
    const float* __restrict__ x, const float* __restrict__ ng,
    const float* __restrict__ nb, const float* __restrict__ gW,
    const float* __restrict__ gb)
{
    __shared__ float sgW[2048];
    __shared__ float sng[512], snb[512];
    const int tid = threadIdx.x;
    for (int i = tid; i < 2048; i += 256) sgW[i] = gW[i];
    for (int i = tid; i < 512; i += 256) { sng[i] = ng[i]; snb[i] = nb[i]; }
    __syncthreads();

    const int wid = tid >> 5, l = tid & 31;
    const float gb0 = gb[0], gb1 = gb[1], gb2 = gb[2], gb3 = gb[3];
    const float4* sgW4 = (const float4*)sgW;
    const float4* sng4 = (const float4*)sng;
    const float4* snb4 = (const float4*)snb;

    for (int t = blockIdx.x * 8 + wid; t < T_TOK; t += gridDim.x * 8) {
        const float4* xr = (const float4*)(x + (size_t)t * 512);
        float4 v[4];
#pragma unroll
        for (int j = 0; j < 4; j++) v[j] = xr[l + 32 * j];
        float s = 0.f;
#pragma unroll
        for (int j = 0; j < 4; j++) s += v[j].x + v[j].y + v[j].z + v[j].w;
        s = warp_sum(s);
        float m = s * (1.0f / 512.0f);
        float q = 0.f;
#pragma unroll
        for (int j = 0; j < 4; j++) {
            float dx = v[j].x - m, dy = v[j].y - m, dz = v[j].z - m, dw = v[j].w - m;
            q += dx * dx + dy * dy + dz * dz + dw * dw;
        }
        q = warp_sum(q);
        float rs = rsqrtf(q * (1.0f / 512.0f) + EPSV);

        float4 xnv[4];
        float4* xo  = (float4*)(g_xn  + (size_t)t * 512);
        float4* xot = (float4*)(g_xnt + (size_t)t * 512);
#pragma unroll
        for (int j = 0; j < 4; j++) {
            float4 gv = sng4[l + 32 * j];
            float4 bv = snb4[l + 32 * j];
            xnv[j].x = (v[j].x - m) * rs * gv.x + bv.x;
            xnv[j].y = (v[j].y - m) * rs * gv.y + bv.y;
            xnv[j].z = (v[j].z - m) * rs * gv.z + bv.z;
            xnv[j].w = (v[j].w - m) * rs * gv.w + bv.w;
            xo[l + 32 * j] = xnv[j];
            float4 tv;
            tv.x = f2tf_f(xnv[j].x); tv.y = f2tf_f(xnv[j].y);
            tv.z = f2tf_f(xnv[j].z); tv.w = f2tf_f(xnv[j].w);
            xot[l + 32 * j] = tv;
        }
        float p[4] = {0.f, 0.f, 0.f, 0.f};
#pragma unroll
        for (int h = 0; h < 4; h++) {
#pragma unroll
            for (int j = 0; j < 4; j++) {
                float4 wv = sgW4[h * 128 + l + 32 * j];
                p[h] += xnv[j].x * wv.x + xnv[j].y * wv.y
                      + xnv[j].z * wv.z + xnv[j].w * wv.w;
            }
            p[h] = warp_sum(p[h]);
        }
        if (l == 0) {
            g_gate[(size_t)t * 4 + 0] = 1.0f / (1.0f + expf(-(p[0] + gb0)));
            g_gate[(size_t)t * 4 + 1] = 1.0f / (1.0f + expf(-(p[1] + gb1)));
            g_gate[(size_t)t * 4 + 2] = 1.0f / (1.0f + expf(-(p[2] + gb2)));
            g_gate[(size_t)t * 4 + 3] = 1.0f / (1.0f + expf(-(p[3] + gb3)));
        }
    }
}

// ============================================================================
// K2: h = gelu(LN(xn @ hW1[h] + hb1)).  BM=64,BN=256, block 256, 4-stage ring.
// (R10 verbatim.)
// ============================================================================
#define K2_SMEM 93184
__global__ void __launch_bounds__(256) k_head1_mma(
    const float* __restrict__ hb1,
    const float* __restrict__ hlg, const float* __restrict__ hlb)
{
    extern __shared__ __align__(16) char dsm[];
    uint32_t* As = (uint32_t*)dsm;                 // 20480 (4*64*20)
    uint32_t* Bs = (uint32_t*)(dsm + 20480);       // 67584 (4*16*264)
    float* sB  = (float*)(dsm + 88064);
    float* sG  = (float*)(dsm + 89088);
    float* sBt = (float*)(dsm + 90112);
    float* ps  = (float*)(dsm + 91136);            // 64*4
    float* pq  = (float*)(dsm + 92160);            // 64*4

    const int h = blockIdx.y;
    const int t0 = blockIdx.x * 64;
    const int tid = threadIdx.x, w = tid >> 5, l = tid & 31;
    const int wr = w >> 2, wc = w & 3, g = l >> 2, tig = l & 3;

    sB[tid] = hb1[h * 256 + tid]; sG[tid] = hlg[h * 256 + tid]; sBt[tid] = hlb[h * 256 + tid];

    float acc[2][8][4];
#pragma unroll
    for (int mt = 0; mt < 2; mt++)
#pragma unroll
        for (int nt = 0; nt < 8; nt++)
#pragma unroll
            for (int i = 0; i < 4; i++) acc[mt][nt][i] = 0.f;

    const float* Wp = g_hW1t + (size_t)h * 512 * 256;
    const int ar = tid >> 2, ac4 = (tid & 3) * 4;
    const float* Ap = g_xnt + (size_t)(t0 + ar) * 512 + ac4;

    auto load_stage = [&](int s, int k0) {
        cp16(&As[s * 1280 + ar * 20 + ac4], Ap + k0);
#pragma unroll
        for (int i = 0; i < 4; i++) {
            int idx = tid + 256 * i;
            int kk = idx >> 6, c4 = (idx & 63) * 4;
            cp16(&Bs[s * 4224 + kk * 264 + c4], Wp + (size_t)(k0 + kk) * 256 + c4);
        }
    };

    load_stage(0, 0);  CP_COMMIT();
    load_stage(1, 16); CP_COMMIT();
    load_stage(2, 32); CP_COMMIT();
    int cur = 0;
    for (int it = 0; it < 32; it++) {
        CP_WAIT_2();
        __syncthreads();
        if (it + 3 < 32) load_stage((cur + 3) & 3, (it + 3) * 16);
        CP_COMMIT();
        const uint32_t* Ab = &As[cur * 1280];
        const uint32_t* Bb = &Bs[cur * 4224];
#pragma unroll
        for (int ks = 0; ks < 16; ks += 8) {
            uint32_t af[2][4];
#pragma unroll
            for (int mt = 0; mt < 2; mt++) {
                int rb = (wr * 32 + mt * 16 + g) * 20 + ks;
                af[mt][0] = Ab[rb + tig];       af[mt][1] = Ab[rb + 160 + tig];
                af[mt][2] = Ab[rb + tig + 4];   af[mt][3] = Ab[rb + 160 + tig + 4];
            }
#pragma unroll
            for (int nt = 0; nt < 8; nt++) {
                int cb = wc * 64 + nt * 8 + g;
                uint32_t b0 = Bb[(ks + tig) * 264 + cb];
                uint32_t b1 = Bb[(ks + tig + 4) * 264 + cb];
                mma_tf32(acc[0][nt], af[0], b0, b1);
                mma_tf32(acc[1][nt], af[1], b0, b1);
            }
        }
        cur = (cur + 1) & 3;
    }
    __syncthreads();

    // epilogue: bias + LN(256) + gelu ; store tf32-rounded
    float rsm[4] = {0, 0, 0, 0}, rsq[4] = {0, 0, 0, 0};
#pragma unroll
    for (int mt = 0; mt < 2; mt++)
#pragma unroll
        for (int nt = 0; nt < 8; nt++) {
            int c0 = wc * 64 + nt * 8 + 2 * tig;
            float v0 = acc[mt][nt][0] + sB[c0], v1 = acc[mt][nt][1] + sB[c0 + 1];
            float v2 = acc[mt][nt][2] + sB[c0], v3 = acc[mt][nt][3] + sB[c0 + 1];
            acc[mt][nt][0] = v0; acc[mt][nt][1] = v1; acc[mt][nt][2] = v2; acc[mt][nt][3] = v3;
            rsm[mt * 2 + 0] += v0 + v1; rsq[mt * 2 + 0] += v0 * v0 + v1 * v1;
            rsm[mt * 2 + 1] += v2 + v3; rsq[mt * 2 + 1] += v2 * v2 + v3 * v3;
        }
#pragma unroll
    for (int off = 1; off < 4; off <<= 1)
#pragma unroll
        for (int q = 0; q < 4; q++) {
            rsm[q] += __shfl_xor_sync(0xffffffffu, rsm[q], off);
            rsq[q] += __shfl_xor_sync(0xffffffffu, rsq[q], off);
        }
    if (tig == 0) {
#pragma unroll
        for (int q = 0; q < 4; q++) {
            int row = wr * 32 + (q >> 1) * 16 + (q & 1) * 8 + g;
            ps[row * 4 + wc] = rsm[q]; pq[row * 4 + wc] = rsq[q];
        }
    }
    __syncthreads();
    float mv[4], rv[4];
#pragma unroll
    for (int q = 0; q < 4; q++) {
        int row = wr * 32 + (q >> 1) * 16 + (q & 1) * 8 + g;
        float s  = ps[row * 4 + 0] + ps[row * 4 + 1] + ps[row * 4 + 2] + ps[row * 4 + 3];
        float s2 = pq[row * 4 + 0] + pq[row * 4 + 1] + pq[row * 4 + 2] + pq[row * 4 + 3];
        float m = s * (1.f / 256.f);
        float var = s2 * (1.f / 256.f) - m * m;
        mv[q] = m; rv[q] = rsqrtf(var + EPSV);
    }
#pragma unroll
    for (int mt = 0; mt < 2; mt++)
#pragma unroll
        for (int nt = 0; nt < 8; nt++) {
            int c0 = wc * 64 + nt * 8 + 2 * tig;
            int q0 = mt * 2;
            int row0 = t0 + wr * 32 + mt * 16 + g;
            float u0 = gelu_exact((acc[mt][nt][0] - mv[q0]) * rv[q0] * sG[c0] + sBt[c0]);
            float u1 = gelu_exact((acc[mt][nt][1] - mv[q0]) * rv[q0] * sG[c0 + 1] + sBt[c0 + 1]);
            *(float2*)&g_h[(size_t)row0 * 1024 + h * 256 + c0] =
                make_float2(f2tf_f(u0), f2tf_f(u1));
            float u2 = gelu_exact((acc[mt][nt][2] - mv[q0 + 1]) * rv[q0 + 1] * sG[c0] + sBt[c0]);
            float u3 = gelu_exact((acc[mt][nt][3] - mv[q0 + 1]) * rv[q0 + 1] * sG[c0 + 1] + sBt[c0 + 1]);
            *(float2*)&g_h[(size_t)(row0 + 8) * 1024 + h * 256 + c0] =
                make_float2(f2tf_f(u2), f2tf_f(u3));
        }
}

// ============================================================================
// K3: state GEMM (3-stage) ; [dyn|sa] GEMM (3-stage) ; softmax mix.
// (R10 verbatim — 256 threads, 2 CTAs/SM.)
// ============================================================================
#define K3_SMEM 88864
__global__ void __launch_bounds__(256, 2) k_head2_mma(
    const float* __restrict__ hb2, const float* __restrict__ attr)
{
    extern __shared__ __align__(16) char dsm[];
    uint32_t* As  = (uint32_t*)dsm;                // 15360 (3*64*20)
    uint32_t* Bs  = (uint32_t*)(dsm + 15360);      // 26112 (3*16*136)
    float*    Ss  = (float*)(dsm + 41472);         // 33792 (64*132)
    float*    At  = (float*)(dsm + 75264);         //  4096 (8*128)
    uint32_t* AtT = (uint32_t*)(dsm + 79360);      //  4096 (128*8)
    float*    Sa  = (float*)(dsm + 83456);         //  2048
    float*    Sw  = (float*)(dsm + 85504);         //  2048
    float*    s2p = (float*)(dsm + 87552);         //  1024
    float*    a2s = (float*)(dsm + 88576);         //    32
    float*    Sgt = (float*)(dsm + 88608);         //   256

    const int h = blockIdx.y;
    const int t0 = blockIdx.x * 64;
    const int tid = threadIdx.x, w = tid >> 5, l = tid & 31;
    const int wr = w >> 2, wc = w & 3, g = l >> 2, tig = l & 3;

    {
        float4 v = *(const float4*)(attr + (size_t)h * 1024 + tid * 4);
        *(float4*)&At[tid * 4] = v;
        int a0 = tid >> 5, d0 = (tid & 31) * 4;
        AtT[(d0 + 0) * 8 + a0] = f2tf(v.x);
        AtT[(d0 + 1) * 8 + a0] = f2tf(v.y);
        AtT[(d0 + 2) * 8 + a0] = f2tf(v.z);
        AtT[(d0 + 3) * 8 + a0] = f2tf(v.w);
    }

    float acc[2][4][4];
#pragma unroll
    for (int mt = 0; mt < 2; mt++)
#pragma unroll
        for (int nt = 0; nt < 4; nt++)
#pragma unroll
            for (int i = 0; i < 4; i++) acc[mt][nt][i] = 0.f;

    const int ar = tid >> 2, ac4 = (tid & 3) * 4;
    const float* Ap = g_h + (size_t)(t0 + ar) * 1024 + h * 256 + ac4;
    const float* Wp = g_hW2t + (size_t)h * 256 * 128;

    auto load_stage1 = [&](int s, int k0) {
        cp16(&As[s * 1280 + ar * 20 + ac4], Ap + k0);
#pragma unroll
        for (int i = 0; i < 2; i++) {
            int idx = tid + 256 * i;
            int kk = idx >> 5, c4 = (idx & 31) * 4;
            cp16(&Bs[s * 2176 + kk * 136 + c4], Wp + (size_t)(k0 + kk) * 128 + c4);
        }
    };

    load_stage1(0, 0);  CP_COMMIT();
    load_stage1(1, 16); CP_COMMIT();
    __syncthreads();
    if (tid < 8) {
        float q = 0.f;
#pragma unroll
        for (int k = 0; k < 128; k++) q += At[tid * 128 + k] * At[tid * 128 + k];
        a2s[tid] = q;
    }

    int cur = 0;
    for (int it = 0; it < 16; it++) {
        CP_WAIT_1();
        __syncthreads();
        if (it + 2 < 16) load_stage1((cur + 2 >= 3) ? cur - 1 : cur + 2, (it + 2) * 16);
        CP_COMMIT();
        const uint32_t* Ab = &As[cur * 1280];
        const uint32_t* Bb = &Bs[cur * 2176];
#pragma unroll
        for (int ks = 0; ks < 16; ks += 8) {
            uint32_t af[2][4];
#pragma unroll
            for (int mt = 0; mt < 2; mt++) {
                int rb = (wr * 32 + mt * 16 + g) * 20 + ks;
                af[mt][0] = Ab[rb + tig];       af[mt][1] = Ab[rb + 160 + tig];
                af[mt][2] = Ab[rb + tig + 4];   af[mt][3] = Ab[rb + 160 + tig + 4];
            }
#pragma unroll
            for (int nt = 0; nt < 4; nt++) {
                int cb = wc * 32 + nt * 8 + g;
                uint32_t b0 = Bb[(ks + tig) * 136 + cb];
                uint32_t b1 = Bb[(ks + tig + 4) * 136 + cb];
                mma_tf32(acc[0][nt], af[0], b0, b1);
                mma_tf32(acc[1][nt], af[1], b0, b1);
            }
        }
        cur = (cur + 1 == 3) ? 0 : cur + 1;
    }
    __syncthreads();

    const float* Dp = g_dynt + (size_t)h * 128 * 128;
    auto load_stage2 = [&](int s, int k0) {
#pragma unroll
        for (int i = 0; i < 2; i++) {
            int idx = tid + 256 * i;
            int kk = idx >> 5, c4 = (idx & 31) * 4;
            cp16(&Bs[s * 2176 + kk * 136 + c4], Dp + (size_t)(k0 + kk) * 128 + c4);
        }
    };
    load_stage2(0, 0);  CP_COMMIT();
    load_stage2(1, 16); CP_COMMIT();

    {
        float rq[4] = {0, 0, 0, 0};
#pragma unroll
        for (int mt = 0; mt < 2; mt++)
#pragma unroll
            for (int nt = 0; nt < 4; nt++) {
                int c0 = wc * 32 + nt * 8 + 2 * tig;
                int row = wr * 32 + mt * 16 + g;
                float b0v = hb2[h * 128 + c0], b1v = hb2[h * 128 + c0 + 1];
                float v0 = f2tf_f(acc[mt][nt][0] + b0v);
                float v1 = f2tf_f(acc[mt][nt][1] + b1v);
                float v2 = f2tf_f(acc[mt][nt][2] + b0v);
                float v3 = f2tf_f(acc[mt][nt][3] + b1v);
                Ss[row * 132 + c0]           = v0;
                Ss[row * 132 + c0 + 1]       = v1;
                Ss[(row + 8) * 132 + c0]     = v2;
                Ss[(row + 8) * 132 + c0 + 1] = v3;
                rq[mt * 2 + 0] += v0 * v0 + v1 * v1;
                rq[mt * 2 + 1] += v2 * v2 + v3 * v3;
            }
#pragma unroll
        for (int off = 1; off < 4; off <<= 1)
#pragma unroll
            for (int q = 0; q < 4; q++)
                rq[q] += __shfl_xor_sync(0xffffffffu, rq[q], off);
        if (tig == 0) {
#pragma unroll
            for (int q = 0; q < 4; q++) {
                int row = wr * 32 + (q >> 1) * 16 + (q & 1) * 8 + g;
                s2p[row * 4 + wc] = rq[q];
            }
        }
    }
    __syncthreads();

    float dcc[2][4][4];
    float scc[2][4];
#pragma unroll
    for (int mt = 0; mt < 2; mt++) {
#pragma unroll
        for (int nt = 0; nt < 4; nt++)
#pragma unroll
            for (int i = 0; i < 4; i++) dcc[mt][nt][i] = 0.f;
#pragma unroll
        for (int i = 0; i < 4; i++) scc[mt][i] = 0.f;
    }

    cur = 0;
    for (int it = 0; it < 8; it++) {
        CP_WAIT_1();
        __syncthreads();
        if (it + 2 < 8) load_stage2((cur + 2 >= 3) ? cur - 1 : cur + 2, (it + 2) * 16);
        CP_COMMIT();
        const uint32_t* Bb = &Bs[cur * 2176];
        const int kbase = it * 16;
#pragma unroll
        for (int ks = 0; ks < 16; ks += 8) {
            uint32_t af[2][4];
#pragma unroll
            for (int mt = 0; mt < 2; mt++) {
                int rb = (wr * 32 + mt * 16 + g) * 132 + kbase + ks;
                af[mt][0] = __float_as_uint(Ss[rb + tig]);
                af[mt][1] = __float_as_uint(Ss[rb + 8 * 132 + tig]);
                af[mt][2] = __float_as_uint(Ss[rb + tig + 4]);
                af[mt][3] = __float_as_uint(Ss[rb + 8 * 132 + tig + 4]);
            }
#pragma unroll
            for (int nt = 0; nt < 4; nt++) {
                int cb = wc * 32 + nt * 8 + g;
                uint32_t b0 = Bb[(ks + tig) * 136 + cb];
                uint32_t b1 = Bb[(ks + tig + 4) * 136 + cb];
                mma_tf32(dcc[0][nt], af[0], b0, b1);
                mma_tf32(dcc[1][nt], af[1], b0, b1);
            }
            uint32_t b0s = AtT[(kbase + ks + tig) * 8 + g];
            uint32_t b1s = AtT[(kbase + ks + tig + 4) * 8 + g];
            mma_tf32(scc[0], af[0], b0s, b1s);
            mma_tf32(scc[1], af[1], b0s, b1s);
        }
        cur = (cur + 1 == 3) ? 0 : cur + 1;
    }
    __syncthreads();

    if (wc == 0) {
#pragma unroll
        for (int mt = 0; mt < 2; mt++) {
            int row = wr * 32 + mt * 16 + g;
            Sa[row * 8 + 2 * tig]           = scc[mt][0];
            Sa[row * 8 + 2 * tig + 1]       = scc[mt][1];
            Sa[(row + 8) * 8 + 2 * tig]     = scc[mt][2];
            Sa[(row + 8) * 8 + 2 * tig + 1] = scc[mt][3];
        }
    }
    __syncthreads();

    const float invs = 0.08838834764831845f;  // 1/sqrt(128)
    if (tid < 64) {
        int row = tid;
        float s2 = s2p[row * 4 + 0] + s2p[row * 4 + 1] + s2p[row * 4 + 2] + s2p[row * 4 + 3];
        float lgt[8], mx = -1e30f;
#pragma unroll
        for (int a = 0; a < 8; a++) {
            float dd = sqrtf(fmaxf(s2 + a2s[a] - 2.0f * Sa[row * 8 + a], 0.0f));
            lgt[a] = -dd * invs;
            mx = fmaxf(mx, lgt[a]);
        }
        float e[8], se = 0.f;
#pragma unroll
        for (int a = 0; a < 8; a++) { e[a] = expf(lgt[a] - mx); se += e[a]; }
        float ise = 1.0f / se;
#pragma unroll
        for (int a = 0; a < 8; a++) Sw[row * 8 + a] = e[a] * ise;
        Sgt[row] = 0.1f * g_gate[(size_t)(t0 + row) * 4 + h];
    }
    __syncthreads();

#pragma unroll
    for (int mt = 0; mt < 2; mt++)
#pragma unroll
        for (int nt = 0; nt < 4; nt++) {
            int c0 = wc * 32 + nt * 8 + 2 * tig;
#pragma unroll
            for (int half = 0; half < 2; half++) {
                int row = wr * 32 + mt * 16 + g + 8 * half;
                float gt = Sgt[row];
                float sv0 = Ss[row * 132 + c0];
                float sv1 = Ss[row * 132 + c0 + 1];
                float ai0 = 0.f, ai1 = 0.f;
#pragma unroll
                for (int a = 0; a < 8; a++) {
                    float wgt = Sw[row * 8 + a];
                    ai0 += wgt * At[a * 128 + c0];
                    ai1 += wgt * At[a * 128 + c0 + 1];
                }
                float dv0 = dcc[mt][nt][2 * half + 0];
                float dv1 = dcc[mt][nt][2 * half + 1];
                float o0 = f2tf_f(sv0 + gt * (ai0 - sv0 + tanhf(dv0)));
                float o1 = f2tf_f(sv1 + gt * (ai1 - sv1 + tanhf(dv1)));
                *(float2*)&g_comb[(size_t)(t0 + row) * 512 + h * 128 + c0] =
                    make_float2(o0, o1);
            }
        }
}

// ============================================================================
// K4: o1 = gelu(LN(comb @ oW1 + ob1)).  BM=64,BN=512, block 512, 4-stage ring.
// (R10 verbatim.)
// ============================================================================
#define K4_SMEM 163840
__global__ void __launch_bounds__(512) k_out1_mma(
    const float* __restrict__ ob1,
    const float* __restrict__ olg, const float* __restrict__ olb)
{
    extern __shared__ __align__(16) char dsm[];
    uint32_t* As = (uint32_t*)dsm;                 // 20480 (4*64*20)
    uint32_t* Bs = (uint32_t*)(dsm + 20480);       // 133120 (4*16*520)
    float* sB  = (float*)(dsm + 153600);
    float* sG  = (float*)(dsm + 155648);
    float* sBt = (float*)(dsm + 157696);
    float* ps  = (float*)(dsm + 159744);           // 64*8
    float* pq  = (float*)(dsm + 161792);

    const int t0 = blockIdx.x * 64;
    const int tid = threadIdx.x, w = tid >> 5, l = tid & 31;
    const int wr = w >> 3, wc = w & 7, g = l >> 2, tig = l & 3;

    sB[tid] = ob1[tid]; sG[tid] = olg[tid]; sBt[tid] = olb[tid];

    float acc[2][8][4];
#pragma unroll
    for (int mt = 0; mt < 2; mt++)
#pragma unroll
        for (int nt = 0; nt < 8; nt++)
#pragma unroll
            for (int i = 0; i < 4; i++) acc[mt][nt][i] = 0.f;

    const int ar = tid >> 2, ac4 = (tid & 3) * 4;
    const float* Ap = g_comb + (size_t)(t0 + (ar & 63)) * 512 + ac4;

    auto load_stage = [&](int s, int k0) {
        if (tid < 256) cp16(&As[s * 1280 + ar * 20 + ac4], Ap + k0);
#pragma unroll
        for (int i = 0; i < 4; i++) {
            int idx = tid + 512 * i;
            int kk = idx >> 7, c4 = (idx & 127) * 4;
            cp16(&Bs[s * 8320 + kk * 520 + c4], g_oW1t + (size_t)(k0 + kk) * 512 + c4);
        }
    };

    load_stage(0, 0);  CP_COMMIT();
    load_stage(1, 16); CP_COMMIT();
    load_stage(2, 32); CP_COMMIT();
    int cur = 0;
    for (int it = 0; it < 32; it++) {
        CP_WAIT_2();
        __syncthreads();
        if (it + 3 < 32) load_stage((cur + 3) & 3, (it + 3) * 16);
        CP_COMMIT();
        const uint32_t* Ab = &As[cur * 1280];
        const uint32_t* Bb = &Bs[cur * 8320];
#pragma unroll
        for (int ks = 0; ks < 16; ks += 8) {
            uint32_t af[2][4];
#pragma unroll
            for (int mt = 0; mt < 2; mt++) {
                int rb = (wr * 32 + mt * 16 + g) * 20 + ks;
                af[mt][0] = Ab[rb + tig];       af[mt][1] = Ab[rb + 160 + tig];
                af[mt][2] = Ab[rb + tig + 4];   af[mt][3] = Ab[rb + 160 + tig + 4];
            }
#pragma unroll
            for (int nt = 0; nt < 8; nt++) {
                int cb = wc * 64 + nt * 8 + g;
                uint32_t b0 = Bb[(ks + tig) * 520 + cb];
                uint32_t b1 = Bb[(ks + tig + 4) * 520 + cb];
                mma_tf32(acc[0][nt], af[0], b0, b1);
                mma_tf32(acc[1][nt], af[1], b0, b1);
            }
        }
        cur = (cur + 1) & 3;
    }
    __syncthreads();

    float rsm[4] = {0, 0, 0, 0}, rsq[4] = {0, 0, 0, 0};
#pragma unroll
    for (int mt = 0; mt < 2; mt++)
#pragma unroll
        for (int nt = 0; nt < 8; nt++) {
            int c0 = wc * 64 + nt * 8 + 2 * tig;
            float v0 = acc[mt][nt][0] + sB[c0], v1 = acc[mt][nt][1] + sB[c0 + 1];
            float v2 = acc[mt][nt][2] + sB[c0], v3 = acc[mt][nt][3] + sB[c0 + 1];
            acc[mt][nt][0] = v0; acc[mt][nt][1] = v1; acc[mt][nt][2] = v2; acc[mt][nt][3] = v3;
            rsm[mt * 2 + 0] += v0 + v1; rsq[mt * 2 + 0] += v0 * v0 + v1 * v1;
            rsm[mt * 2 + 1] += v2 + v3; rsq[mt * 2 + 1] += v2 * v2 + v3 * v3;
        }
#pragma unroll
    for (int off = 1; off < 4; off <<= 1)
#pragma unroll
        for (int q = 0; q < 4; q++) {
            rsm[q] += __shfl_xor_sync(0xffffffffu, rsm[q], off);
            rsq[q] += __shfl_xor_sync(0xffffffffu, rsq[q], off);
        }
    if (tig == 0) {
#pragma unroll
        for (int q = 0; q < 4; q++) {
            int row = wr * 32 + (q >> 1) * 16 + (q & 1) * 8 + g;
            ps[row * 8 + wc] = rsm[q]; pq[row * 8 + wc] = rsq[q];
        }
    }
    __syncthreads();
    float mv[4], rv[4];
#pragma unroll
    for (int q = 0; q < 4; q++) {
        int row = wr * 32 + (q >> 1) * 16 + (q & 1) * 8 + g;
        float s = 0.f, s2 = 0.f;
#pragma unroll
        for (int j = 0; j < 8; j++) { s += ps[row * 8 + j]; s2 += pq[row * 8 + j]; }
        float m = s * (1.f / 512.f);
        float var = s2 * (1.f / 512.f) - m * m;
        mv[q] = m; rv[q] = rsqrtf(var + EPSV);
    }
#pragma unroll
    for (int mt = 0; mt < 2; mt++)
#pragma unroll
        for (int nt = 0; nt < 8; nt++) {
            int c0 = wc * 64 + nt * 8 + 2 * tig;
            int q0 = mt * 2;
            int row0 = t0 + wr * 32 + mt * 16 + g;
            float u0 = gelu_exact((acc[mt][nt][0] - mv[q0]) * rv[q0] * sG[c0] + sBt[c0]);
            float u1 = gelu_exact((acc[mt][nt][1] - mv[q0]) * rv[q0] * sG[c0 + 1] + sBt[c0 + 1]);
            *(float2*)&g_oact[(size_t)row0 * 512 + c0] = make_float2(f2tf_f(u0), f2tf_f(u1));
            float u2 = gelu_exact((acc[mt][nt][2] - mv[q0 + 1]) * rv[q0 + 1] * sG[c0] + sBt[c0]);
            float u3 = gelu_exact((acc[mt][nt][3] - mv[q0 + 1]) * rv[q0 + 1] * sG[c0 + 1] + sBt[c0 + 1]);
            *(float2*)&g_oact[(size_t)(row0 + 8) * 512 + c0] = make_float2(f2tf_f(u2), f2tf_f(u3));
        }
}

// ============================================================================
// K5 (R13): out = xn + oact @ oW2 + ob2.  K2 geometry: BM=64, BN=256,
// block 256 (warps 2x4), grid (T/64, 2), 4-stage ring -> 2 CTAs/SM.
// smem: As 20480 | Bs 67584 | sB 1024 = 89088 B
// ============================================================================
#define K5_SMEM 89088
__global__ void __launch_bounds__(256) k_out2_mma(
    const float* __restrict__ ob2, float* __restrict__ out)
{
    extern __shared__ __align__(16) char dsm[];
    uint32_t* As = (uint32_t*)dsm;                 // 20480 (4*64*20)
    uint32_t* Bs = (uint32_t*)(dsm + 20480);       // 67584 (4*16*264)
    float* sB = (float*)(dsm + 88064);

    const int t0 = blockIdx.x * 64;
    const int c0base = blockIdx.y * 256;
    const int tid = threadIdx.x, w = tid >> 5, l = tid & 31;
    const int wr = w >> 2, wc = w & 3, g = l >> 2, tig = l & 3;

    sB[tid] = ob2[c0base + tid];

    float acc[2][8][4];
#pragma unroll
    for (int mt = 0; mt < 2; mt++)
#pragma unroll
        for (int nt = 0; nt < 8; nt++)
#pragma unroll
            for (int i = 0; i < 4; i++) acc[mt][nt][i] = 0.f;

    const int ar = tid >> 2, ac4 = (tid & 3) * 4;
    const float* Ap = g_oact + (size_t)(t0 + ar) * 512 + ac4;

    auto load_stage = [&](int s, int k0) {
        cp16(&As[s * 1280 + ar * 20 + ac4], Ap + k0);
#pragma unroll
        for (int i = 0; i < 4; i++) {
            int idx = tid + 256 * i;
            int kk = idx >> 6, c4 = (idx & 63) * 4;
            cp16(&Bs[s * 4224 + kk * 264 + c4],
                 g_oW2t + (size_t)(k0 + kk) * 512 + c0base + c4);
        }
    };

    load_stage(0, 0);  CP_COMMIT();
    load_stage(1, 16); CP_COMMIT();
    load_stage(2, 32); CP_COMMIT();
    int cur = 0;
    for (int it = 0; it < 32; it++) {
        CP_WAIT_2();
        __syncthreads();
        if (it + 3 < 32) load_stage((cur + 3) & 3, (it + 3) * 16);
        CP_COMMIT();
        const uint32_t* Ab = &As[cur * 1280];
        const uint32_t* Bb = &Bs[cur * 4224];
#pragma unroll
        for (int ks = 0; ks < 16; ks += 8) {
            uint32_t af[2][4];
#pragma unroll
            for (int mt = 0; mt < 2; mt++) {
                int rb = (wr * 32 + mt * 16 + g) * 20 + ks;
                af[mt][0] = Ab[rb + tig];       af[mt][1] = Ab[rb + 160 + tig];
                af[mt][2] = Ab[rb + tig + 4];   af[mt][3] = Ab[rb + 160 + tig + 4];
            }
#pragma unroll
            for (int nt = 0; nt < 8; nt++) {
                int cb = wc * 64 + nt * 8 + g;
                uint32_t b0 = Bb[(ks + tig) * 264 + cb];
                uint32_t b1 = Bb[(ks + tig + 4) * 264 + cb];
                mma_tf32(acc[0][nt], af[0], b0, b1);
                mma_tf32(acc[1][nt], af[1], b0, b1);
            }
        }
        cur = (cur + 1) & 3;
    }

#pragma unroll
    for (int mt = 0; mt < 2; mt++)
#pragma unroll
        for (int nt = 0; nt < 8; nt++) {
            int c0 = wc * 64 + nt * 8 + 2 * tig;
            int col = c0base + c0;
            int row0 = t0 + wr * 32 + mt * 16 + g;
            size_t o0 = (size_t)row0 * 512 + col;
            size_t o1 = (size_t)(row0 + 8) * 512 + col;
            float2 x0 = *(const float2*)&g_xn[o0];
            float2 x1 = *(const float2*)&g_xn[o1];
            *(float2*)&out[o0] = make_float2(acc[mt][nt][0] + sB[c0] + x0.x,
                                             acc[mt][nt][1] + sB[c0 + 1] + x0.y);
            *(float2*)&out[o1] = make_float2(acc[mt][nt][2] + sB[c0] + x1.x,
                                             acc[mt][nt][3] + sB[c0 + 1] + x1.y);
        }
}

// ============================================================================
extern "C" void kernel_launch(void* const* d_in, const int* in_sizes, int n_in,
                              void* d_out, int out_size)
{
    (void)in_sizes; (void)n_in; (void)out_size;
    const float* x    = (const float*)d_in[0];
    const float* ng   = (const float*)d_in[1];
    const float* nb   = (const float*)d_in[2];
    const float* hW1  = (const float*)d_in[3];
    const float* hb1  = (const float*)d_in[4];
    const float* hlg  = (const float*)d_in[5];
    const float* hlb  = (const float*)d_in[6];
    const float* hW2  = (const float*)d_in[7];
    const float* hb2  = (const float*)d_in[8];
    const float* attr = (const float*)d_in[9];
    const float* dynm = (const float*)d_in[10];
    const float* gW   = (const float*)d_in[11];
    const float* gb   = (const float*)d_in[12];
    const float* oW1  = (const float*)d_in[13];
    const float* ob1  = (const float*)d_in[14];
    const float* olg  = (const float*)d_in[15];
    const float* olb  = (const float*)d_in[16];
    const float* oW2  = (const float*)d_in[17];
    const float* ob2  = (const float*)d_in[18];
    float* out = (float*)d_out;

    cudaFuncSetAttribute(k_head1_mma, cudaFuncAttributeMaxDynamicSharedMemorySize, K2_SMEM);
    cudaFuncSetAttribute(k_head2_mma, cudaFuncAttributeMaxDynamicSharedMemorySize, K3_SMEM);
    cudaFuncSetAttribute(k_out1_mma,  cudaFuncAttributeMaxDynamicSharedMemorySize, K4_SMEM);
    cudaFuncSetAttribute(k_out2_mma,  cudaFuncAttributeMaxDynamicSharedMemorySize, K5_SMEM);

    k_prep<<<4864, 256>>>(hW1, hW2, dynm, oW1, oW2);
    k_ln_gate<<<8192, 256>>>(x, ng, nb, gW, gb);

    dim3 gh(T_TOK / 64, 4);
    k_head1_mma<<<gh, 256, K2_SMEM>>>(hb1, hlg, hlb);
    k_head2_mma<<<gh, 256, K3_SMEM>>>(hb2, attr);

    k_out1_mma<<<T_TOK / 64, 512, K4_SMEM>>>(ob1, olg, olb);
    dim3 g5(T_TOK / 64, 2);
    k_out2_mma<<<g5, 256, K5_SMEM>>>(ob2, out);
}

// round 14
// speedup vs baseline: 1.5460x; 1.0402x over previous
#include <cuda_runtime.h>
#include <math.h>
#include <stdint.h>

// ----------------------------------------------------------------------------
// NoiseRobustAttractorLayer — TF32 mma.sync. R14 = R13 (best: 1374us) with
// XOR-swizzled B tiles in all GEMMs. Old B strides (264/136/520 ≡ 8 mod 32)
// caused 8-way bank conflicts on EVERY B-fragment LDS. New layout: stride
// 256/128/512 + column swizzle c ^ (8*(k&3)) -> conflict-free (1 phase).
// Bit-identical math.
// ----------------------------------------------------------------------------

#define T_TOK 65536
#define EPSV  1e-5f

__device__ float g_xn  [(size_t)T_TOK * 512];   // fp32 (residual)
__device__ float g_xnt [(size_t)T_TOK * 512];   // tf32-rounded (GEMM A)
__device__ float g_gate[(size_t)T_TOK * 4];
__device__ float g_h   [(size_t)T_TOK * 1024];  // tf32-rounded
__device__ float g_comb[(size_t)T_TOK * 512];   // tf32-rounded
__device__ float g_oact[(size_t)T_TOK * 512];   // tf32-rounded

__device__ float g_hW1t[4 * 512 * 256];
__device__ float g_hW2t[4 * 256 * 128];
__device__ float g_dynt[4 * 128 * 128];
__device__ float g_oW1t[512 * 512];
__device__ float g_oW2t[512 * 512];

__device__ __forceinline__ float warp_sum(float v) {
#pragma unroll
    for (int o = 16; o > 0; o >>= 1) v += __shfl_xor_sync(0xffffffffu, v, o);
    return v;
}
__device__ __forceinline__ float gelu_exact(float x) {
    return 0.5f * x * (1.0f + erff(x * 0.70710678118654752f));
}
__device__ __forceinline__ uint32_t f2tf(float x) {
    uint32_t r; asm("cvt.rna.tf32.f32 %0, %1;" : "=r"(r) : "f"(x)); return r;
}
__device__ __forceinline__ float f2tf_f(float x) {
    return __uint_as_float(f2tf(x));
}
__device__ __forceinline__ void mma_tf32(float c[4], const uint32_t a[4],
                                         uint32_t b0, uint32_t b1) {
    asm volatile(
        "mma.sync.aligned.m16n8k8.row.col.f32.tf32.tf32.f32 "
        "{%0,%1,%2,%3},{%4,%5,%6,%7},{%8,%9},{%0,%1,%2,%3};"
        : "+f"(c[0]), "+f"(c[1]), "+f"(c[2]), "+f"(c[3])
        : "r"(a[0]), "r"(a[1]), "r"(a[2]), "r"(a[3]), "r"(b0), "r"(b1));
}
__device__ __forceinline__ void cp16(void* s, const void* g) {
    uint32_t sa = (uint32_t)__cvta_generic_to_shared(s);
    asm volatile("cp.async.cg.shared.global [%0], [%1], 16;" :: "r"(sa), "l"(g));
}
#define CP_COMMIT()  asm volatile("cp.async.commit_group;")
#define CP_WAIT_1()  asm volatile("cp.async.wait_group 1;" ::: "memory")
#define CP_WAIT_2()  asm volatile("cp.async.wait_group 2;" ::: "memory")

// ============================================================================
// K0: weight pre-conversion fp32 -> tf32
// ============================================================================
__global__ void __launch_bounds__(256) k_prep(
    const float* __restrict__ hW1, const float* __restrict__ hW2,
    const float* __restrict__ dynm, const float* __restrict__ oW1,
    const float* __restrict__ oW2)
{
    int i = blockIdx.x * 256 + threadIdx.x;
    if (i < 524288)       g_hW1t[i]           = f2tf_f(hW1[i]);
    else if (i < 655360)  g_hW2t[i - 524288]  = f2tf_f(hW2[i - 524288]);
    else if (i < 720896)  g_dynt[i - 655360]  = f2tf_f(dynm[i - 655360]);
    else if (i < 983040)  g_oW1t[i - 720896]  = f2tf_f(oW1[i - 720896]);
    else if (i < 1245184) g_oW2t[i - 983040]  = f2tf_f(oW2[i - 983040]);
}

// ============================================================================
// K1: warp-per-token LN + gate (verbatim).
// ============================================================================
__global__ void __launch_bounds__(256) k_ln_gate(
    const float* __restrict__ x, const float* __restrict__ ng,
    const float* __restrict__ nb, const float* __restrict__ gW,
    const float* __restrict__ gb)
{
    __shared__ float sgW[2048];
    __shared__ float sng[512], snb[512];
    const int tid = threadIdx.x;
    for (int i = tid; i < 2048; i += 256) sgW[i] = gW[i];
    for (int i = tid; i < 512; i += 256) { sng[i] = ng[i]; snb[i] = nb[i]; }
    __syncthreads();

    const int wid = tid >> 5, l = tid & 31;
    const float gb0 = gb[0], gb1 = gb[1], gb2 = gb[2], gb3 = gb[3];
    const float4* sgW4 = (const float4*)sgW;
    const float4* sng4 = (const float4*)sng;
    const float4* snb4 = (const float4*)snb;

    for (int t = blockIdx.x * 8 + wid; t < T_TOK; t += gridDim.x * 8) {
        const float4* xr = (const float4*)(x + (size_t)t * 512);
        float4 v[4];
#pragma unroll
        for (int j = 0; j < 4; j++) v[j] = xr[l + 32 * j];
        float s = 0.f;
#pragma unroll
        for (int j = 0; j < 4; j++) s += v[j].x + v[j].y + v[j].z + v[j].w;
        s = warp_sum(s);
        float m = s * (1.0f / 512.0f);
        float q = 0.f;
#pragma unroll
        for (int j = 0; j < 4; j++) {
            float dx = v[j].x - m, dy = v[j].y - m, dz = v[j].z - m, dw = v[j].w - m;
            q += dx * dx + dy * dy + dz * dz + dw * dw;
        }
        q = warp_sum(q);
        float rs = rsqrtf(q * (1.0f / 512.0f) + EPSV);

        float4 xnv[4];
        float4* xo  = (float4*)(g_xn  + (size_t)t * 512);
        float4* xot = (float4*)(g_xnt + (size_t)t * 512);
#pragma unroll
        for (int j = 0; j < 4; j++) {
            float4 gv = sng4[l + 32 * j];
            float4 bv = snb4[l + 32 * j];
            xnv[j].x = (v[j].x - m) * rs * gv.x + bv.x;
            xnv[j].y = (v[j].y - m) * rs * gv.y + bv.y;
            xnv[j].z = (v[j].z - m) * rs * gv.z + bv.z;
            xnv[j].w = (v[j].w - m) * rs * gv.w + bv.w;
            xo[l + 32 * j] = xnv[j];
            float4 tv;
            tv.x = f2tf_f(xnv[j].x); tv.y = f2tf_f(xnv[j].y);
            tv.z = f2tf_f(xnv[j].z); tv.w = f2tf_f(xnv[j].w);
            xot[l + 32 * j] = tv;
        }
        float p[4] = {0.f, 0.f, 0.f, 0.f};
#pragma unroll
        for (int h = 0; h < 4; h++) {
#pragma unroll
            for (int j = 0; j < 4; j++) {
                float4 wv = sgW4[h * 128 + l + 32 * j];
                p[h] += xnv[j].x * wv.x + xnv[j].y * wv.y
                      + xnv[j].z * wv.z + xnv[j].w * wv.w;
            }
            p[h] = warp_sum(p[h]);
        }
        if (l == 0) {
            g_gate[(size_t)t * 4 + 0] = 1.0f / (1.0f + expf(-(p[0] + gb0)));
            g_gate[(size_t)t * 4 + 1] = 1.0f / (1.0f + expf(-(p[1] + gb1)));
            g_gate[(size_t)t * 4 + 2] = 1.0f / (1.0f + expf(-(p[2] + gb2)));
            g_gate[(size_t)t * 4 + 3] = 1.0f / (1.0f + expf(-(p[3] + gb3)));
        }
    }
}

// ============================================================================
// K2: h = gelu(LN(xn @ hW1[h] + hb1)).  BM=64,BN=256, block 256, 4-stage,
// swizzled B (stride 256, c ^ 8*(k&3)).
// smem: As 20480 | Bs 65536 | sB sG sBt 3072 | ps pq 2048 = 91136 (2 CTAs)
// ============================================================================
#define K2_SMEM 91136
__global__ void __launch_bounds__(256) k_head1_mma(
    const float* __restrict__ hb1,
    const float* __restrict__ hlg, const float* __restrict__ hlb)
{
    extern __shared__ __align__(16) char dsm[];
    uint32_t* As = (uint32_t*)dsm;                 // 20480 (4*64*20)
    uint32_t* Bs = (uint32_t*)(dsm + 20480);       // 65536 (4*16*256)
    float* sB  = (float*)(dsm + 86016);
    float* sG  = (float*)(dsm + 87040);
    float* sBt = (float*)(dsm + 88064);
    float* ps  = (float*)(dsm + 89088);            // 64*4
    float* pq  = (float*)(dsm + 90112);            // 64*4

    const int h = blockIdx.y;
    const int t0 = blockIdx.x * 64;
    const int tid = threadIdx.x, w = tid >> 5, l = tid & 31;
    const int wr = w >> 2, wc = w & 3, g = l >> 2, tig = l & 3;
    const int swz = tig << 3;

    sB[tid] = hb1[h * 256 + tid]; sG[tid] = hlg[h * 256 + tid]; sBt[tid] = hlb[h * 256 + tid];

    float acc[2][8][4];
#pragma unroll
    for (int mt = 0; mt < 2; mt++)
#pragma unroll
        for (int nt = 0; nt < 8; nt++)
#pragma unroll
            for (int i = 0; i < 4; i++) acc[mt][nt][i] = 0.f;

    const float* Wp = g_hW1t + (size_t)h * 512 * 256;
    const int ar = tid >> 2, ac4 = (tid & 3) * 4;
    const float* Ap = g_xnt + (size_t)(t0 + ar) * 512 + ac4;

    auto load_stage = [&](int s, int k0) {
        cp16(&As[s * 1280 + ar * 20 + ac4], Ap + k0);
#pragma unroll
        for (int i = 0; i < 4; i++) {
            int idx = tid + 256 * i;
            int kk = idx >> 6, c4 = (idx & 63) * 4;
            cp16(&Bs[s * 4096 + kk * 256 + (c4 ^ ((kk & 3) << 3))],
                 Wp + (size_t)(k0 + kk) * 256 + c4);
        }
    };

    load_stage(0, 0);  CP_COMMIT();
    load_stage(1, 16); CP_COMMIT();
    load_stage(2, 32); CP_COMMIT();
    int cur = 0;
    for (int it = 0; it < 32; it++) {
        CP_WAIT_2();
        __syncthreads();
        if (it + 3 < 32) load_stage((cur + 3) & 3, (it + 3) * 16);
        CP_COMMIT();
        const uint32_t* Ab = &As[cur * 1280];
        const uint32_t* Bb = &Bs[cur * 4096];
#pragma unroll
        for (int ks = 0; ks < 16; ks += 8) {
            uint32_t af[2][4];
#pragma unroll
            for (int mt = 0; mt < 2; mt++) {
                int rb = (wr * 32 + mt * 16 + g) * 20 + ks;
                af[mt][0] = Ab[rb + tig];       af[mt][1] = Ab[rb + 160 + tig];
                af[mt][2] = Ab[rb + tig + 4];   af[mt][3] = Ab[rb + 160 + tig + 4];
            }
#pragma unroll
            for (int nt = 0; nt < 8; nt++) {
                int sc = (wc * 64 + nt * 8 + g) ^ swz;
                uint32_t b0 = Bb[(ks + tig) * 256 + sc];
                uint32_t b1 = Bb[(ks + tig + 4) * 256 + sc];
                mma_tf32(acc[0][nt], af[0], b0, b1);
                mma_tf32(acc[1][nt], af[1], b0, b1);
            }
        }
        cur = (cur + 1) & 3;
    }
    __syncthreads();

    // epilogue: bias + LN(256) + gelu ; store tf32-rounded
    float rsm[4] = {0, 0, 0, 0}, rsq[4] = {0, 0, 0, 0};
#pragma unroll
    for (int mt = 0; mt < 2; mt++)
#pragma unroll
        for (int nt = 0; nt < 8; nt++) {
            int c0 = wc * 64 + nt * 8 + 2 * tig;
            float v0 = acc[mt][nt][0] + sB[c0], v1 = acc[mt][nt][1] + sB[c0 + 1];
            float v2 = acc[mt][nt][2] + sB[c0], v3 = acc[mt][nt][3] + sB[c0 + 1];
            acc[mt][nt][0] = v0; acc[mt][nt][1] = v1; acc[mt][nt][2] = v2; acc[mt][nt][3] = v3;
            rsm[mt * 2 + 0] += v0 + v1; rsq[mt * 2 + 0] += v0 * v0 + v1 * v1;
            rsm[mt * 2 + 1] += v2 + v3; rsq[mt * 2 + 1] += v2 * v2 + v3 * v3;
        }
#pragma unroll
    for (int off = 1; off < 4; off <<= 1)
#pragma unroll
        for (int q = 0; q < 4; q++) {
            rsm[q] += __shfl_xor_sync(0xffffffffu, rsm[q], off);
            rsq[q] += __shfl_xor_sync(0xffffffffu, rsq[q], off);
        }
    if (tig == 0) {
#pragma unroll
        for (int q = 0; q < 4; q++) {
            int row = wr * 32 + (q >> 1) * 16 + (q & 1) * 8 + g;
            ps[row * 4 + wc] = rsm[q]; pq[row * 4 + wc] = rsq[q];
        }
    }
    __syncthreads();
    float mv[4], rv[4];
#pragma unroll
    for (int q = 0; q < 4; q++) {
        int row = wr * 32 + (q >> 1) * 16 + (q & 1) * 8 + g;
        float s  = ps[row * 4 + 0] + ps[row * 4 + 1] + ps[row * 4 + 2] + ps[row * 4 + 3];
        float s2 = pq[row * 4 + 0] + pq[row * 4 + 1] + pq[row * 4 + 2] + pq[row * 4 + 3];
        float m = s * (1.f / 256.f);
        float var = s2 * (1.f / 256.f) - m * m;
        mv[q] = m; rv[q] = rsqrtf(var + EPSV);
    }
#pragma unroll
    for (int mt = 0; mt < 2; mt++)
#pragma unroll
        for (int nt = 0; nt < 8; nt++) {
            int c0 = wc * 64 + nt * 8 + 2 * tig;
            int q0 = mt * 2;
            int row0 = t0 + wr * 32 + mt * 16 + g;
            float u0 = gelu_exact((acc[mt][nt][0] - mv[q0]) * rv[q0] * sG[c0] + sBt[c0]);
            float u1 = gelu_exact((acc[mt][nt][1] - mv[q0]) * rv[q0] * sG[c0 + 1] + sBt[c0 + 1]);
            *(float2*)&g_h[(size_t)row0 * 1024 + h * 256 + c0] =
                make_float2(f2tf_f(u0), f2tf_f(u1));
            float u2 = gelu_exact((acc[mt][nt][2] - mv[q0 + 1]) * rv[q0 + 1] * sG[c0] + sBt[c0]);
            float u3 = gelu_exact((acc[mt][nt][3] - mv[q0 + 1]) * rv[q0 + 1] * sG[c0 + 1] + sBt[c0 + 1]);
            *(float2*)&g_h[(size_t)(row0 + 8) * 1024 + h * 256 + c0] =
                make_float2(f2tf_f(u2), f2tf_f(u3));
        }
}

// ============================================================================
// K3: state GEMM ; [dyn|sa] GEMM ; softmax mix.  Swizzled B (stride 128).
// smem: As 15360 | Bs 24576 | Ss 33792 | At 4096 | AtT 4096 | Sa 2048 |
//       Sw 2048 | s2p 1024 | a2s 32 | Sgt 256 = 87328 (2 CTAs)
// ============================================================================
#define K3_SMEM 87328
__global__ void __launch_bounds__(256, 2) k_head2_mma(
    const float* __restrict__ hb2, const float* __restrict__ attr)
{
    extern __shared__ __align__(16) char dsm[];
    uint32_t* As  = (uint32_t*)dsm;                // 15360 (3*64*20)
    uint32_t* Bs  = (uint32_t*)(dsm + 15360);      // 24576 (3*16*128)
    float*    Ss  = (float*)(dsm + 39936);         // 33792 (64*132)
    float*    At  = (float*)(dsm + 73728);         //  4096 (8*128)
    uint32_t* AtT = (uint32_t*)(dsm + 77824);      //  4096 (128*8)
    float*    Sa  = (float*)(dsm + 81920);         //  2048
    float*    Sw  = (float*)(dsm + 83968);         //  2048
    float*    s2p = (float*)(dsm + 86016);         //  1024
    float*    a2s = (float*)(dsm + 87040);         //    32
    float*    Sgt = (float*)(dsm + 87072);         //   256

    const int h = blockIdx.y;
    const int t0 = blockIdx.x * 64;
    const int tid = threadIdx.x, w = tid >> 5, l = tid & 31;
    const int wr = w >> 2, wc = w & 3, g = l >> 2, tig = l & 3;
    const int swz = tig << 3;

    {
        float4 v = *(const float4*)(attr + (size_t)h * 1024 + tid * 4);
        *(float4*)&At[tid * 4] = v;
        int a0 = tid >> 5, d0 = (tid & 31) * 4;
        AtT[(d0 + 0) * 8 + a0] = f2tf(v.x);
        AtT[(d0 + 1) * 8 + a0] = f2tf(v.y);
        AtT[(d0 + 2) * 8 + a0] = f2tf(v.z);
        AtT[(d0 + 3) * 8 + a0] = f2tf(v.w);
    }

    float acc[2][4][4];
#pragma unroll
    for (int mt = 0; mt < 2; mt++)
#pragma unroll
        for (int nt = 0; nt < 4; nt++)
#pragma unroll
            for (int i = 0; i < 4; i++) acc[mt][nt][i] = 0.f;

    const int ar = tid >> 2, ac4 = (tid & 3) * 4;
    const float* Ap = g_h + (size_t)(t0 + ar) * 1024 + h * 256 + ac4;
    const float* Wp = g_hW2t + (size_t)h * 256 * 128;

    auto load_stage1 = [&](int s, int k0) {
        cp16(&As[s * 1280 + ar * 20 + ac4], Ap + k0);
#pragma unroll
        for (int i = 0; i < 2; i++) {
            int idx = tid + 256 * i;
            int kk = idx >> 5, c4 = (idx & 31) * 4;
            cp16(&Bs[s * 2048 + kk * 128 + (c4 ^ ((kk & 3) << 3))],
                 Wp + (size_t)(k0 + kk) * 128 + c4);
        }
    };

    load_stage1(0, 0);  CP_COMMIT();
    load_stage1(1, 16); CP_COMMIT();
    __syncthreads();
    if (tid < 8) {
        float q = 0.f;
#pragma unroll
        for (int k = 0; k < 128; k++) q += At[tid * 128 + k] * At[tid * 128 + k];
        a2s[tid] = q;
    }

    int cur = 0;
    for (int it = 0; it < 16; it++) {
        CP_WAIT_1();
        __syncthreads();
        if (it + 2 < 16) load_stage1((cur + 2 >= 3) ? cur - 1 : cur + 2, (it + 2) * 16);
        CP_COMMIT();
        const uint32_t* Ab = &As[cur * 1280];
        const uint32_t* Bb = &Bs[cur * 2048];
#pragma unroll
        for (int ks = 0; ks < 16; ks += 8) {
            uint32_t af[2][4];
#pragma unroll
            for (int mt = 0; mt < 2; mt++) {
                int rb = (wr * 32 + mt * 16 + g) * 20 + ks;
                af[mt][0] = Ab[rb + tig];       af[mt][1] = Ab[rb + 160 + tig];
                af[mt][2] = Ab[rb + tig + 4];   af[mt][3] = Ab[rb + 160 + tig + 4];
            }
#pragma unroll
            for (int nt = 0; nt < 4; nt++) {
                int sc = (wc * 32 + nt * 8 + g) ^ swz;
                uint32_t b0 = Bb[(ks + tig) * 128 + sc];
                uint32_t b1 = Bb[(ks + tig + 4) * 128 + sc];
                mma_tf32(acc[0][nt], af[0], b0, b1);
                mma_tf32(acc[1][nt], af[1], b0, b1);
            }
        }
        cur = (cur + 1 == 3) ? 0 : cur + 1;
    }
    __syncthreads();

    const float* Dp = g_dynt + (size_t)h * 128 * 128;
    auto load_stage2 = [&](int s, int k0) {
#pragma unroll
        for (int i = 0; i < 2; i++) {
            int idx = tid + 256 * i;
            int kk = idx >> 5, c4 = (idx & 31) * 4;
            cp16(&Bs[s * 2048 + kk * 128 + (c4 ^ ((kk & 3) << 3))],
                 Dp + (size_t)(k0 + kk) * 128 + c4);
        }
    };
    load_stage2(0, 0);  CP_COMMIT();
    load_stage2(1, 16); CP_COMMIT();

    {
        float rq[4] = {0, 0, 0, 0};
#pragma unroll
        for (int mt = 0; mt < 2; mt++)
#pragma unroll
            for (int nt = 0; nt < 4; nt++) {
                int c0 = wc * 32 + nt * 8 + 2 * tig;
                int row = wr * 32 + mt * 16 + g;
                float b0v = hb2[h * 128 + c0], b1v = hb2[h * 128 + c0 + 1];
                float v0 = f2tf_f(acc[mt][nt][0] + b0v);
                float v1 = f2tf_f(acc[mt][nt][1] + b1v);
                float v2 = f2tf_f(acc[mt][nt][2] + b0v);
                float v3 = f2tf_f(acc[mt][nt][3] + b1v);
                Ss[row * 132 + c0]           = v0;
                Ss[row * 132 + c0 + 1]       = v1;
                Ss[(row + 8) * 132 + c0]     = v2;
                Ss[(row + 8) * 132 + c0 + 1] = v3;
                rq[mt * 2 + 0] += v0 * v0 + v1 * v1;
                rq[mt * 2 + 1] += v2 * v2 + v3 * v3;
            }
#pragma unroll
        for (int off = 1; off < 4; off <<= 1)
#pragma unroll
            for (int q = 0; q < 4; q++)
                rq[q] += __shfl_xor_sync(0xffffffffu, rq[q], off);
        if (tig == 0) {
#pragma unroll
            for (int q = 0; q < 4; q++) {
                int row = wr * 32 + (q >> 1) * 16 + (q & 1) * 8 + g;
                s2p[row * 4 + wc] = rq[q];
            }
        }
    }
    __syncthreads();

    float dcc[2][4][4];
    float scc[2][4];
#pragma unroll
    for (int mt = 0; mt < 2; mt++) {
#pragma unroll
        for (int nt = 0; nt < 4; nt++)
#pragma unroll
            for (int i = 0; i < 4; i++) dcc[mt][nt][i] = 0.f;
#pragma unroll
        for (int i = 0; i < 4; i++) scc[mt][i] = 0.f;
    }

    cur = 0;
    for (int it = 0; it < 8; it++) {
        CP_WAIT_1();
        __syncthreads();
        if (it + 2 < 8) load_stage2((cur + 2 >= 3) ? cur - 1 : cur + 2, (it + 2) * 16);
        CP_COMMIT();
        const uint32_t* Bb = &Bs[cur * 2048];
        const int kbase = it * 16;
#pragma unroll
        for (int ks = 0; ks < 16; ks += 8) {
            uint32_t af[2][4];
#pragma unroll
            for (int mt = 0; mt < 2; mt++) {
                int rb = (wr * 32 + mt * 16 + g) * 132 + kbase + ks;
                af[mt][0] = __float_as_uint(Ss[rb + tig]);
                af[mt][1] = __float_as_uint(Ss[rb + 8 * 132 + tig]);
                af[mt][2] = __float_as_uint(Ss[rb + tig + 4]);
                af[mt][3] = __float_as_uint(Ss[rb + 8 * 132 + tig + 4]);
            }
#pragma unroll
            for (int nt = 0; nt < 4; nt++) {
                int sc = (wc * 32 + nt * 8 + g) ^ swz;
                uint32_t b0 = Bb[(ks + tig) * 128 + sc];
                uint32_t b1 = Bb[(ks + tig + 4) * 128 + sc];
                mma_tf32(dcc[0][nt], af[0], b0, b1);
                mma_tf32(dcc[1][nt], af[1], b0, b1);
            }
            uint32_t b0s = AtT[(kbase + ks + tig) * 8 + g];
            uint32_t b1s = AtT[(kbase + ks + tig + 4) * 8 + g];
            mma_tf32(scc[0], af[0], b0s, b1s);
            mma_tf32(scc[1], af[1], b0s, b1s);
        }
        cur = (cur + 1 == 3) ? 0 : cur + 1;
    }
    __syncthreads();

    if (wc == 0) {
#pragma unroll
        for (int mt = 0; mt < 2; mt++) {
            int row = wr * 32 + mt * 16 + g;
            Sa[row * 8 + 2 * tig]           = scc[mt][0];
            Sa[row * 8 + 2 * tig + 1]       = scc[mt][1];
            Sa[(row + 8) * 8 + 2 * tig]     = scc[mt][2];
            Sa[(row + 8) * 8 + 2 * tig + 1] = scc[mt][3];
        }
    }
    __syncthreads();

    const float invs = 0.08838834764831845f;  // 1/sqrt(128)
    if (tid < 64) {
        int row = tid;
        float s2 = s2p[row * 4 + 0] + s2p[row * 4 + 1] + s2p[row * 4 + 2] + s2p[row * 4 + 3];
        float lgt[8], mx = -1e30f;
#pragma unroll
        for (int a = 0; a < 8; a++) {
            float dd = sqrtf(fmaxf(s2 + a2s[a] - 2.0f * Sa[row * 8 + a], 0.0f));
            lgt[a] = -dd * invs;
            mx = fmaxf(mx, lgt[a]);
        }
        float e[8], se = 0.f;
#pragma unroll
        for (int a = 0; a < 8; a++) { e[a] = expf(lgt[a] - mx); se += e[a]; }
        float ise = 1.0f / se;
#pragma unroll
        for (int a = 0; a < 8; a++) Sw[row * 8 + a] = e[a] * ise;
        Sgt[row] = 0.1f * g_gate[(size_t)(t0 + row) * 4 + h];
    }
    __syncthreads();

#pragma unroll
    for (int mt = 0; mt < 2; mt++)
#pragma unroll
        for (int nt = 0; nt < 4; nt++) {
            int c0 = wc * 32 + nt * 8 + 2 * tig;
#pragma unroll
            for (int half = 0; half < 2; half++) {
                int row = wr * 32 + mt * 16 + g + 8 * half;
                float gt = Sgt[row];
                float sv0 = Ss[row * 132 + c0];
                float sv1 = Ss[row * 132 + c0 + 1];
                float ai0 = 0.f, ai1 = 0.f;
#pragma unroll
                for (int a = 0; a < 8; a++) {
                    float wgt = Sw[row * 8 + a];
                    ai0 += wgt * At[a * 128 + c0];
                    ai1 += wgt * At[a * 128 + c0 + 1];
                }
                float dv0 = dcc[mt][nt][2 * half + 0];
                float dv1 = dcc[mt][nt][2 * half + 1];
                float o0 = f2tf_f(sv0 + gt * (ai0 - sv0 + tanhf(dv0)));
                float o1 = f2tf_f(sv1 + gt * (ai1 - sv1 + tanhf(dv1)));
                *(float2*)&g_comb[(size_t)(t0 + row) * 512 + h * 128 + c0] =
                    make_float2(o0, o1);
            }
        }
}

// ============================================================================
// K4: o1 = gelu(LN(comb @ oW1 + ob1)).  BM=64,BN=512, block 512, 4-stage,
// swizzled B (stride 512).
// smem: As 20480 | Bs 131072 | sB sG sBt 6144 | ps pq 4096 = 161792 B
// ============================================================================
#define K4_SMEM 161792
__global__ void __launch_bounds__(512) k_out1_mma(
    const float* __restrict__ ob1,
    const float* __restrict__ olg, const float* __restrict__ olb)
{
    extern __shared__ __align__(16) char dsm[];
    uint32_t* As = (uint32_t*)dsm;                 // 20480 (4*64*20)
    uint32_t* Bs = (uint32_t*)(dsm + 20480);       // 131072 (4*16*512)
    float* sB  = (float*)(dsm + 151552);
    float* sG  = (float*)(dsm + 153600);
    float* sBt = (float*)(dsm + 155648);
    float* ps  = (float*)(dsm + 157696);           // 64*8
    float* pq  = (float*)(dsm + 159744);

    const int t0 = blockIdx.x * 64;
    const int tid = threadIdx.x, w = tid >> 5, l = tid & 31;
    const int wr = w >> 3, wc = w & 7, g = l >> 2, tig = l & 3;
    const int swz = tig << 3;

    sB[tid] = ob1[tid]; sG[tid] = olg[tid]; sBt[tid] = olb[tid];

    float acc[2][8][4];
#pragma unroll
    for (int mt = 0; mt < 2; mt++)
#pragma unroll
        for (int nt = 0; nt < 8; nt++)
#pragma unroll
            for (int i = 0; i < 4; i++) acc[mt][nt][i] = 0.f;

    const int ar = tid >> 2, ac4 = (tid & 3) * 4;
    const float* Ap = g_comb + (size_t)(t0 + (ar & 63)) * 512 + ac4;

    auto load_stage = [&](int s, int k0) {
        if (tid < 256) cp16(&As[s * 1280 + ar * 20 + ac4], Ap + k0);
#pragma unroll
        for (int i = 0; i < 4; i++) {
            int idx = tid + 512 * i;
            int kk = idx >> 7, c4 = (idx & 127) * 4;
            cp16(&Bs[s * 8192 + kk * 512 + (c4 ^ ((kk & 3) << 3))],
                 g_oW1t + (size_t)(k0 + kk) * 512 + c4);
        }
    };

    load_stage(0, 0);  CP_COMMIT();
    load_stage(1, 16); CP_COMMIT();
    load_stage(2, 32); CP_COMMIT();
    int cur = 0;
    for (int it = 0; it < 32; it++) {
        CP_WAIT_2();
        __syncthreads();
        if (it + 3 < 32) load_stage((cur + 3) & 3, (it + 3) * 16);
        CP_COMMIT();
        const uint32_t* Ab = &As[cur * 1280];
        const uint32_t* Bb = &Bs[cur * 8192];
#pragma unroll
        for (int ks = 0; ks < 16; ks += 8) {
            uint32_t af[2][4];
#pragma unroll
            for (int mt = 0; mt < 2; mt++) {
                int rb = (wr * 32 + mt * 16 + g) * 20 + ks;
                af[mt][0] = Ab[rb + tig];       af[mt][1] = Ab[rb + 160 + tig];
                af[mt][2] = Ab[rb + tig + 4];   af[mt][3] = Ab[rb + 160 + tig + 4];
            }
#pragma unroll
            for (int nt = 0; nt < 8; nt++) {
                int sc = (wc * 64 + nt * 8 + g) ^ swz;
                uint32_t b0 = Bb[(ks + tig) * 512 + sc];
                uint32_t b1 = Bb[(ks + tig + 4) * 512 + sc];
                mma_tf32(acc[0][nt], af[0], b0, b1);
                mma_tf32(acc[1][nt], af[1], b0, b1);
            }
        }
        cur = (cur + 1) & 3;
    }
    __syncthreads();

    float rsm[4] = {0, 0, 0, 0}, rsq[4] = {0, 0, 0, 0};
#pragma unroll
    for (int mt = 0; mt < 2; mt++)
#pragma unroll
        for (int nt = 0; nt < 8; nt++) {
            int c0 = wc * 64 + nt * 8 + 2 * tig;
            float v0 = acc[mt][nt][0] + sB[c0], v1 = acc[mt][nt][1] + sB[c0 + 1];
            float v2 = acc[mt][nt][2] + sB[c0], v3 = acc[mt][nt][3] + sB[c0 + 1];
            acc[mt][nt][0] = v0; acc[mt][nt][1] = v1; acc[mt][nt][2] = v2; acc[mt][nt][3] = v3;
            rsm[mt * 2 + 0] += v0 + v1; rsq[mt * 2 + 0] += v0 * v0 + v1 * v1;
            rsm[mt * 2 + 1] += v2 + v3; rsq[mt * 2 + 1] += v2 * v2 + v3 * v3;
        }
#pragma unroll
    for (int off = 1; off < 4; off <<= 1)
#pragma unroll
        for (int q = 0; q < 4; q++) {
            rsm[q] += __shfl_xor_sync(0xffffffffu, rsm[q], off);
            rsq[q] += __shfl_xor_sync(0xffffffffu, rsq[q], off);
        }
    if (tig == 0) {
#pragma unroll
        for (int q = 0; q < 4; q++) {
            int row = wr * 32 + (q >> 1) * 16 + (q & 1) * 8 + g;
            ps[row * 8 + wc] = rsm[q]; pq[row * 8 + wc] = rsq[q];
        }
    }
    __syncthreads();
    float mv[4], rv[4];
#pragma unroll
    for (int q = 0; q < 4; q++) {
        int row = wr * 32 + (q >> 1) * 16 + (q & 1) * 8 + g;
        float s = 0.f, s2 = 0.f;
#pragma unroll
        for (int j = 0; j < 8; j++) { s += ps[row * 8 + j]; s2 += pq[row * 8 + j]; }
        float m = s * (1.f / 512.f);
        float var = s2 * (1.f / 512.f) - m * m;
        mv[q] = m; rv[q] = rsqrtf(var + EPSV);
    }
#pragma unroll
    for (int mt = 0; mt < 2; mt++)
#pragma unroll
        for (int nt = 0; nt < 8; nt++) {
            int c0 = wc * 64 + nt * 8 + 2 * tig;
            int q0 = mt * 2;
            int row0 = t0 + wr * 32 + mt * 16 + g;
            float u0 = gelu_exact((acc[mt][nt][0] - mv[q0]) * rv[q0] * sG[c0] + sBt[c0]);
            float u1 = gelu_exact((acc[mt][nt][1] - mv[q0]) * rv[q0] * sG[c0 + 1] + sBt[c0 + 1]);
            *(float2*)&g_oact[(size_t)row0 * 512 + c0] = make_float2(f2tf_f(u0), f2tf_f(u1));
            float u2 = gelu_exact((acc[mt][nt][2] - mv[q0 + 1]) * rv[q0 + 1] * sG[c0] + sBt[c0]);
            float u3 = gelu_exact((acc[mt][nt][3] - mv[q0 + 1]) * rv[q0 + 1] * sG[c0 + 1] + sBt[c0 + 1]);
            *(float2*)&g_oact[(size_t)(row0 + 8) * 512 + c0] = make_float2(f2tf_f(u2), f2tf_f(u3));
        }
}

// ============================================================================
// K5: out = xn + oact @ oW2 + ob2.  BM=64,BN=256, block 256, grid (T/64,2),
// 4-stage, swizzled B (stride 256).
// smem: As 20480 | Bs 65536 | sB 1024 = 87040 B (2 CTAs)
// ============================================================================
#define K5_SMEM 87040
__global__ void __launch_bounds__(256) k_out2_mma(
    const float* __restrict__ ob2, float* __restrict__ out)
{
    extern __shared__ __align__(16) char dsm[];
    uint32_t* As = (uint32_t*)dsm;                 // 20480 (4*64*20)
    uint32_t* Bs = (uint32_t*)(dsm + 20480);       // 65536 (4*16*256)
    float* sB = (float*)(dsm + 86016);

    const int t0 = blockIdx.x * 64;
    const int c0base = blockIdx.y * 256;
    const int tid = threadIdx.x, w = tid >> 5, l = tid & 31;
    const int wr = w >> 2, wc = w & 3, g = l >> 2, tig = l & 3;
    const int swz = tig << 3;

    sB[tid] = ob2[c0base + tid];

    float acc[2][8][4];
#pragma unroll
    for (int mt = 0; mt < 2; mt++)
#pragma unroll
        for (int nt = 0; nt < 8; nt++)
#pragma unroll
            for (int i = 0; i < 4; i++) acc[mt][nt][i] = 0.f;

    const int ar = tid >> 2, ac4 = (tid & 3) * 4;
    const float* Ap = g_oact + (size_t)(t0 + ar) * 512 + ac4;

    auto load_stage = [&](int s, int k0) {
        cp16(&As[s * 1280 + ar * 20 + ac4], Ap + k0);
#pragma unroll
        for (int i = 0; i < 4; i++) {
            int idx = tid + 256 * i;
            int kk = idx >> 6, c4 = (idx & 63) * 4;
            cp16(&Bs[s * 4096 + kk * 256 + (c4 ^ ((kk & 3) << 3))],
                 g_oW2t + (size_t)(k0 + kk) * 512 + c0base + c4);
        }
    };

    load_stage(0, 0);  CP_COMMIT();
    load_stage(1, 16); CP_COMMIT();
    load_stage(2, 32); CP_COMMIT();
    int cur = 0;
    for (int it = 0; it < 32; it++) {
        CP_WAIT_2();
        __syncthreads();
        if (it + 3 < 32) load_stage((cur + 3) & 3, (it + 3) * 16);
        CP_COMMIT();
        const uint32_t* Ab = &As[cur * 1280];
        const uint32_t* Bb = &Bs[cur * 4096];
#pragma unroll
        for (int ks = 0; ks < 16; ks += 8) {
            uint32_t af[2][4];
#pragma unroll
            for (int mt = 0; mt < 2; mt++) {
                int rb = (wr * 32 + mt * 16 + g) * 20 + ks;
                af[mt][0] = Ab[rb + tig];       af[mt][1] = Ab[rb + 160 + tig];
                af[mt][2] = Ab[rb + tig + 4];   af[mt][3] = Ab[rb + 160 + tig + 4];
            }
#pragma unroll
            for (int nt = 0; nt < 8; nt++) {
                int sc = (wc * 64 + nt * 8 + g) ^ swz;
                uint32_t b0 = Bb[(ks + tig) * 256 + sc];
                uint32_t b1 = Bb[(ks + tig + 4) * 256 + sc];
                mma_tf32(acc[0][nt], af[0], b0, b1);
                mma_tf32(acc[1][nt], af[1], b0, b1);
            }
        }
        cur = (cur + 1) & 3;
    }

#pragma unroll
    for (int mt = 0; mt < 2; mt++)
#pragma unroll
        for (int nt = 0; nt < 8; nt++) {
            int c0 = wc * 64 + nt * 8 + 2 * tig;
            int col = c0base + c0;
            int row0 = t0 + wr * 32 + mt * 16 + g;
            size_t o0 = (size_t)row0 * 512 + col;
            size_t o1 = (size_t)(row0 + 8) * 512 + col;
            float2 x0 = *(const float2*)&g_xn[o0];
            float2 x1 = *(const float2*)&g_xn[o1];
            *(float2*)&out[o0] = make_float2(acc[mt][nt][0] + sB[c0] + x0.x,
                                             acc[mt][nt][1] + sB[c0 + 1] + x0.y);
            *(float2*)&out[o1] = make_float2(acc[mt][nt][2] + sB[c0] + x1.x,
                                             acc[mt][nt][3] + sB[c0 + 1] + x1.y);
        }
}

// ============================================================================
extern "C" void kernel_launch(void* const* d_in, const int* in_sizes, int n_in,
                              void* d_out, int out_size)
{
    (void)in_sizes; (void)n_in; (void)out_size;
    const float* x    = (const float*)d_in[0];
    const float* ng   = (const float*)d_in[1];
    const float* nb   = (const float*)d_in[2];
    const float* hW1  = (const float*)d_in[3];
    const float* hb1  = (const float*)d_in[4];
    const float* hlg  = (const float*)d_in[5];
    const float* hlb  = (const float*)d_in[6];
    const float* hW2  = (const float*)d_in[7];
    const float* hb2  = (const float*)d_in[8];
    const float* attr = (const float*)d_in[9];
    const float* dynm = (const float*)d_in[10];
    const float* gW   = (const float*)d_in[11];
    const float* gb   = (const float*)d_in[12];
    const float* oW1  = (const float*)d_in[13];
    const float* ob1  = (const float*)d_in[14];
    const float* olg  = (const float*)d_in[15];
    const float* olb  = (const float*)d_in[16];
    const float* oW2  = (const float*)d_in[17];
    const float* ob2  = (const float*)d_in[18];
    float* out = (float*)d_out;

    cudaFuncSetAttribute(k_head1_mma, cudaFuncAttributeMaxDynamicSharedMemorySize, K2_SMEM);
    cudaFuncSetAttribute(k_head2_mma, cudaFuncAttributeMaxDynamicSharedMemorySize, K3_SMEM);
    cudaFuncSetAttribute(k_out1_mma,  cudaFuncAttributeMaxDynamicSharedMemorySize, K4_SMEM);
    cudaFuncSetAttribute(k_out2_mma,  cudaFuncAttributeMaxDynamicSharedMemorySize, K5_SMEM);

    k_prep<<<4864, 256>>>(hW1, hW2, dynm, oW1, oW2);
    k_ln_gate<<<8192, 256>>>(x, ng, nb, gW, gb);

    dim3 gh(T_TOK / 64, 4);
    k_head1_mma<<<gh, 256, K2_SMEM>>>(hb1, hlg, hlb);
    k_head2_mma<<<gh, 256, K3_SMEM>>>(hb2, attr);

    k_out1_mma<<<T_TOK / 64, 512, K4_SMEM>>>(ob1, olg, olb);
    dim3 g5(T_TOK / 64, 2);
    k_out2_mma<<<g5, 256, K5_SMEM>>>(ob2, out);
}

// round 15
// speedup vs baseline: 2.3578x; 1.5251x over previous
#include <cuda_runtime.h>
#include <cuda_fp16.h>
#include <math.h>
#include <stdint.h>

// ----------------------------------------------------------------------------
// NoiseRobustAttractorLayer — R15: GEMMs moved from tf32 m16n8k8 to fp16
// m16n8k16 (same 10-bit mantissa, fp32 accumulate): half the MMA count, half
// the fragment LDS, half the smem/global traffic, BK=32 per barrier.
// C-fragment layout identical -> R14 epilogues unchanged. K3 phase-2
// (dynamics/sa) kept in verified tf32 form.
// ----------------------------------------------------------------------------

#define T_TOK 65536
#define EPSV  1e-5f

__device__ float  g_xn   [(size_t)T_TOK * 512];   // fp32 (residual)
__device__ __half g_xnth [(size_t)T_TOK * 512];   // fp16 (GEMM A)
__device__ float  g_gate [(size_t)T_TOK * 4];
__device__ __half g_hh   [(size_t)T_TOK * 1024];  // fp16
__device__ __half g_combh[(size_t)T_TOK * 512];   // fp16
__device__ __half g_oacth[(size_t)T_TOK * 512];   // fp16

// weights: blocked fp16 [K/16][N][16] (k fastest) ; dynamics kept tf32
__device__ __half g_hW1h[4 * 512 * 256];
__device__ __half g_hW2h[4 * 256 * 128];
__device__ float  g_dynt[4 * 128 * 128];
__device__ __half g_oW1h[512 * 512];
__device__ __half g_oW2h[512 * 512];

__device__ __forceinline__ float warp_sum(float v) {
#pragma unroll
    for (int o = 16; o > 0; o >>= 1) v += __shfl_xor_sync(0xffffffffu, v, o);
    return v;
}
__device__ __forceinline__ float gelu_exact(float x) {
    return 0.5f * x * (1.0f + erff(x * 0.70710678118654752f));
}
__device__ __forceinline__ uint32_t f2tf(float x) {
    uint32_t r; asm("cvt.rna.tf32.f32 %0, %1;" : "=r"(r) : "f"(x)); return r;
}
__device__ __forceinline__ float f2tf_f(float x) {
    return __uint_as_float(f2tf(x));
}
__device__ __forceinline__ void mma_f16(float c[4], const uint32_t a[4],
                                        uint32_t b0, uint32_t b1) {
    asm volatile(
        "mma.sync.aligned.m16n8k16.row.col.f32.f16.f16.f32 "
        "{%0,%1,%2,%3},{%4,%5,%6,%7},{%8,%9},{%0,%1,%2,%3};"
        : "+f"(c[0]), "+f"(c[1]), "+f"(c[2]), "+f"(c[3])
        : "r"(a[0]), "r"(a[1]), "r"(a[2]), "r"(a[3]), "r"(b0), "r"(b1));
}
__device__ __forceinline__ void mma_tf32(float c[4], const uint32_t a[4],
                                         uint32_t b0, uint32_t b1) {
    asm volatile(
        "mma.sync.aligned.m16n8k8.row.col.f32.tf32.tf32.f32 "
        "{%0,%1,%2,%3},{%4,%5,%6,%7},{%8,%9},{%0,%1,%2,%3};"
        : "+f"(c[0]), "+f"(c[1]), "+f"(c[2]), "+f"(c[3])
        : "r"(a[0]), "r"(a[1]), "r"(a[2]), "r"(a[3]), "r"(b0), "r"(b1));
}
__device__ __forceinline__ void cp16(void* s, const void* g) {
    uint32_t sa = (uint32_t)__cvta_generic_to_shared(s);
    asm volatile("cp.async.cg.shared.global [%0], [%1], 16;" :: "r"(sa), "l"(g));
}
#define CP_COMMIT()  asm volatile("cp.async.commit_group;")
#define CP_WAIT_1()  asm volatile("cp.async.wait_group 1;" ::: "memory")
#define CP_WAIT_2()  asm volatile("cp.async.wait_group 2;" ::: "memory")

// ============================================================================
// K0: weight conversion. fp16 blocked [K/16][N][16]; dynamics tf32 row-major.
// ============================================================================
__global__ void __launch_bounds__(256) k_prep(
    const float* __restrict__ hW1, const float* __restrict__ hW2,
    const float* __restrict__ dynm, const float* __restrict__ oW1,
    const float* __restrict__ oW2)
{
    int i = blockIdx.x * 256 + threadIdx.x;
    if (i < 524288) {                       // hW1: 4 heads x 512x256
        int hh = i >> 17, rem = i & 131071;
        int k = rem >> 8, n = rem & 255;
        g_hW1h[(size_t)hh * 131072 + (k >> 4) * 4096 + n * 16 + (k & 15)] =
            __float2half_rn(hW1[i]);
    } else if (i < 655360) {                // hW2: 4 heads x 256x128
        int j = i - 524288;
        int hh = j >> 15, rem = j & 32767;
        int k = rem >> 7, n = rem & 127;
        g_hW2h[(size_t)hh * 32768 + (k >> 4) * 2048 + n * 16 + (k & 15)] =
            __float2half_rn(hW2[j]);
    } else if (i < 720896) {                // dynamics: tf32
        g_dynt[i - 655360] = f2tf_f(dynm[i - 655360]);
    } else if (i < 983040) {                // oW1: 512x512
        int j = i - 720896;
        int k = j >> 9, n = j & 511;
        g_oW1h[(size_t)(k >> 4) * 8192 + n * 16 + (k & 15)] = __float2half_rn(oW1[j]);
    } else if (i < 1245184) {               // oW2: 512x512
        int j = i - 983040;
        int k = j >> 9, n = j & 511;
        g_oW2h[(size_t)(k >> 4) * 8192 + n * 16 + (k & 15)] = __float2half_rn(oW2[j]);
    }
}

// ============================================================================
// K1: warp-per-token LN + gate; writes xn fp32 + fp16 copy.
// ============================================================================
__global__ void __launch_bounds__(256) k_ln_gate(
    const float* __restrict__ x, const float* __restrict__ ng,
    const float* __restrict__ nb, const float* __restrict__ gW,
    const float* __restrict__ gb)
{
    __shared__ float sgW[2048];
    __shared__ float sng[512], snb[512];
    const int tid = threadIdx.x;
    for (int i = tid; i < 2048; i += 256) sgW[i] = gW[i];
    for (int i = tid; i < 512; i += 256) { sng[i] = ng[i]; snb[i] = nb[i]; }
    __syncthreads();

    const int wid = tid >> 5, l = tid & 31;
    const float gb0 = gb[0], gb1 = gb[1], gb2 = gb[2], gb3 = gb[3];
    const float4* sgW4 = (const float4*)sgW;
    const float4* sng4 = (const float4*)sng;
    const float4* snb4 = (const float4*)snb;

    for (int t = blockIdx.x * 8 + wid; t < T_TOK; t += gridDim.x * 8) {
        const float4* xr = (const float4*)(x + (size_t)t * 512);
        float4 v[4];
#pragma unroll
        for (int j = 0; j < 4; j++) v[j] = xr[l + 32 * j];
        float s = 0.f;
#pragma unroll
        for (int j = 0; j < 4; j++) s += v[j].x + v[j].y + v[j].z + v[j].w;
        s = warp_sum(s);
        float m = s * (1.0f / 512.0f);
        float q = 0.f;
#pragma unroll
        for (int j = 0; j < 4; j++) {
            float dx = v[j].x - m, dy = v[j].y - m, dz = v[j].z - m, dw = v[j].w - m;
            q += dx * dx + dy * dy + dz * dz + dw * dw;
        }
        q = warp_sum(q);
        float rs = rsqrtf(q * (1.0f / 512.0f) + EPSV);

        float4 xnv[4];
        float4*  xo   = (float4*)(g_xn + (size_t)t * 512);
        __half2* xoth = (__half2*)(g_xnth + (size_t)t * 512);
#pragma unroll
        for (int j = 0; j < 4; j++) {
            float4 gv = sng4[l + 32 * j];
            float4 bv = snb4[l + 32 * j];
            xnv[j].x = (v[j].x - m) * rs * gv.x + bv.x;
            xnv[j].y = (v[j].y - m) * rs * gv.y + bv.y;
            xnv[j].z = (v[j].z - m) * rs * gv.z + bv.z;
            xnv[j].w = (v[j].w - m) * rs * gv.w + bv.w;
            xo[l + 32 * j] = xnv[j];
            xoth[(l + 32 * j) * 2 + 0] = __floats2half2_rn(xnv[j].x, xnv[j].y);
            xoth[(l + 32 * j) * 2 + 1] = __floats2half2_rn(xnv[j].z, xnv[j].w);
        }
        float p[4] = {0.f, 0.f, 0.f, 0.f};
#pragma unroll
        for (int h = 0; h < 4; h++) {
#pragma unroll
            for (int j = 0; j < 4; j++) {
                float4 wv = sgW4[h * 128 + l + 32 * j];
                p[h] += xnv[j].x * wv.x + xnv[j].y * wv.y
                      + xnv[j].z * wv.z + xnv[j].w * wv.w;
            }
            p[h] = warp_sum(p[h]);
        }
        if (l == 0) {
            g_gate[(size_t)t * 4 + 0] = 1.0f / (1.0f + expf(-(p[0] + gb0)));
            g_gate[(size_t)t * 4 + 1] = 1.0f / (1.0f + expf(-(p[1] + gb1)));
            g_gate[(size_t)t * 4 + 2] = 1.0f / (1.0f + expf(-(p[2] + gb2)));
            g_gate[(size_t)t * 4 + 3] = 1.0f / (1.0f + expf(-(p[3] + gb3)));
        }
    }
}

// ============================================================================
// K2: h = gelu(LN(xn @ hW1[h] + hb1)).  fp16 m16n8k16, BM=64, BN=256, BK=32,
// block 256, 4-stage.  smem: As 16384 | Bs 65536 | params 5120 = 87040 (2 CTA)
// ============================================================================
#define K2_SMEM 87040
__global__ void __launch_bounds__(256) k_head1_mma(
    const float* __restrict__ hb1,
    const float* __restrict__ hlg, const float* __restrict__ hlb)
{
    extern __shared__ __align__(16) char dsm[];
    uint32_t* As = (uint32_t*)dsm;                 // 16384 B (4*1024 w)
    uint32_t* Bs = (uint32_t*)(dsm + 16384);       // 65536 B (4*4096 w)
    float* sB  = (float*)(dsm + 81920);
    float* sG  = (float*)(dsm + 82944);
    float* sBt = (float*)(dsm + 83968);
    float* ps  = (float*)(dsm + 84992);            // 64*4
    float* pq  = (float*)(dsm + 86016);            // 64*4

    const int h = blockIdx.y;
    const int t0 = blockIdx.x * 64;
    const int tid = threadIdx.x, w = tid >> 5, l = tid & 31;
    const int wr = w >> 2, wc = w & 3, g = l >> 2, tig = l & 3;
    const int w0 = tig ^ (g & 4), w1 = w0 ^ 4;

    sB[tid] = hb1[h * 256 + tid]; sG[tid] = hlg[h * 256 + tid]; sBt[tid] = hlb[h * 256 + tid];

    float acc[2][8][4];
#pragma unroll
    for (int mt = 0; mt < 2; mt++)
#pragma unroll
        for (int nt = 0; nt < 8; nt++)
#pragma unroll
            for (int i = 0; i < 4; i++) acc[mt][nt][i] = 0.f;

    const __half* Wh = g_hW1h + (size_t)h * 131072;
    const int arow = tid >> 2, ach = tid & 3;
    const uint32_t adst = (ach >> 1) * 512 + arow * 8 + (((ach & 1) * 4) ^ (arow & 4));
    const __half* Ap = g_xnth + (size_t)(t0 + arow) * 512 + ach * 8;

    auto load_stage = [&](int s, int k0) {
        cp16(&As[s * 1024 + adst], Ap + k0);
#pragma unroll
        for (int i = 0; i < 4; i++) {
            int idx = tid + 256 * i;
            int n = idx >> 2, bch = idx & 3;
            int bsub = bch >> 1, bc = (bch & 1) * 4;
            cp16(&Bs[s * 4096 + bsub * 2048 + n * 8 + (bc ^ (n & 4))],
                 Wh + ((size_t)((k0 >> 4) + bsub) * 256 + n) * 16 + bc * 2);
        }
    };

    load_stage(0, 0);  CP_COMMIT();
    load_stage(1, 32); CP_COMMIT();
    load_stage(2, 64); CP_COMMIT();
    int cur = 0;
    for (int it = 0; it < 16; it++) {
        CP_WAIT_2();
        __syncthreads();
        if (it + 3 < 16) load_stage((cur + 3) & 3, (it + 3) * 32);
        CP_COMMIT();
        const uint32_t* Ab = &As[cur * 1024];
        const uint32_t* Bb = &Bs[cur * 4096];
#pragma unroll
        for (int sub = 0; sub < 2; sub++) {
            const uint32_t* Asb = Ab + sub * 512;
            const uint32_t* Bsb = Bb + sub * 2048;
            uint32_t af[2][4];
#pragma unroll
            for (int mt = 0; mt < 2; mt++) {
                int rb = (wr * 32 + mt * 16 + g) * 8;
                af[mt][0] = Asb[rb + w0];      af[mt][1] = Asb[rb + 64 + w0];
                af[mt][2] = Asb[rb + w1];      af[mt][3] = Asb[rb + 64 + w1];
            }
#pragma unroll
            for (int nt = 0; nt < 8; nt++) {
                int nb = (wc * 64 + nt * 8 + g) * 8;
                uint32_t b0 = Bsb[nb + w0], b1 = Bsb[nb + w1];
                mma_f16(acc[0][nt], af[0], b0, b1);
                mma_f16(acc[1][nt], af[1], b0, b1);
            }
        }
        cur = (cur + 1) & 3;
    }
    __syncthreads();

    // epilogue: bias + LN(256) + gelu ; store fp16
    float rsm[4] = {0, 0, 0, 0}, rsq[4] = {0, 0, 0, 0};
#pragma unroll
    for (int mt = 0; mt < 2; mt++)
#pragma unroll
        for (int nt = 0; nt < 8; nt++) {
            int c0 = wc * 64 + nt * 8 + 2 * tig;
            float v0 = acc[mt][nt][0] + sB[c0], v1 = acc[mt][nt][1] + sB[c0 + 1];
            float v2 = acc[mt][nt][2] + sB[c0], v3 = acc[mt][nt][3] + sB[c0 + 1];
            acc[mt][nt][0] = v0; acc[mt][nt][1] = v1; acc[mt][nt][2] = v2; acc[mt][nt][3] = v3;
            rsm[mt * 2 + 0] += v0 + v1; rsq[mt * 2 + 0] += v0 * v0 + v1 * v1;
            rsm[mt * 2 + 1] += v2 + v3; rsq[mt * 2 + 1] += v2 * v2 + v3 * v3;
        }
#pragma unroll
    for (int off = 1; off < 4; off <<= 1)
#pragma unroll
        for (int q = 0; q < 4; q++) {
            rsm[q] += __shfl_xor_sync(0xffffffffu, rsm[q], off);
            rsq[q] += __shfl_xor_sync(0xffffffffu, rsq[q], off);
        }
    if (tig == 0) {
#pragma unroll
        for (int q = 0; q < 4; q++) {
            int row = wr * 32 + (q >> 1) * 16 + (q & 1) * 8 + g;
            ps[row * 4 + wc] = rsm[q]; pq[row * 4 + wc] = rsq[q];
        }
    }
    __syncthreads();
    float mv[4], rv[4];
#pragma unroll
    for (int q = 0; q < 4; q++) {
        int row = wr * 32 + (q >> 1) * 16 + (q & 1) * 8 + g;
        float s  = ps[row * 4 + 0] + ps[row * 4 + 1] + ps[row * 4 + 2] + ps[row * 4 + 3];
        float s2 = pq[row * 4 + 0] + pq[row * 4 + 1] + pq[row * 4 + 2] + pq[row * 4 + 3];
        float m = s * (1.f / 256.f);
        float var = s2 * (1.f / 256.f) - m * m;
        mv[q] = m; rv[q] = rsqrtf(var + EPSV);
    }
#pragma unroll
    for (int mt = 0; mt < 2; mt++)
#pragma unroll
        for (int nt = 0; nt < 8; nt++) {
            int c0 = wc * 64 + nt * 8 + 2 * tig;
            int q0 = mt * 2;
            int row0 = t0 + wr * 32 + mt * 16 + g;
            float u0 = gelu_exact((acc[mt][nt][0] - mv[q0]) * rv[q0] * sG[c0] + sBt[c0]);
            float u1 = gelu_exact((acc[mt][nt][1] - mv[q0]) * rv[q0] * sG[c0 + 1] + sBt[c0 + 1]);
            *(__half2*)&g_hh[(size_t)row0 * 1024 + h * 256 + c0] = __floats2half2_rn(u0, u1);
            float u2 = gelu_exact((acc[mt][nt][2] - mv[q0 + 1]) * rv[q0 + 1] * sG[c0] + sBt[c0]);
            float u3 = gelu_exact((acc[mt][nt][3] - mv[q0 + 1]) * rv[q0 + 1] * sG[c0 + 1] + sBt[c0 + 1]);
            *(__half2*)&g_hh[(size_t)(row0 + 8) * 1024 + h * 256 + c0] = __floats2half2_rn(u2, u3);
        }
}

// ============================================================================
// K3: phase-1 state GEMM in fp16 (BM=64,BN=128,BK=32, 4-stage);
// phase-2 [dyn|sa] kept in verified tf32 form; softmax mix unchanged.
// smem: As 16384 | Bs 32768 | Ss 33792 | At 4096 | AtT 4096 | Sa 2048 |
//       Sw 2048 | s2p 1024 | a2s 32 | Sgt 256 = 96544  (2 CTAs)
// ============================================================================
#define K3_SMEM 96544
__global__ void __launch_bounds__(256, 2) k_head2_mma(
    const float* __restrict__ hb2, const float* __restrict__ attr)
{
    extern __shared__ __align__(16) char dsm[];
    uint32_t* As  = (uint32_t*)dsm;                // 16384 (4*1024 w)
    uint32_t* Bs  = (uint32_t*)(dsm + 16384);      // 32768 (fp16: 4*2048 w / tf32: 3*2048 w)
    float*    Ss  = (float*)(dsm + 49152);         // 33792 (64*132)
    float*    At  = (float*)(dsm + 82944);         //  4096 (8*128)
    uint32_t* AtT = (uint32_t*)(dsm + 87040);      //  4096 (128*8)
    float*    Sa  = (float*)(dsm + 91136);         //  2048
    float*    Sw  = (float*)(dsm + 93184);         //  2048
    float*    s2p = (float*)(dsm + 95232);         //  1024
    float*    a2s = (float*)(dsm + 96256);         //    32
    float*    Sgt = (float*)(dsm + 96288);         //   256

    const int h = blockIdx.y;
    const int t0 = blockIdx.x * 64;
    const int tid = threadIdx.x, w = tid >> 5, l = tid & 31;
    const int wr = w >> 2, wc = w & 3, g = l >> 2, tig = l & 3;
    const int w0 = tig ^ (g & 4), w1 = w0 ^ 4;
    const int swz = tig << 3;

    {
        float4 v = *(const float4*)(attr + (size_t)h * 1024 + tid * 4);
        *(float4*)&At[tid * 4] = v;
        int a0 = tid >> 5, d0 = (tid & 31) * 4;
        AtT[(d0 + 0) * 8 + a0] = f2tf(v.x);
        AtT[(d0 + 1) * 8 + a0] = f2tf(v.y);
        AtT[(d0 + 2) * 8 + a0] = f2tf(v.z);
        AtT[(d0 + 3) * 8 + a0] = f2tf(v.w);
    }

    // ---- phase 1: state = h @ hW2[h]  (fp16) ----
    float acc[2][4][4];
#pragma unroll
    for (int mt = 0; mt < 2; mt++)
#pragma unroll
        for (int nt = 0; nt < 4; nt++)
#pragma unroll
            for (int i = 0; i < 4; i++) acc[mt][nt][i] = 0.f;

    const __half* Wh = g_hW2h + (size_t)h * 32768;
    const int arow = tid >> 2, ach = tid & 3;
    const uint32_t adst = (ach >> 1) * 512 + arow * 8 + (((ach & 1) * 4) ^ (arow & 4));
    const __half* Ap = g_hh + (size_t)(t0 + arow) * 1024 + h * 256 + ach * 8;

    auto load_stage1 = [&](int s, int k0) {
        cp16(&As[s * 1024 + adst], Ap + k0);
#pragma unroll
        for (int i = 0; i < 2; i++) {
            int idx = tid + 256 * i;           // 0..511
            int n = idx >> 2, bch = idx & 3;
            int bsub = bch >> 1, bc = (bch & 1) * 4;
            cp16(&Bs[s * 2048 + bsub * 1024 + n * 8 + (bc ^ (n & 4))],
                 Wh + ((size_t)((k0 >> 4) + bsub) * 128 + n) * 16 + bc * 2);
        }
    };

    load_stage1(0, 0);  CP_COMMIT();
    load_stage1(1, 32); CP_COMMIT();
    load_stage1(2, 64); CP_COMMIT();
    __syncthreads();
    if (tid < 8) {
        float q = 0.f;
#pragma unroll
        for (int k = 0; k < 128; k++) q += At[tid * 128 + k] * At[tid * 128 + k];
        a2s[tid] = q;
    }

    int cur = 0;
    for (int it = 0; it < 8; it++) {
        CP_WAIT_2();
        __syncthreads();
        if (it + 3 < 8) load_stage1((cur + 3) & 3, (it + 3) * 32);
        CP_COMMIT();
        const uint32_t* Ab = &As[cur * 1024];
        const uint32_t* Bb = &Bs[cur * 2048];
#pragma unroll
        for (int sub = 0; sub < 2; sub++) {
            const uint32_t* Asb = Ab + sub * 512;
            const uint32_t* Bsb = Bb + sub * 1024;
            uint32_t af[2][4];
#pragma unroll
            for (int mt = 0; mt < 2; mt++) {
                int rb = (wr * 32 + mt * 16 + g) * 8;
                af[mt][0] = Asb[rb + w0];      af[mt][1] = Asb[rb + 64 + w0];
                af[mt][2] = Asb[rb + w1];      af[mt][3] = Asb[rb + 64 + w1];
            }
#pragma unroll
            for (int nt = 0; nt < 4; nt++) {
                int nb = (wc * 32 + nt * 8 + g) * 8;
                uint32_t b0 = Bsb[nb + w0], b1 = Bsb[nb + w1];
                mma_f16(acc[0][nt], af[0], b0, b1);
                mma_f16(acc[1][nt], af[1], b0, b1);
            }
        }
        cur = (cur + 1) & 3;
    }
    __syncthreads();

    // prefetch dynamics (tf32) stages 0,1 into Bs (stride 2048 words/stage)
    const float* Dp = g_dynt + (size_t)h * 128 * 128;
    auto load_stage2 = [&](int s, int k0) {
#pragma unroll
        for (int i = 0; i < 2; i++) {
            int idx = tid + 256 * i;
            int kk = idx >> 5, c4 = (idx & 31) * 4;
            cp16(&Bs[s * 2048 + kk * 128 + (c4 ^ ((kk & 3) << 3))],
                 Dp + (size_t)(k0 + kk) * 128 + c4);
        }
    };
    load_stage2(0, 0);  CP_COMMIT();
    load_stage2(1, 16); CP_COMMIT();

    // epilogue 1: bias, tf32-round, store Ss, ||s||^2 partials (unchanged)
    {
        float rq[4] = {0, 0, 0, 0};
#pragma unroll
        for (int mt = 0; mt < 2; mt++)
#pragma unroll
            for (int nt = 0; nt < 4; nt++) {
                int c0 = wc * 32 + nt * 8 + 2 * tig;
                int row = wr * 32 + mt * 16 + g;
                float b0v = hb2[h * 128 + c0], b1v = hb2[h * 128 + c0 + 1];
                float v0 = f2tf_f(acc[mt][nt][0] + b0v);
                float v1 = f2tf_f(acc[mt][nt][1] + b1v);
                float v2 = f2tf_f(acc[mt][nt][2] + b0v);
                float v3 = f2tf_f(acc[mt][nt][3] + b1v);
                Ss[row * 132 + c0]           = v0;
                Ss[row * 132 + c0 + 1]       = v1;
                Ss[(row + 8) * 132 + c0]     = v2;
                Ss[(row + 8) * 132 + c0 + 1] = v3;
                rq[mt * 2 + 0] += v0 * v0 + v1 * v1;
                rq[mt * 2 + 1] += v2 * v2 + v3 * v3;
            }
#pragma unroll
        for (int off = 1; off < 4; off <<= 1)
#pragma unroll
            for (int q = 0; q < 4; q++)
                rq[q] += __shfl_xor_sync(0xffffffffu, rq[q], off);
        if (tig == 0) {
#pragma unroll
            for (int q = 0; q < 4; q++) {
                int row = wr * 32 + (q >> 1) * 16 + (q & 1) * 8 + g;
                s2p[row * 4 + wc] = rq[q];
            }
        }
    }
    __syncthreads();

    // ---- phase 2: [dyn | sa] (tf32, verbatim R14) ----
    float dcc[2][4][4];
    float scc[2][4];
#pragma unroll
    for (int mt = 0; mt < 2; mt++) {
#pragma unroll
        for (int nt = 0; nt < 4; nt++)
#pragma unroll
            for (int i = 0; i < 4; i++) dcc[mt][nt][i] = 0.f;
#pragma unroll
        for (int i = 0; i < 4; i++) scc[mt][i] = 0.f;
    }

    cur = 0;
    for (int it = 0; it < 8; it++) {
        CP_WAIT_1();
        __syncthreads();
        if (it + 2 < 8) load_stage2((cur + 2 >= 3) ? cur - 1 : cur + 2, (it + 2) * 16);
        CP_COMMIT();
        const uint32_t* Bb = &Bs[cur * 2048];
        const int kbase = it * 16;
#pragma unroll
        for (int ks = 0; ks < 16; ks += 8) {
            uint32_t af[2][4];
#pragma unroll
            for (int mt = 0; mt < 2; mt++) {
                int rb = (wr * 32 + mt * 16 + g) * 132 + kbase + ks;
                af[mt][0] = __float_as_uint(Ss[rb + tig]);
                af[mt][1] = __float_as_uint(Ss[rb + 8 * 132 + tig]);
                af[mt][2] = __float_as_uint(Ss[rb + tig + 4]);
                af[mt][3] = __float_as_uint(Ss[rb + 8 * 132 + tig + 4]);
            }
#pragma unroll
            for (int nt = 0; nt < 4; nt++) {
                int sc = (wc * 32 + nt * 8 + g) ^ swz;
                uint32_t b0 = Bb[(ks + tig) * 128 + sc];
                uint32_t b1 = Bb[(ks + tig + 4) * 128 + sc];
                mma_tf32(dcc[0][nt], af[0], b0, b1);
                mma_tf32(dcc[1][nt], af[1], b0, b1);
            }
            uint32_t b0s = AtT[(kbase + ks + tig) * 8 + g];
            uint32_t b1s = AtT[(kbase + ks + tig + 4) * 8 + g];
            mma_tf32(scc[0], af[0], b0s, b1s);
            mma_tf32(scc[1], af[1], b0s, b1s);
        }
        cur = (cur + 1 == 3) ? 0 : cur + 1;
    }
    __syncthreads();

    if (wc == 0) {
#pragma unroll
        for (int mt = 0; mt < 2; mt++) {
            int row = wr * 32 + mt * 16 + g;
            Sa[row * 8 + 2 * tig]           = scc[mt][0];
            Sa[row * 8 + 2 * tig + 1]       = scc[mt][1];
            Sa[(row + 8) * 8 + 2 * tig]     = scc[mt][2];
            Sa[(row + 8) * 8 + 2 * tig + 1] = scc[mt][3];
        }
    }
    __syncthreads();

    const float invs = 0.08838834764831845f;  // 1/sqrt(128)
    if (tid < 64) {
        int row = tid;
        float s2 = s2p[row * 4 + 0] + s2p[row * 4 + 1] + s2p[row * 4 + 2] + s2p[row * 4 + 3];
        float lgt[8], mx = -1e30f;
#pragma unroll
        for (int a = 0; a < 8; a++) {
            float dd = sqrtf(fmaxf(s2 + a2s[a] - 2.0f * Sa[row * 8 + a], 0.0f));
            lgt[a] = -dd * invs;
            mx = fmaxf(mx, lgt[a]);
        }
        float e[8], se = 0.f;
#pragma unroll
        for (int a = 0; a < 8; a++) { e[a] = expf(lgt[a] - mx); se += e[a]; }
        float ise = 1.0f / se;
#pragma unroll
        for (int a = 0; a < 8; a++) Sw[row * 8 + a] = e[a] * ise;
        Sgt[row] = 0.1f * g_gate[(size_t)(t0 + row) * 4 + h];
    }
    __syncthreads();

#pragma unroll
    for (int mt = 0; mt < 2; mt++)
#pragma unroll
        for (int nt = 0; nt < 4; nt++) {
            int c0 = wc * 32 + nt * 8 + 2 * tig;
#pragma unroll
            for (int half = 0; half < 2; half++) {
                int row = wr * 32 + mt * 16 + g + 8 * half;
                float gt = Sgt[row];
                float sv0 = Ss[row * 132 + c0];
                float sv1 = Ss[row * 132 + c0 + 1];
                float ai0 = 0.f, ai1 = 0.f;
#pragma unroll
                for (int a = 0; a < 8; a++) {
                    float wgt = Sw[row * 8 + a];
                    ai0 += wgt * At[a * 128 + c0];
                    ai1 += wgt * At[a * 128 + c0 + 1];
                }
                float dv0 = dcc[mt][nt][2 * half + 0];
                float dv1 = dcc[mt][nt][2 * half + 1];
                float o0 = sv0 + gt * (ai0 - sv0 + tanhf(dv0));
                float o1 = sv1 + gt * (ai1 - sv1 + tanhf(dv1));
                *(__half2*)&g_combh[(size_t)(t0 + row) * 512 + h * 128 + c0] =
                    __floats2half2_rn(o0, o1);
            }
        }
}

// ============================================================================
// K4: o1 = gelu(LN(comb @ oW1 + ob1)).  fp16, BM=64, BN=512, BK=32, block 512,
// 4-stage.  smem: As 16384 | Bs 131072 | params 6144 | ps pq 4096 = 157696
// ============================================================================
#define K4_SMEM 157696
__global__ void __launch_bounds__(512) k_out1_mma(
    const float* __restrict__ ob1,
    const float* __restrict__ olg, const float* __restrict__ olb)
{
    extern __shared__ __align__(16) char dsm[];
    uint32_t* As = (uint32_t*)dsm;                 // 16384 B
    uint32_t* Bs = (uint32_t*)(dsm + 16384);       // 131072 B (4*8192 w)
    float* sB  = (float*)(dsm + 147456);
    float* sG  = (float*)(dsm + 149504);
    float* sBt = (float*)(dsm + 151552);
    float* ps  = (float*)(dsm + 153600);           // 64*8
    float* pq  = (float*)(dsm + 155648);

    const int t0 = blockIdx.x * 64;
    const int tid = threadIdx.x, w = tid >> 5, l = tid & 31;
    const int wr = w >> 3, wc = w & 7, g = l >> 2, tig = l & 3;
    const int w0 = tig ^ (g & 4), w1 = w0 ^ 4;

    sB[tid] = ob1[tid]; sG[tid] = olg[tid]; sBt[tid] = olb[tid];

    float acc[2][8][4];
#pragma unroll
    for (int mt = 0; mt < 2; mt++)
#pragma unroll
        for (int nt = 0; nt < 8; nt++)
#pragma unroll
            for (int i = 0; i < 4; i++) acc[mt][nt][i] = 0.f;

    const int arow = (tid & 255) >> 2, ach = tid & 3;
    const uint32_t adst = (ach >> 1) * 512 + arow * 8 + (((ach & 1) * 4) ^ (arow & 4));
    const __half* Ap = g_combh + (size_t)(t0 + arow) * 512 + ach * 8;

    auto load_stage = [&](int s, int k0) {
        if (tid < 256) cp16(&As[s * 1024 + adst], Ap + k0);
#pragma unroll
        for (int i = 0; i < 4; i++) {
            int idx = tid + 512 * i;           // 0..2047
            int n = idx >> 2, bch = idx & 3;
            int bsub = bch >> 1, bc = (bch & 1) * 4;
            cp16(&Bs[s * 8192 + bsub * 4096 + n * 8 + (bc ^ (n & 4))],
                 g_oW1h + ((size_t)((k0 >> 4) + bsub) * 512 + n) * 16 + bc * 2);
        }
    };

    load_stage(0, 0);  CP_COMMIT();
    load_stage(1, 32); CP_COMMIT();
    load_stage(2, 64); CP_COMMIT();
    int cur = 0;
    for (int it = 0; it < 16; it++) {
        CP_WAIT_2();
        __syncthreads();
        if (it + 3 < 16) load_stage((cur + 3) & 3, (it + 3) * 32);
        CP_COMMIT();
        const uint32_t* Ab = &As[cur * 1024];
        const uint32_t* Bb = &Bs[cur * 8192];
#pragma unroll
        for (int sub = 0; sub < 2; sub++) {
            const uint32_t* Asb = Ab + sub * 512;
            const uint32_t* Bsb = Bb + sub * 4096;
            uint32_t af[2][4];
#pragma unroll
            for (int mt = 0; mt < 2; mt++) {
                int rb = (wr * 32 + mt * 16 + g) * 8;
                af[mt][0] = Asb[rb + w0];      af[mt][1] = Asb[rb + 64 + w0];
                af[mt][2] = Asb[rb + w1];      af[mt][3] = Asb[rb + 64 + w1];
            }
#pragma unroll
            for (int nt = 0; nt < 8; nt++) {
                int nb = (wc * 64 + nt * 8 + g) * 8;
                uint32_t b0 = Bsb[nb + w0], b1 = Bsb[nb + w1];
                mma_f16(acc[0][nt], af[0], b0, b1);
                mma_f16(acc[1][nt], af[1], b0, b1);
            }
        }
        cur = (cur + 1) & 3;
    }
    __syncthreads();

    float rsm[4] = {0, 0, 0, 0}, rsq[4] = {0, 0, 0, 0};
#pragma unroll
    for (int mt = 0; mt < 2; mt++)
#pragma unroll
        for (int nt = 0; nt < 8; nt++) {
            int c0 = wc * 64 + nt * 8 + 2 * tig;
            float v0 = acc[mt][nt][0] + sB[c0], v1 = acc[mt][nt][1] + sB[c0 + 1];
            float v2 = acc[mt][nt][2] + sB[c0], v3 = acc[mt][nt][3] + sB[c0 + 1];
            acc[mt][nt][0] = v0; acc[mt][nt][1] = v1; acc[mt][nt][2] = v2; acc[mt][nt][3] = v3;
            rsm[mt * 2 + 0] += v0 + v1; rsq[mt * 2 + 0] += v0 * v0 + v1 * v1;
            rsm[mt * 2 + 1] += v2 + v3; rsq[mt * 2 + 1] += v2 * v2 + v3 * v3;
        }
#pragma unroll
    for (int off = 1; off < 4; off <<= 1)
#pragma unroll
        for (int q = 0; q < 4; q++) {
            rsm[q] += __shfl_xor_sync(0xffffffffu, rsm[q], off);
            rsq[q] += __shfl_xor_sync(0xffffffffu, rsq[q], off);
        }
    if (tig == 0) {
#pragma unroll
        for (int q = 0; q < 4; q++) {
            int row = wr * 32 + (q >> 1) * 16 + (q & 1) * 8 + g;
            ps[row * 8 + wc] = rsm[q]; pq[row * 8 + wc] = rsq[q];
        }
    }
    __syncthreads();
    float mv[4], rv[4];
#pragma unroll
    for (int q = 0; q < 4; q++) {
        int row = wr * 32 + (q >> 1) * 16 + (q & 1) * 8 + g;
        float s = 0.f, s2 = 0.f;
#pragma unroll
        for (int j = 0; j < 8; j++) { s += ps[row * 8 + j]; s2 += pq[row * 8 + j]; }
        float m = s * (1.f / 512.f);
        float var = s2 * (1.f / 512.f) - m * m;
        mv[q] = m; rv[q] = rsqrtf(var + EPSV);
    }
#pragma unroll
    for (int mt = 0; mt < 2; mt++)
#pragma unroll
        for (int nt = 0; nt < 8; nt++) {
            int c0 = wc * 64 + nt * 8 + 2 * tig;
            int q0 = mt * 2;
            int row0 = t0 + wr * 32 + mt * 16 + g;
            float u0 = gelu_exact((acc[mt][nt][0] - mv[q0]) * rv[q0] * sG[c0] + sBt[c0]);
            float u1 = gelu_exact((acc[mt][nt][1] - mv[q0]) * rv[q0] * sG[c0 + 1] + sBt[c0 + 1]);
            *(__half2*)&g_oacth[(size_t)row0 * 512 + c0] = __floats2half2_rn(u0, u1);
            float u2 = gelu_exact((acc[mt][nt][2] - mv[q0 + 1]) * rv[q0 + 1] * sG[c0] + sBt[c0]);
            float u3 = gelu_exact((acc[mt][nt][3] - mv[q0 + 1]) * rv[q0 + 1] * sG[c0 + 1] + sBt[c0 + 1]);
            *(__half2*)&g_oacth[(size_t)(row0 + 8) * 512 + c0] = __floats2half2_rn(u2, u3);
        }
}

// ============================================================================
// K5: out = xn + oact @ oW2 + ob2.  fp16, BM=64, BN=256, BK=32, block 256,
// grid (T/64, 2), 4-stage.  smem: As 16384 | Bs 65536 | sB 1024 = 82944 (2 CTA)
// ============================================================================
#define K5_SMEM 82944
__global__ void __launch_bounds__(256) k_out2_mma(
    const float* __restrict__ ob2, float* __restrict__ out)
{
    extern __shared__ __align__(16) char dsm[];
    uint32_t* As = (uint32_t*)dsm;                 // 16384
    uint32_t* Bs = (uint32_t*)(dsm + 16384);       // 65536
    float* sB = (float*)(dsm + 81920);

    const int t0 = blockIdx.x * 64;
    const int c0base = blockIdx.y * 256;
    const int tid = threadIdx.x, w = tid >> 5, l = tid & 31;
    const int wr = w >> 2, wc = w & 3, g = l >> 2, tig = l & 3;
    const int w0 = tig ^ (g & 4), w1 = w0 ^ 4;

    sB[tid] = ob2[c0base + tid];

    float acc[2][8][4];
#pragma unroll
    for (int mt = 0; mt < 2; mt++)
#pragma unroll
        for (int nt = 0; nt < 8; nt++)
#pragma unroll
            for (int i = 0; i < 4; i++) acc[mt][nt][i] = 0.f;

    const int arow = tid >> 2, ach = tid & 3;
    const uint32_t adst = (ach >> 1) * 512 + arow * 8 + (((ach & 1) * 4) ^ (arow & 4));
    const __half* Ap = g_oacth + (size_t)(t0 + arow) * 512 + ach * 8;

    auto load_stage = [&](int s, int k0) {
        cp16(&As[s * 1024 + adst], Ap + k0);
#pragma unroll
        for (int i = 0; i < 4; i++) {
            int idx = tid + 256 * i;
            int n = idx >> 2, bch = idx & 3;
            int bsub = bch >> 1, bc = (bch & 1) * 4;
            cp16(&Bs[s * 4096 + bsub * 2048 + n * 8 + (bc ^ (n & 4))],
                 g_oW2h + ((size_t)((k0 >> 4) + bsub) * 512 + c0base + n) * 16 + bc * 2);
        }
    };

    load_stage(0, 0);  CP_COMMIT();
    load_stage(1, 32); CP_COMMIT();
    load_stage(2, 64); CP_COMMIT();
    int cur = 0;
    for (int it = 0; it < 16; it++) {
        CP_WAIT_2();
        __syncthreads();
        if (it + 3 < 16) load_stage((cur + 3) & 3, (it + 3) * 32);
        CP_COMMIT();
        const uint32_t* Ab = &As[cur * 1024];
        const uint32_t* Bb = &Bs[cur * 4096];
#pragma unroll
        for (int sub = 0; sub < 2; sub++) {
            const uint32_t* Asb = Ab + sub * 512;
            const uint32_t* Bsb = Bb + sub * 2048;
            uint32_t af[2][4];
#pragma unroll
            for (int mt = 0; mt < 2; mt++) {
                int rb = (wr * 32 + mt * 16 + g) * 8;
                af[mt][0] = Asb[rb + w0];      af[mt][1] = Asb[rb + 64 + w0];
                af[mt][2] = Asb[rb + w1];      af[mt][3] = Asb[rb + 64 + w1];
            }
#pragma unroll
            for (int nt = 0; nt < 8; nt++) {
                int nb = (wc * 64 + nt * 8 + g) * 8;
                uint32_t b0 = Bsb[nb + w0], b1 = Bsb[nb + w1];
                mma_f16(acc[0][nt], af[0], b0, b1);
                mma_f16(acc[1][nt], af[1], b0, b1);
            }
        }
        cur = (cur + 1) & 3;
    }

#pragma unroll
    for (int mt = 0; mt < 2; mt++)
#pragma unroll
        for (int nt = 0; nt < 8; nt++) {
            int c0 = wc * 64 + nt * 8 + 2 * tig;
            int col = c0base + c0;
            int row0 = t0 + wr * 32 + mt * 16 + g;
            size_t o0 = (size_t)row0 * 512 + col;
            size_t o1 = (size_t)(row0 + 8) * 512 + col;
            float2 x0 = *(const float2*)&g_xn[o0];
            float2 x1 = *(const float2*)&g_xn[o1];
            *(float2*)&out[o0] = make_float2(acc[mt][nt][0] + sB[c0] + x0.x,
                                             acc[mt][nt][1] + sB[c0 + 1] + x0.y);
            *(float2*)&out[o1] = make_float2(acc[mt][nt][2] + sB[c0] + x1.x,
                                             acc[mt][nt][3] + sB[c0 + 1] + x1.y);
        }
}

// ============================================================================
extern "C" void kernel_launch(void* const* d_in, const int* in_sizes, int n_in,
                              void* d_out, int out_size)
{
    (void)in_sizes; (void)n_in; (void)out_size;
    const float* x    = (const float*)d_in[0];
    const float* ng   = (const float*)d_in[1];
    const float* nb   = (const float*)d_in[2];
    const float* hW1  = (const float*)d_in[3];
    const float* hb1  = (const float*)d_in[4];
    const float* hlg  = (const float*)d_in[5];
    const float* hlb  = (const float*)d_in[6];
    const float* hW2  = (const float*)d_in[7];
    const float* hb2  = (const float*)d_in[8];
    const float* attr = (const float*)d_in[9];
    const float* dynm = (const float*)d_in[10];
    const float* gW   = (const float*)d_in[11];
    const float* gb   = (const float*)d_in[12];
    const float* oW1  = (const float*)d_in[13];
    const float* ob1  = (const float*)d_in[14];
    const float* olg  = (const float*)d_in[15];
    const float* olb  = (const float*)d_in[16];
    const float* oW2  = (const float*)d_in[17];
    const float* ob2  = (const float*)d_in[18];
    float* out = (float*)d_out;

    cudaFuncSetAttribute(k_head1_mma, cudaFuncAttributeMaxDynamicSharedMemorySize, K2_SMEM);
    cudaFuncSetAttribute(k_head2_mma, cudaFuncAttributeMaxDynamicSharedMemorySize, K3_SMEM);
    cudaFuncSetAttribute(k_out1_mma,  cudaFuncAttributeMaxDynamicSharedMemorySize, K4_SMEM);
    cudaFuncSetAttribute(k_out2_mma,  cudaFuncAttributeMaxDynamicSharedMemorySize, K5_SMEM);

    k_prep<<<4864, 256>>>(hW1, hW2, dynm, oW1, oW2);
    k_ln_gate<<<8192, 256>>>(x, ng, nb, gW, gb);

    dim3 gh(T_TOK / 64, 4);
    k_head1_mma<<<gh, 256, K2_SMEM>>>(hb1, hlg, hlb);
    k_head2_mma<<<gh, 256, K3_SMEM>>>(hb2, attr);

    k_out1_mma<<<T_TOK / 64, 512, K4_SMEM>>>(ob1, olg, olb);
    dim3 g5(T_TOK / 64, 2);
    k_out2_mma<<<g5, 256, K5_SMEM>>>(ob2, out);
}

// round 16
// speedup vs baseline: 2.5441x; 1.0790x over previous
#include <cuda_runtime.h>
#include <cuda_fp16.h>
#include <math.h>
#include <stdint.h>

// ----------------------------------------------------------------------------
// NoiseRobustAttractorLayer — R16: all GEMMs fp16 m16n8k16 (fp32 accumulate).
// vs R15 (866us): K3 phase-2 converted to fp16 (Ss fp16 in A-tile layout,
// dynamics blocked fp16, sa via packed AtTh) -> 4 iterations instead of 8;
// fp32 g_xn dropped — K5 residual reads the fp16 copy (saves 268 MB HBM).
// ----------------------------------------------------------------------------

#define T_TOK 65536
#define EPSV  1e-5f

__device__ __half g_xnth [(size_t)T_TOK * 512];   // fp16 (GEMM A + residual)
__device__ float  g_gate [(size_t)T_TOK * 4];
__device__ __half g_hh   [(size_t)T_TOK * 1024];  // fp16
__device__ __half g_combh[(size_t)T_TOK * 512];   // fp16
__device__ __half g_oacth[(size_t)T_TOK * 512];   // fp16

// weights: blocked fp16 [K/16][N][16] (k fastest)
__device__ __half g_hW1h[4 * 512 * 256];
__device__ __half g_hW2h[4 * 256 * 128];
__device__ __half g_dynh[4 * 128 * 128];
__device__ __half g_oW1h[512 * 512];
__device__ __half g_oW2h[512 * 512];

__device__ __forceinline__ float warp_sum(float v) {
#pragma unroll
    for (int o = 16; o > 0; o >>= 1) v += __shfl_xor_sync(0xffffffffu, v, o);
    return v;
}
__device__ __forceinline__ float gelu_exact(float x) {
    return 0.5f * x * (1.0f + erff(x * 0.70710678118654752f));
}
__device__ __forceinline__ void mma_f16(float c[4], const uint32_t a[4],
                                        uint32_t b0, uint32_t b1) {
    asm volatile(
        "mma.sync.aligned.m16n8k16.row.col.f32.f16.f16.f32 "
        "{%0,%1,%2,%3},{%4,%5,%6,%7},{%8,%9},{%0,%1,%2,%3};"
        : "+f"(c[0]), "+f"(c[1]), "+f"(c[2]), "+f"(c[3])
        : "r"(a[0]), "r"(a[1]), "r"(a[2]), "r"(a[3]), "r"(b0), "r"(b1));
}
__device__ __forceinline__ void cp16(void* s, const void* g) {
    uint32_t sa = (uint32_t)__cvta_generic_to_shared(s);
    asm volatile("cp.async.cg.shared.global [%0], [%1], 16;" :: "r"(sa), "l"(g));
}
#define CP_COMMIT()  asm volatile("cp.async.commit_group;")
#define CP_WAIT_0()  asm volatile("cp.async.wait_group 0;" ::: "memory")
#define CP_WAIT_2()  asm volatile("cp.async.wait_group 2;" ::: "memory")

// ============================================================================
// K0: weight conversion to blocked fp16 [K/16][N][16].
// ============================================================================
__global__ void __launch_bounds__(256) k_prep(
    const float* __restrict__ hW1, const float* __restrict__ hW2,
    const float* __restrict__ dynm, const float* __restrict__ oW1,
    const float* __restrict__ oW2)
{
    int i = blockIdx.x * 256 + threadIdx.x;
    if (i < 524288) {                       // hW1: 4 heads x 512x256
        int hh = i >> 17, rem = i & 131071;
        int k = rem >> 8, n = rem & 255;
        g_hW1h[(size_t)hh * 131072 + (k >> 4) * 4096 + n * 16 + (k & 15)] =
            __float2half_rn(hW1[i]);
    } else if (i < 655360) {                // hW2: 4 heads x 256x128
        int j = i - 524288;
        int hh = j >> 15, rem = j & 32767;
        int k = rem >> 7, n = rem & 127;
        g_hW2h[(size_t)hh * 32768 + (k >> 4) * 2048 + n * 16 + (k & 15)] =
            __float2half_rn(hW2[j]);
    } else if (i < 720896) {                // dynamics: 4 heads x 128x128
        int j = i - 655360;
        int hh = j >> 14, rem = j & 16383;
        int k = rem >> 7, n = rem & 127;
        g_dynh[(size_t)hh * 16384 + (k >> 4) * 2048 + n * 16 + (k & 15)] =
            __float2half_rn(dynm[j]);
    } else if (i < 983040) {                // oW1: 512x512
        int j = i - 720896;
        int k = j >> 9, n = j & 511;
        g_oW1h[(size_t)(k >> 4) * 8192 + n * 16 + (k & 15)] = __float2half_rn(oW1[j]);
    } else if (i < 1245184) {               // oW2: 512x512
        int j = i - 983040;
        int k = j >> 9, n = j & 511;
        g_oW2h[(size_t)(k >> 4) * 8192 + n * 16 + (k & 15)] = __float2half_rn(oW2[j]);
    }
}

// ============================================================================
// K1: warp-per-token LN + gate; writes xn fp16 only.
// ============================================================================
__global__ void __launch_bounds__(256) k_ln_gate(
    const float* __restrict__ x, const float* __restrict__ ng,
    const float* __restrict__ nb, const float* __restrict__ gW,
    const float* __restrict__ gb)
{
    __shared__ float sgW[2048];
    __shared__ float sng[512], snb[512];
    const int tid = threadIdx.x;
    for (int i = tid; i < 2048; i += 256) sgW[i] = gW[i];
    for (int i = tid; i < 512; i += 256) { sng[i] = ng[i]; snb[i] = nb[i]; }
    __syncthreads();

    const int wid = tid >> 5, l = tid & 31;
    const float gb0 = gb[0], gb1 = gb[1], gb2 = gb[2], gb3 = gb[3];
    const float4* sgW4 = (const float4*)sgW;
    const float4* sng4 = (const float4*)sng;
    const float4* snb4 = (const float4*)snb;

    for (int t = blockIdx.x * 8 + wid; t < T_TOK; t += gridDim.x * 8) {
        const float4* xr = (const float4*)(x + (size_t)t * 512);
        float4 v[4];
#pragma unroll
        for (int j = 0; j < 4; j++) v[j] = xr[l + 32 * j];
        float s = 0.f;
#pragma unroll
        for (int j = 0; j < 4; j++) s += v[j].x + v[j].y + v[j].z + v[j].w;
        s = warp_sum(s);
        float m = s * (1.0f / 512.0f);
        float q = 0.f;
#pragma unroll
        for (int j = 0; j < 4; j++) {
            float dx = v[j].x - m, dy = v[j].y - m, dz = v[j].z - m, dw = v[j].w - m;
            q += dx * dx + dy * dy + dz * dz + dw * dw;
        }
        q = warp_sum(q);
        float rs = rsqrtf(q * (1.0f / 512.0f) + EPSV);

        float4 xnv[4];
        __half2* xoth = (__half2*)(g_xnth + (size_t)t * 512);
#pragma unroll
        for (int j = 0; j < 4; j++) {
            float4 gv = sng4[l + 32 * j];
            float4 bv = snb4[l + 32 * j];
            xnv[j].x = (v[j].x - m) * rs * gv.x + bv.x;
            xnv[j].y = (v[j].y - m) * rs * gv.y + bv.y;
            xnv[j].z = (v[j].z - m) * rs * gv.z + bv.z;
            xnv[j].w = (v[j].w - m) * rs * gv.w + bv.w;
            xoth[(l + 32 * j) * 2 + 0] = __floats2half2_rn(xnv[j].x, xnv[j].y);
            xoth[(l + 32 * j) * 2 + 1] = __floats2half2_rn(xnv[j].z, xnv[j].w);
        }
        float p[4] = {0.f, 0.f, 0.f, 0.f};
#pragma unroll
        for (int h = 0; h < 4; h++) {
#pragma unroll
            for (int j = 0; j < 4; j++) {
                float4 wv = sgW4[h * 128 + l + 32 * j];
                p[h] += xnv[j].x * wv.x + xnv[j].y * wv.y
                      + xnv[j].z * wv.z + xnv[j].w * wv.w;
            }
            p[h] = warp_sum(p[h]);
        }
        if (l == 0) {
            g_gate[(size_t)t * 4 + 0] = 1.0f / (1.0f + expf(-(p[0] + gb0)));
            g_gate[(size_t)t * 4 + 1] = 1.0f / (1.0f + expf(-(p[1] + gb1)));
            g_gate[(size_t)t * 4 + 2] = 1.0f / (1.0f + expf(-(p[2] + gb2)));
            g_gate[(size_t)t * 4 + 3] = 1.0f / (1.0f + expf(-(p[3] + gb3)));
        }
    }
}

// ============================================================================
// K2: h = gelu(LN(xn @ hW1[h] + hb1)).  fp16, BM=64, BN=256, BK=32, 4-stage.
// (R15 verbatim.)
// ============================================================================
#define K2_SMEM 87040
__global__ void __launch_bounds__(256) k_head1_mma(
    const float* __restrict__ hb1,
    const float* __restrict__ hlg, const float* __restrict__ hlb)
{
    extern __shared__ __align__(16) char dsm[];
    uint32_t* As = (uint32_t*)dsm;                 // 16384 B (4*1024 w)
    uint32_t* Bs = (uint32_t*)(dsm + 16384);       // 65536 B (4*4096 w)
    float* sB  = (float*)(dsm + 81920);
    float* sG  = (float*)(dsm + 82944);
    float* sBt = (float*)(dsm + 83968);
    float* ps  = (float*)(dsm + 84992);            // 64*4
    float* pq  = (float*)(dsm + 86016);            // 64*4

    const int h = blockIdx.y;
    const int t0 = blockIdx.x * 64;
    const int tid = threadIdx.x, w = tid >> 5, l = tid & 31;
    const int wr = w >> 2, wc = w & 3, g = l >> 2, tig = l & 3;
    const int w0 = tig ^ (g & 4), w1 = w0 ^ 4;

    sB[tid] = hb1[h * 256 + tid]; sG[tid] = hlg[h * 256 + tid]; sBt[tid] = hlb[h * 256 + tid];

    float acc[2][8][4];
#pragma unroll
    for (int mt = 0; mt < 2; mt++)
#pragma unroll
        for (int nt = 0; nt < 8; nt++)
#pragma unroll
            for (int i = 0; i < 4; i++) acc[mt][nt][i] = 0.f;

    const __half* Wh = g_hW1h + (size_t)h * 131072;
    const int arow = tid >> 2, ach = tid & 3;
    const uint32_t adst = (ach >> 1) * 512 + arow * 8 + (((ach & 1) * 4) ^ (arow & 4));
    const __half* Ap = g_xnth + (size_t)(t0 + arow) * 512 + ach * 8;

    auto load_stage = [&](int s, int k0) {
        cp16(&As[s * 1024 + adst], Ap + k0);
#pragma unroll
        for (int i = 0; i < 4; i++) {
            int idx = tid + 256 * i;
            int n = idx >> 2, bch = idx & 3;
            int bsub = bch >> 1, bc = (bch & 1) * 4;
            cp16(&Bs[s * 4096 + bsub * 2048 + n * 8 + (bc ^ (n & 4))],
                 Wh + ((size_t)((k0 >> 4) + bsub) * 256 + n) * 16 + bc * 2);
        }
    };

    load_stage(0, 0);  CP_COMMIT();
    load_stage(1, 32); CP_COMMIT();
    load_stage(2, 64); CP_COMMIT();
    int cur = 0;
    for (int it = 0; it < 16; it++) {
        CP_WAIT_2();
        __syncthreads();
        if (it + 3 < 16) load_stage((cur + 3) & 3, (it + 3) * 32);
        CP_COMMIT();
        const uint32_t* Ab = &As[cur * 1024];
        const uint32_t* Bb = &Bs[cur * 4096];
#pragma unroll
        for (int sub = 0; sub < 2; sub++) {
            const uint32_t* Asb = Ab + sub * 512;
            const uint32_t* Bsb = Bb + sub * 2048;
            uint32_t af[2][4];
#pragma unroll
            for (int mt = 0; mt < 2; mt++) {
                int rb = (wr * 32 + mt * 16 + g) * 8;
                af[mt][0] = Asb[rb + w0];      af[mt][1] = Asb[rb + 64 + w0];
                af[mt][2] = Asb[rb + w1];      af[mt][3] = Asb[rb + 64 + w1];
            }
#pragma unroll
            for (int nt = 0; nt < 8; nt++) {
                int nb = (wc * 64 + nt * 8 + g) * 8;
                uint32_t b0 = Bsb[nb + w0], b1 = Bsb[nb + w1];
                mma_f16(acc[0][nt], af[0], b0, b1);
                mma_f16(acc[1][nt], af[1], b0, b1);
            }
        }
        cur = (cur + 1) & 3;
    }
    __syncthreads();

    // epilogue: bias + LN(256) + gelu ; store fp16
    float rsm[4] = {0, 0, 0, 0}, rsq[4] = {0, 0, 0, 0};
#pragma unroll
    for (int mt = 0; mt < 2; mt++)
#pragma unroll
        for (int nt = 0; nt < 8; nt++) {
            int c0 = wc * 64 + nt * 8 + 2 * tig;
            float v0 = acc[mt][nt][0] + sB[c0], v1 = acc[mt][nt][1] + sB[c0 + 1];
            float v2 = acc[mt][nt][2] + sB[c0], v3 = acc[mt][nt][3] + sB[c0 + 1];
            acc[mt][nt][0] = v0; acc[mt][nt][1] = v1; acc[mt][nt][2] = v2; acc[mt][nt][3] = v3;
            rsm[mt * 2 + 0] += v0 + v1; rsq[mt * 2 + 0] += v0 * v0 + v1 * v1;
            rsm[mt * 2 + 1] += v2 + v3; rsq[mt * 2 + 1] += v2 * v2 + v3 * v3;
        }
#pragma unroll
    for (int off = 1; off < 4; off <<= 1)
#pragma unroll
        for (int q = 0; q < 4; q++) {
            rsm[q] += __shfl_xor_sync(0xffffffffu, rsm[q], off);
            rsq[q] += __shfl_xor_sync(0xffffffffu, rsq[q], off);
        }
    if (tig == 0) {
#pragma unroll
        for (int q = 0; q < 4; q++) {
            int row = wr * 32 + (q >> 1) * 16 + (q & 1) * 8 + g;
            ps[row * 4 + wc] = rsm[q]; pq[row * 4 + wc] = rsq[q];
        }
    }
    __syncthreads();
    float mv[4], rv[4];
#pragma unroll
    for (int q = 0; q < 4; q++) {
        int row = wr * 32 + (q >> 1) * 16 + (q & 1) * 8 + g;
        float s  = ps[row * 4 + 0] + ps[row * 4 + 1] + ps[row * 4 + 2] + ps[row * 4 + 3];
        float s2 = pq[row * 4 + 0] + pq[row * 4 + 1] + pq[row * 4 + 2] + pq[row * 4 + 3];
        float m = s * (1.f / 256.f);
        float var = s2 * (1.f / 256.f) - m * m;
        mv[q] = m; rv[q] = rsqrtf(var + EPSV);
    }
#pragma unroll
    for (int mt = 0; mt < 2; mt++)
#pragma unroll
        for (int nt = 0; nt < 8; nt++) {
            int c0 = wc * 64 + nt * 8 + 2 * tig;
            int q0 = mt * 2;
            int row0 = t0 + wr * 32 + mt * 16 + g;
            float u0 = gelu_exact((acc[mt][nt][0] - mv[q0]) * rv[q0] * sG[c0] + sBt[c0]);
            float u1 = gelu_exact((acc[mt][nt][1] - mv[q0]) * rv[q0] * sG[c0 + 1] + sBt[c0 + 1]);
            *(__half2*)&g_hh[(size_t)row0 * 1024 + h * 256 + c0] = __floats2half2_rn(u0, u1);
            float u2 = gelu_exact((acc[mt][nt][2] - mv[q0 + 1]) * rv[q0 + 1] * sG[c0] + sBt[c0]);
            float u3 = gelu_exact((acc[mt][nt][3] - mv[q0 + 1]) * rv[q0 + 1] * sG[c0 + 1] + sBt[c0 + 1]);
            *(__half2*)&g_hh[(size_t)(row0 + 8) * 1024 + h * 256 + c0] = __floats2half2_rn(u2, u3);
        }
}

// ============================================================================
// K3 (R16): fully fp16. Phase-1 state GEMM (BK=32, 4-stage);
// Ss stored fp16 in swizzled A-tile layout; phase-2 [dyn|sa] fp16 (4 its).
// smem: As 16384 | Bs 32768 | Ssh 16384 | At 4096 | AtTh 2048 | Sa 2048 |
//       Sw 2048 | s2p 1024 | a2s 32 | Sgt 256 = 77088  (2 CTAs)
// ============================================================================
#define K3_SMEM 77088
__global__ void __launch_bounds__(256, 2) k_head2_mma(
    const float* __restrict__ hb2, const float* __restrict__ attr)
{
    extern __shared__ __align__(16) char dsm[];
    uint32_t* As   = (uint32_t*)dsm;               // 16384 (4*1024 w)
    uint32_t* Bs   = (uint32_t*)(dsm + 16384);     // 32768 (4*2048 w)
    uint32_t* Ssh  = (uint32_t*)(dsm + 49152);     // 16384 (8 subs *64r*8w)
    float*    At   = (float*)(dsm + 65536);        //  4096 (8*128)
    uint32_t* AtTh = (uint32_t*)(dsm + 69632);     //  2048 (64 k2 * 8 n)
    float*    Sa   = (float*)(dsm + 71680);        //  2048
    float*    Sw   = (float*)(dsm + 73728);        //  2048
    float*    s2p  = (float*)(dsm + 75776);        //  1024
    float*    a2s  = (float*)(dsm + 76800);        //    32
    float*    Sgt  = (float*)(dsm + 76832);        //   256

    const int h = blockIdx.y;
    const int t0 = blockIdx.x * 64;
    const int tid = threadIdx.x, w = tid >> 5, l = tid & 31;
    const int wr = w >> 2, wc = w & 3, g = l >> 2, tig = l & 3;
    const int w0 = tig ^ (g & 4), w1 = w0 ^ 4;

    {
        float4 v = *(const float4*)(attr + (size_t)h * 1024 + tid * 4);
        *(float4*)&At[tid * 4] = v;
        int a0 = tid >> 5, d0 = (tid & 31) * 4;    // attractor a0, dims d0..d0+3
        __half2* ath = (__half2*)AtTh;             // word (k2=d/2)*8 + a
        ath[(d0 >> 1) * 8 + a0]       = __floats2half2_rn(v.x, v.y);
        ath[((d0 >> 1) + 1) * 8 + a0] = __floats2half2_rn(v.z, v.w);
    }

    // ---- phase 1: state = h @ hW2[h]  (fp16) ----
    float acc[2][4][4];
#pragma unroll
    for (int mt = 0; mt < 2; mt++)
#pragma unroll
        for (int nt = 0; nt < 4; nt++)
#pragma unroll
            for (int i = 0; i < 4; i++) acc[mt][nt][i] = 0.f;

    const __half* Wh = g_hW2h + (size_t)h * 32768;
    const int arow = tid >> 2, ach = tid & 3;
    const uint32_t adst = (ach >> 1) * 512 + arow * 8 + (((ach & 1) * 4) ^ (arow & 4));
    const __half* Ap = g_hh + (size_t)(t0 + arow) * 1024 + h * 256 + ach * 8;

    auto load_stage1 = [&](int s, int k0) {
        cp16(&As[s * 1024 + adst], Ap + k0);
#pragma unroll
        for (int i = 0; i < 2; i++) {
            int idx = tid + 256 * i;
            int n = idx >> 2, bch = idx & 3;
            int bsub = bch >> 1, bc = (bch & 1) * 4;
            cp16(&Bs[s * 2048 + bsub * 1024 + n * 8 + (bc ^ (n & 4))],
                 Wh + ((size_t)((k0 >> 4) + bsub) * 128 + n) * 16 + bc * 2);
        }
    };

    load_stage1(0, 0);  CP_COMMIT();
    load_stage1(1, 32); CP_COMMIT();
    load_stage1(2, 64); CP_COMMIT();
    __syncthreads();
    if (tid < 8) {
        float q = 0.f;
#pragma unroll
        for (int k = 0; k < 128; k++) q += At[tid * 128 + k] * At[tid * 128 + k];
        a2s[tid] = q;
    }

    int cur = 0;
    for (int it = 0; it < 8; it++) {
        CP_WAIT_2();
        __syncthreads();
        if (it + 3 < 8) load_stage1((cur + 3) & 3, (it + 3) * 32);
        CP_COMMIT();
        const uint32_t* Ab = &As[cur * 1024];
        const uint32_t* Bb = &Bs[cur * 2048];
#pragma unroll
        for (int sub = 0; sub < 2; sub++) {
            const uint32_t* Asb = Ab + sub * 512;
            const uint32_t* Bsb = Bb + sub * 1024;
            uint32_t af[2][4];
#pragma unroll
            for (int mt = 0; mt < 2; mt++) {
                int rb = (wr * 32 + mt * 16 + g) * 8;
                af[mt][0] = Asb[rb + w0];      af[mt][1] = Asb[rb + 64 + w0];
                af[mt][2] = Asb[rb + w1];      af[mt][3] = Asb[rb + 64 + w1];
            }
#pragma unroll
            for (int nt = 0; nt < 4; nt++) {
                int nb = (wc * 32 + nt * 8 + g) * 8;
                uint32_t b0 = Bsb[nb + w0], b1 = Bsb[nb + w1];
                mma_f16(acc[0][nt], af[0], b0, b1);
                mma_f16(acc[1][nt], af[1], b0, b1);
            }
        }
        cur = (cur + 1) & 3;
    }
    __syncthreads();   // all warps done reading phase-1 Bs

    // prefetch dynamics fp16 (all 4 stages of BK=32)
    const __half* Dh = g_dynh + (size_t)h * 16384;
    auto load_stage2 = [&](int s, int k0) {
#pragma unroll
        for (int i = 0; i < 2; i++) {
            int idx = tid + 256 * i;
            int n = idx >> 2, bch = idx & 3;
            int bsub = bch >> 1, bc = (bch & 1) * 4;
            cp16(&Bs[s * 2048 + bsub * 1024 + n * 8 + (bc ^ (n & 4))],
                 Dh + ((size_t)((k0 >> 4) + bsub) * 128 + n) * 16 + bc * 2);
        }
    };
    load_stage2(0, 0);   CP_COMMIT();
    load_stage2(1, 32);  CP_COMMIT();
    load_stage2(2, 64);  CP_COMMIT();
    load_stage2(3, 96);  CP_COMMIT();

    // epilogue 1: bias, fp16-round, store Ssh (A-tile layout), ||s||^2 partials
    {
        float rq[4] = {0, 0, 0, 0};
#pragma unroll
        for (int mt = 0; mt < 2; mt++)
#pragma unroll
            for (int nt = 0; nt < 4; nt++) {
                int c0 = wc * 32 + nt * 8 + 2 * tig;
                int row = wr * 32 + mt * 16 + g;
                float b0v = hb2[h * 128 + c0], b1v = hb2[h * 128 + c0 + 1];
                __half2 h01 = __floats2half2_rn(acc[mt][nt][0] + b0v, acc[mt][nt][1] + b1v);
                __half2 h23 = __floats2half2_rn(acc[mt][nt][2] + b0v, acc[mt][nt][3] + b1v);
                int sub = c0 >> 4;
                int wv = ((c0 >> 1) & 7) ^ (row & 4);
                ((__half2*)Ssh)[sub * 512 + row * 8 + wv]       = h01;
                ((__half2*)Ssh)[sub * 512 + (row + 8) * 8 + wv] = h23;
                float v0 = __low2float(h01), v1 = __high2float(h01);
                float v2 = __low2float(h23), v3 = __high2float(h23);
                rq[mt * 2 + 0] += v0 * v0 + v1 * v1;
                rq[mt * 2 + 1] += v2 * v2 + v3 * v3;
            }
#pragma unroll
        for (int off = 1; off < 4; off <<= 1)
#pragma unroll
            for (int q = 0; q < 4; q++)
                rq[q] += __shfl_xor_sync(0xffffffffu, rq[q], off);
        if (tig == 0) {
#pragma unroll
            for (int q = 0; q < 4; q++) {
                int row = wr * 32 + (q >> 1) * 16 + (q & 1) * 8 + g;
                s2p[row * 4 + wc] = rq[q];
            }
        }
    }
    CP_WAIT_0();
    __syncthreads();   // publishes Ssh, s2p, dynamics stages

    // ---- phase 2: [dyn | sa] = state @ [dynamics | attrT]  (fp16, 4 its) ----
    float dcc[2][4][4];
    float scc[2][4];
#pragma unroll
    for (int mt = 0; mt < 2; mt++) {
#pragma unroll
        for (int nt = 0; nt < 4; nt++)
#pragma unroll
            for (int i = 0; i < 4; i++) dcc[mt][nt][i] = 0.f;
#pragma unroll
        for (int i = 0; i < 4; i++) scc[mt][i] = 0.f;
    }

#pragma unroll
    for (int it = 0; it < 4; it++) {
        const uint32_t* Bb = &Bs[it * 2048];
#pragma unroll
        for (int sub = 0; sub < 2; sub++) {
            const int k16 = it * 2 + sub;
            const uint32_t* Ssb = Ssh + k16 * 512;
            const uint32_t* Bsb = Bb + sub * 1024;
            uint32_t af[2][4];
#pragma unroll
            for (int mt = 0; mt < 2; mt++) {
                int rb = (wr * 32 + mt * 16 + g) * 8;
                af[mt][0] = Ssb[rb + w0];      af[mt][1] = Ssb[rb + 64 + w0];
                af[mt][2] = Ssb[rb + w1];      af[mt][3] = Ssb[rb + 64 + w1];
            }
#pragma unroll
            for (int nt = 0; nt < 4; nt++) {
                int nb = (wc * 32 + nt * 8 + g) * 8;
                uint32_t b0 = Bsb[nb + w0], b1 = Bsb[nb + w1];
                mma_f16(dcc[0][nt], af[0], b0, b1);
                mma_f16(dcc[1][nt], af[1], b0, b1);
            }
            uint32_t b0s = AtTh[(k16 * 8 + tig) * 8 + g];
            uint32_t b1s = AtTh[(k16 * 8 + tig + 4) * 8 + g];
            mma_f16(scc[0], af[0], b0s, b1s);
            mma_f16(scc[1], af[1], b0s, b1s);
        }
    }
    __syncthreads();

    if (wc == 0) {
#pragma unroll
        for (int mt = 0; mt < 2; mt++) {
            int row = wr * 32 + mt * 16 + g;
            Sa[row * 8 + 2 * tig]           = scc[mt][0];
            Sa[row * 8 + 2 * tig + 1]       = scc[mt][1];
            Sa[(row + 8) * 8 + 2 * tig]     = scc[mt][2];
            Sa[(row + 8) * 8 + 2 * tig + 1] = scc[mt][3];
        }
    }
    __syncthreads();

    const float invs = 0.08838834764831845f;  // 1/sqrt(128)
    if (tid < 64) {
        int row = tid;
        float s2 = s2p[row * 4 + 0] + s2p[row * 4 + 1] + s2p[row * 4 + 2] + s2p[row * 4 + 3];
        float lgt[8], mx = -1e30f;
#pragma unroll
        for (int a = 0; a < 8; a++) {
            float dd = sqrtf(fmaxf(s2 + a2s[a] - 2.0f * Sa[row * 8 + a], 0.0f));
            lgt[a] = -dd * invs;
            mx = fmaxf(mx, lgt[a]);
        }
        float e[8], se = 0.f;
#pragma unroll
        for (int a = 0; a < 8; a++) { e[a] = expf(lgt[a] - mx); se += e[a]; }
        float ise = 1.0f / se;
#pragma unroll
        for (int a = 0; a < 8; a++) Sw[row * 8 + a] = e[a] * ise;
        Sgt[row] = 0.1f * g_gate[(size_t)(t0 + row) * 4 + h];
    }
    __syncthreads();

    // mix: sv re-read from Ssh (fp16), dv from registers, ai FFMA from At/Sw
#pragma unroll
    for (int mt = 0; mt < 2; mt++)
#pragma unroll
        for (int nt = 0; nt < 4; nt++) {
            int c0 = wc * 32 + nt * 8 + 2 * tig;
            int sub = c0 >> 4;
            int rowb = wr * 32 + mt * 16 + g;
            int wv = ((c0 >> 1) & 7) ^ (rowb & 4);
#pragma unroll
            for (int half = 0; half < 2; half++) {
                int row = rowb + 8 * half;
                float gt = Sgt[row];
                __half2 svh = ((__half2*)Ssh)[sub * 512 + row * 8 + wv];
                float sv0 = __low2float(svh), sv1 = __high2float(svh);
                float ai0 = 0.f, ai1 = 0.f;
#pragma unroll
                for (int a = 0; a < 8; a++) {
                    float wgt = Sw[row * 8 + a];
                    ai0 += wgt * At[a * 128 + c0];
                    ai1 += wgt * At[a * 128 + c0 + 1];
                }
                float dv0 = dcc[mt][nt][2 * half + 0];
                float dv1 = dcc[mt][nt][2 * half + 1];
                float o0 = sv0 + gt * (ai0 - sv0 + tanhf(dv0));
                float o1 = sv1 + gt * (ai1 - sv1 + tanhf(dv1));
                *(__half2*)&g_combh[(size_t)(t0 + row) * 512 + h * 128 + c0] =
                    __floats2half2_rn(o0, o1);
            }
        }
}

// ============================================================================
// K4: o1 = gelu(LN(comb @ oW1 + ob1)).  fp16, BM=64, BN=512, BK=32, block 512.
// (R15 verbatim.)
// ============================================================================
#define K4_SMEM 157696
__global__ void __launch_bounds__(512) k_out1_mma(
    const float* __restrict__ ob1,
    const float* __restrict__ olg, const float* __restrict__ olb)
{
    extern __shared__ __align__(16) char dsm[];
    uint32_t* As = (uint32_t*)dsm;                 // 16384 B
    uint32_t* Bs = (uint32_t*)(dsm + 16384);       // 131072 B (4*8192 w)
    float* sB  = (float*)(dsm + 147456);
    float* sG  = (float*)(dsm + 149504);
    float* sBt = (float*)(dsm + 151552);
    float* ps  = (float*)(dsm + 153600);           // 64*8
    float* pq  = (float*)(dsm + 155648);

    const int t0 = blockIdx.x * 64;
    const int tid = threadIdx.x, w = tid >> 5, l = tid & 31;
    const int wr = w >> 3, wc = w & 7, g = l >> 2, tig = l & 3;
    const int w0 = tig ^ (g & 4), w1 = w0 ^ 4;

    sB[tid] = ob1[tid]; sG[tid] = olg[tid]; sBt[tid] = olb[tid];

    float acc[2][8][4];
#pragma unroll
    for (int mt = 0; mt < 2; mt++)
#pragma unroll
        for (int nt = 0; nt < 8; nt++)
#pragma unroll
            for (int i = 0; i < 4; i++) acc[mt][nt][i] = 0.f;

    const int arow = (tid & 255) >> 2, ach = tid & 3;
    const uint32_t adst = (ach >> 1) * 512 + arow * 8 + (((ach & 1) * 4) ^ (arow & 4));
    const __half* Ap = g_combh + (size_t)(t0 + arow) * 512 + ach * 8;

    auto load_stage = [&](int s, int k0) {
        if (tid < 256) cp16(&As[s * 1024 + adst], Ap + k0);
#pragma unroll
        for (int i = 0; i < 4; i++) {
            int idx = tid + 512 * i;
            int n = idx >> 2, bch = idx & 3;
            int bsub = bch >> 1, bc = (bch & 1) * 4;
            cp16(&Bs[s * 8192 + bsub * 4096 + n * 8 + (bc ^ (n & 4))],
                 g_oW1h + ((size_t)((k0 >> 4) + bsub) * 512 + n) * 16 + bc * 2);
        }
    };

    load_stage(0, 0);  CP_COMMIT();
    load_stage(1, 32); CP_COMMIT();
    load_stage(2, 64); CP_COMMIT();
    int cur = 0;
    for (int it = 0; it < 16; it++) {
        CP_WAIT_2();
        __syncthreads();
        if (it + 3 < 16) load_stage((cur + 3) & 3, (it + 3) * 32);
        CP_COMMIT();
        const uint32_t* Ab = &As[cur * 1024];
        const uint32_t* Bb = &Bs[cur * 8192];
#pragma unroll
        for (int sub = 0; sub < 2; sub++) {
            const uint32_t* Asb = Ab + sub * 512;
            const uint32_t* Bsb = Bb + sub * 4096;
            uint32_t af[2][4];
#pragma unroll
            for (int mt = 0; mt < 2; mt++) {
                int rb = (wr * 32 + mt * 16 + g) * 8;
                af[mt][0] = Asb[rb + w0];      af[mt][1] = Asb[rb + 64 + w0];
                af[mt][2] = Asb[rb + w1];      af[mt][3] = Asb[rb + 64 + w1];
            }
#pragma unroll
            for (int nt = 0; nt < 8; nt++) {
                int nb = (wc * 64 + nt * 8 + g) * 8;
                uint32_t b0 = Bsb[nb + w0], b1 = Bsb[nb + w1];
                mma_f16(acc[0][nt], af[0], b0, b1);
                mma_f16(acc[1][nt], af[1], b0, b1);
            }
        }
        cur = (cur + 1) & 3;
    }
    __syncthreads();

    float rsm[4] = {0, 0, 0, 0}, rsq[4] = {0, 0, 0, 0};
#pragma unroll
    for (int mt = 0; mt < 2; mt++)
#pragma unroll
        for (int nt = 0; nt < 8; nt++) {
            int c0 = wc * 64 + nt * 8 + 2 * tig;
            float v0 = acc[mt][nt][0] + sB[c0], v1 = acc[mt][nt][1] + sB[c0 + 1];
            float v2 = acc[mt][nt][2] + sB[c0], v3 = acc[mt][nt][3] + sB[c0 + 1];
            acc[mt][nt][0] = v0; acc[mt][nt][1] = v1; acc[mt][nt][2] = v2; acc[mt][nt][3] = v3;
            rsm[mt * 2 + 0] += v0 + v1; rsq[mt * 2 + 0] += v0 * v0 + v1 * v1;
            rsm[mt * 2 + 1] += v2 + v3; rsq[mt * 2 + 1] += v2 * v2 + v3 * v3;
        }
#pragma unroll
    for (int off = 1; off < 4; off <<= 1)
#pragma unroll
        for (int q = 0; q < 4; q++) {
            rsm[q] += __shfl_xor_sync(0xffffffffu, rsm[q], off);
            rsq[q] += __shfl_xor_sync(0xffffffffu, rsq[q], off);
        }
    if (tig == 0) {
#pragma unroll
        for (int q = 0; q < 4; q++) {
            int row = wr * 32 + (q >> 1) * 16 + (q & 1) * 8 + g;
            ps[row * 8 + wc] = rsm[q]; pq[row * 8 + wc] = rsq[q];
        }
    }
    __syncthreads();
    float mv[4], rv[4];
#pragma unroll
    for (int q = 0; q < 4; q++) {
        int row = wr * 32 + (q >> 1) * 16 + (q & 1) * 8 + g;
        float s = 0.f, s2 = 0.f;
#pragma unroll
        for (int j = 0; j < 8; j++) { s += ps[row * 8 + j]; s2 += pq[row * 8 + j]; }
        float m = s * (1.f / 512.f);
        float var = s2 * (1.f / 512.f) - m * m;
        mv[q] = m; rv[q] = rsqrtf(var + EPSV);
    }
#pragma unroll
    for (int mt = 0; mt < 2; mt++)
#pragma unroll
        for (int nt = 0; nt < 8; nt++) {
            int c0 = wc * 64 + nt * 8 + 2 * tig;
            int q0 = mt * 2;
            int row0 = t0 + wr * 32 + mt * 16 + g;
            float u0 = gelu_exact((acc[mt][nt][0] - mv[q0]) * rv[q0] * sG[c0] + sBt[c0]);
            float u1 = gelu_exact((acc[mt][nt][1] - mv[q0]) * rv[q0] * sG[c0 + 1] + sBt[c0 + 1]);
            *(__half2*)&g_oacth[(size_t)row0 * 512 + c0] = __floats2half2_rn(u0, u1);
            float u2 = gelu_exact((acc[mt][nt][2] - mv[q0 + 1]) * rv[q0 + 1] * sG[c0] + sBt[c0]);
            float u3 = gelu_exact((acc[mt][nt][3] - mv[q0 + 1]) * rv[q0 + 1] * sG[c0 + 1] + sBt[c0 + 1]);
            *(__half2*)&g_oacth[(size_t)(row0 + 8) * 512 + c0] = __floats2half2_rn(u2, u3);
        }
}

// ============================================================================
// K5: out = xn + oact @ oW2 + ob2.  fp16 GEMM + fp16 residual.
// BM=64, BN=256, BK=32, block 256, grid (T/64, 2), 4-stage.
// ============================================================================
#define K5_SMEM 82944
__global__ void __launch_bounds__(256) k_out2_mma(
    const float* __restrict__ ob2, float* __restrict__ out)
{
    extern __shared__ __align__(16) char dsm[];
    uint32_t* As = (uint32_t*)dsm;                 // 16384
    uint32_t* Bs = (uint32_t*)(dsm + 16384);       // 65536
    float* sB = (float*)(dsm + 81920);

    const int t0 = blockIdx.x * 64;
    const int c0base = blockIdx.y * 256;
    const int tid = threadIdx.x, w = tid >> 5, l = tid & 31;
    const int wr = w >> 2, wc = w & 3, g = l >> 2, tig = l & 3;
    const int w0 = tig ^ (g & 4), w1 = w0 ^ 4;

    sB[tid] = ob2[c0base + tid];

    float acc[2][8][4];
#pragma unroll
    for (int mt = 0; mt < 2; mt++)
#pragma unroll
        for (int nt = 0; nt < 8; nt++)
#pragma unroll
            for (int i = 0; i < 4; i++) acc[mt][nt][i] = 0.f;

    const int arow = tid >> 2, ach = tid & 3;
    const uint32_t adst = (ach >> 1) * 512 + arow * 8 + (((ach & 1) * 4) ^ (arow & 4));
    const __half* Ap = g_oacth + (size_t)(t0 + arow) * 512 + ach * 8;

    auto load_stage = [&](int s, int k0) {
        cp16(&As[s * 1024 + adst], Ap + k0);
#pragma unroll
        for (int i = 0; i < 4; i++) {
            int idx = tid + 256 * i;
            int n = idx >> 2, bch = idx & 3;
            int bsub = bch >> 1, bc = (bch & 1) * 4;
            cp16(&Bs[s * 4096 + bsub * 2048 + n * 8 + (bc ^ (n & 4))],
                 g_oW2h + ((size_t)((k0 >> 4) + bsub) * 512 + c0base + n) * 16 + bc * 2);
        }
    };

    load_stage(0, 0);  CP_COMMIT();
    load_stage(1, 32); CP_COMMIT();
    load_stage(2, 64); CP_COMMIT();
    int cur = 0;
    for (int it = 0; it < 16; it++) {
        CP_WAIT_2();
        __syncthreads();
        if (it + 3 < 16) load_stage((cur + 3) & 3, (it + 3) * 32);
        CP_COMMIT();
        const uint32_t* Ab = &As[cur * 1024];
        const uint32_t* Bb = &Bs[cur * 4096];
#pragma unroll
        for (int sub = 0; sub < 2; sub++) {
            const uint32_t* Asb = Ab + sub * 512;
            const uint32_t* Bsb = Bb + sub * 2048;
            uint32_t af[2][4];
#pragma unroll
            for (int mt = 0; mt < 2; mt++) {
                int rb = (wr * 32 + mt * 16 + g) * 8;
                af[mt][0] = Asb[rb + w0];      af[mt][1] = Asb[rb + 64 + w0];
                af[mt][2] = Asb[rb + w1];      af[mt][3] = Asb[rb + 64 + w1];
            }
#pragma unroll
            for (int nt = 0; nt < 8; nt++) {
                int nb = (wc * 64 + nt * 8 + g) * 8;
                uint32_t b0 = Bsb[nb + w0], b1 = Bsb[nb + w1];
                mma_f16(acc[0][nt], af[0], b0, b1);
                mma_f16(acc[1][nt], af[1], b0, b1);
            }
        }
        cur = (cur + 1) & 3;
    }

#pragma unroll
    for (int mt = 0; mt < 2; mt++)
#pragma unroll
        for (int nt = 0; nt < 8; nt++) {
            int c0 = wc * 64 + nt * 8 + 2 * tig;
            int col = c0base + c0;
            int row0 = t0 + wr * 32 + mt * 16 + g;
            size_t o0 = (size_t)row0 * 512 + col;
            size_t o1 = (size_t)(row0 + 8) * 512 + col;
            __half2 x0h = *(const __half2*)&g_xnth[o0];
            __half2 x1h = *(const __half2*)&g_xnth[o1];
            *(float2*)&out[o0] = make_float2(acc[mt][nt][0] + sB[c0] + __low2float(x0h),
                                             acc[mt][nt][1] + sB[c0 + 1] + __high2float(x0h));
            *(float2*)&out[o1] = make_float2(acc[mt][nt][2] + sB[c0] + __low2float(x1h),
                                             acc[mt][nt][3] + sB[c0 + 1] + __high2float(x1h));
        }
}

// ============================================================================
extern "C" void kernel_launch(void* const* d_in, const int* in_sizes, int n_in,
                              void* d_out, int out_size)
{
    (void)in_sizes; (void)n_in; (void)out_size;
    const float* x    = (const float*)d_in[0];
    const float* ng   = (const float*)d_in[1];
    const float* nb   = (const float*)d_in[2];
    const float* hW1  = (const float*)d_in[3];
    const float* hb1  = (const float*)d_in[4];
    const float* hlg  = (const float*)d_in[5];
    const float* hlb  = (const float*)d_in[6];
    const float* hW2  = (const float*)d_in[7];
    const float* hb2  = (const float*)d_in[8];
    const float* attr = (const float*)d_in[9];
    const float* dynm = (const float*)d_in[10];
    const float* gW   = (const float*)d_in[11];
    const float* gb   = (const float*)d_in[12];
    const float* oW1  = (const float*)d_in[13];
    const float* ob1  = (const float*)d_in[14];
    const float* olg  = (const float*)d_in[15];
    const float* olb  = (const float*)d_in[16];
    const float* oW2  = (const float*)d_in[17];
    const float* ob2  = (const float*)d_in[18];
    float* out = (float*)d_out;

    cudaFuncSetAttribute(k_head1_mma, cudaFuncAttributeMaxDynamicSharedMemorySize, K2_SMEM);
    cudaFuncSetAttribute(k_head2_mma, cudaFuncAttributeMaxDynamicSharedMemorySize, K3_SMEM);
    cudaFuncSetAttribute(k_out1_mma,  cudaFuncAttributeMaxDynamicSharedMemorySize, K4_SMEM);
    cudaFuncSetAttribute(k_out2_mma,  cudaFuncAttributeMaxDynamicSharedMemorySize, K5_SMEM);

    k_prep<<<4864, 256>>>(hW1, hW2, dynm, oW1, oW2);
    k_ln_gate<<<8192, 256>>>(x, ng, nb, gW, gb);

    dim3 gh(T_TOK / 64, 4);
    k_head1_mma<<<gh, 256, K2_SMEM>>>(hb1, hlg, hlb);
    k_head2_mma<<<gh, 256, K3_SMEM>>>(hb2, attr);

    k_out1_mma<<<T_TOK / 64, 512, K4_SMEM>>>(ob1, olg, olb);
    dim3 g5(T_TOK / 64, 2);
    k_out2_mma<<<g5, 256, K5_SMEM>>>(ob2, out);
}